// round 1
// baseline (speedup 1.0000x reference)
#include <cuda_runtime.h>
#include <math.h>

#define NB   4
#define NC   64
#define HW   96
#define HF   48
#define LL   2304    /* 48*48 */
#define KK1  576     /* C*9   */
#define MM2  1024    /* C*16  */
#define NP   2304    /* correlation spatial 48*48 */
#define NPIX 9216    /* 96*96 */

typedef long long ll;

// ---------------- scratch (device globals; no allocation) ----------------
__device__ float g_Wmat[(size_t)NB*LL*KK1];   // 5.3M
__device__ float g_Xmat[(size_t)NB*KK1*NP];   // 5.3M
__device__ float g_bufA[(size_t)NB*LL*LL];    // 21.2M
__device__ float g_bufB[(size_t)NB*LL*LL];    // 21.2M
__device__ float g_W2  [(size_t)NB*MM2*LL];   // 9.4M
__device__ float g_Tmp [(size_t)NB*MM2*LL];   // 9.4M
__device__ float g_y   [(size_t)NB*NC*NPIX];  // 2.36M
__device__ float g_c1  [(size_t)NB*NC*NPIX];  // 2.36M
__device__ float g_rn  [NB*LL];

// ---------------- builders ----------------
// Xmat[b][k=(c,dh,dw)][p=(fh,fw)] = fd_pad[c, fh+dh, fw+dw], fd = f[:,:,::2,::2]
__global__ void build_X_k(const float* __restrict__ f, float* __restrict__ X)
{
    int idx = blockIdx.x*blockDim.x + threadIdx.x;
    if (idx >= NB*KK1*NP) return;
    int p = idx % NP; int t = idx / NP;
    int k = t % KK1;  int b = t / KK1;
    int c  = k / 9;  int tt = k % 9; int dh = tt/3, dw = tt%3;
    int fh = p / HF, fw = p % HF;
    int u = fh + dh - 1, v = fw + dw - 1;
    float val = 0.f;
    if ((unsigned)u < HF && (unsigned)v < HF)
        val = f[(((size_t)b*NC + c)*HW + 2*u)*HW + 2*v];
    X[idx] = val;
}

// Wmat[b][n][k=(c,dh,dw)] : g=n*64+c -> (c0,h0,w0); value = bd_pad[c0,h0+dh,w0+dw]
__global__ void build_W_k(const float* __restrict__ bimg, float* __restrict__ W)
{
    int idx = blockIdx.x*blockDim.x + threadIdx.x;
    if (idx >= NB*LL*KK1) return;
    int k = idx % KK1; int t = idx / KK1;
    int n = t % LL;    int b = t / LL;
    int c  = k / 9;  int tt = k % 9; int dh = tt/3, dw = tt%3;
    int g = n*NC + c;
    int c0 = g / LL; int rr = g % LL; int h0 = rr / HF, w0 = rr % HF;
    int u = h0 + dh - 1, v = w0 + dw - 1;
    float val = 0.f;
    if ((unsigned)u < HF && (unsigned)v < HF)
        val = bimg[(((size_t)b*NC + c0)*HW + 2*u)*HW + 2*v];
    W[idx] = val;
}

// W2[b][m=c*16+i*4+j][l] = b_pad98[c0, 2h0+3-i, 2w0+3-j], g = l*64+c
__global__ void build_W2_k(const float* __restrict__ bimg, float* __restrict__ W2)
{
    int idx = blockIdx.x*blockDim.x + threadIdx.x;
    if (idx >= NB*MM2*LL) return;
    int l = idx % LL; int t = idx / LL;
    int m = t % MM2;  int b = t / MM2;
    int c = m / 16; int tt = m % 16; int i = tt/4, j = tt%4;
    int g = l*NC + c;
    int c0 = g / LL; int rr = g % LL; int h0 = rr / HF, w0 = rr % HF;
    int u = 2*h0 + 2 - i, v = 2*w0 + 2 - j;   // b-coords (pad removed)
    float val = 0.f;
    if ((unsigned)u < HW && (unsigned)v < HW)
        val = bimg[(((size_t)b*NC + c0)*HW + u)*HW + v];
    W2[idx] = val;
}

// rnorm: one warp per (b,n): 1/max(sqrt(sum W^2),1e-4)
__global__ void rnorm_k(const float* __restrict__ W, float* __restrict__ rn)
{
    int warp = (blockIdx.x*blockDim.x + threadIdx.x) >> 5;
    int lane = threadIdx.x & 31;
    if (warp >= NB*LL) return;
    const float* row = W + (size_t)warp*KK1;
    float s = 0.f;
    for (int k = lane; k < KK1; k += 32) { float v = row[k]; s += v*v; }
    #pragma unroll
    for (int o = 16; o; o >>= 1) s += __shfl_xor_sync(0xffffffffu, s, o);
    if (lane == 0) rn[warp] = 1.0f / fmaxf(sqrtf(s), 1e-4f);
}

// ---------------- generic fp32 SGEMM: C = rowscale(A@B) + bias ----------------
__global__ __launch_bounds__(256, 2) void sgemm_k(
    const float* __restrict__ Ag, const float* __restrict__ Bg, float* __restrict__ Cg,
    int M, int N, int K, ll sA, ll sB, ll sC,
    const float* __restrict__ rowscale, int sRS, const float* __restrict__ bias)
{
    int bz = blockIdx.z;
    const float* A  = Ag + (ll)bz*sA;
    const float* Bm = Bg + (ll)bz*sB;
    float* Cc = Cg + (ll)bz*sC;
    int bm = blockIdx.y*128, bn = blockIdx.x*128;
    int tid = threadIdx.x;
    __shared__ float As[8][132];
    __shared__ float Bs[8][132];
    int tx = tid & 15, ty = tid >> 4;
    int arow = tid >> 1, acol = (tid & 1)*4;
    int brow = tid >> 5, bcol = (tid & 31)*4;
    float acc[8][8];
    #pragma unroll
    for (int i=0;i<8;i++)
        #pragma unroll
        for (int j=0;j<8;j++) acc[i][j]=0.f;

    bool arow_ok = (bm + arow) < M;
    const float* Aptr = A + (ll)(bm+arow)*K + acol;
    const float* Bptr = Bm + (ll)brow*N + bn + bcol;

    for (int k0 = 0; k0 < K; k0 += 8) {
        float4 av = make_float4(0.f,0.f,0.f,0.f);
        if (arow_ok) av = *(const float4*)(Aptr + k0);
        float4 bv = *(const float4*)(Bptr + (ll)k0*N);
        As[acol  ][arow]=av.x; As[acol+1][arow]=av.y;
        As[acol+2][arow]=av.z; As[acol+3][arow]=av.w;
        *(float4*)&Bs[brow][bcol] = bv;
        __syncthreads();
        #pragma unroll
        for (int kk=0; kk<8; kk++){
            float ar[8], br[8];
            *(float4*)(ar)   = *(const float4*)&As[kk][ty*8];
            *(float4*)(ar+4) = *(const float4*)&As[kk][ty*8+4];
            *(float4*)(br)   = *(const float4*)&Bs[kk][tx*8];
            *(float4*)(br+4) = *(const float4*)&Bs[kk][tx*8+4];
            #pragma unroll
            for (int i=0;i<8;i++)
                #pragma unroll
                for (int j=0;j<8;j++)
                    acc[i][j] = fmaf(ar[i], br[j], acc[i][j]);
        }
        __syncthreads();
    }
    #pragma unroll
    for (int i=0;i<8;i++){
        int row = bm + ty*8 + i;
        if (row >= M) break;
        float sc = rowscale ? rowscale[bz*sRS + row] : 1.f;
        float bb = bias ? bias[row] : 0.f;
        float* cp = Cc + (ll)row*N + bn + tx*8;
        float4 v0, v1;
        v0.x=acc[i][0]*sc+bb; v0.y=acc[i][1]*sc+bb; v0.z=acc[i][2]*sc+bb; v0.w=acc[i][3]*sc+bb;
        v1.x=acc[i][4]*sc+bb; v1.y=acc[i][5]*sc+bb; v1.z=acc[i][6]*sc+bb; v1.w=acc[i][7]*sc+bb;
        *(float4*)cp = v0; *(float4*)(cp+4) = v1;
    }
}

// ---------------- fuse (diagonal 3-tap on 2304x2304, zero-padded) ----------------
__global__ void fuse_k(const float* __restrict__ In, float* __restrict__ Out)
{
    int idx = blockIdx.x*blockDim.x + threadIdx.x;
    if (idx >= NB*LL*LL) return;
    int rem = idx % (LL*LL);
    int b   = idx / (LL*LL);
    int r = rem / LL, s = rem % LL;
    const float* base = In + (size_t)b*LL*LL;
    float v = base[rem];
    if (r > 0     && s > 0)     v += base[rem - LL - 1];
    if (r < LL-1  && s < LL-1)  v += base[rem + LL + 1];
    Out[idx] = v;
}

// ---------------- both-axis 48x48 permutation: Out[r'][s'] = In[swap(r')][swap(s')] ----------------
__global__ void perm_k(const float* __restrict__ In, float* __restrict__ Out)
{
    int b  = blockIdx.z;
    int rp = blockIdx.x;                       // output row r'
    int a  = (rp % HF)*HF + rp / HF;           // swap(r')
    const float* src = In  + ((size_t)b*LL + a )*LL;
    float*       dst = Out + ((size_t)b*LL + rp)*LL;
    __shared__ float sm[HF][HF+1];
    for (int i = threadIdx.x; i < LL; i += blockDim.x)
        sm[i / HF][i % HF] = src[i];
    __syncthreads();
    for (int i = threadIdx.x; i < LL; i += blockDim.x)
        dst[i] = sm[i % HF][i / HF];           // = src[swap(i)]
}

// ---------------- column softmax over rows (axis l), scale 10, in-place ----------------
__global__ void softmax_k(float* __restrict__ Ad)
{
    int b   = blockIdx.z;
    int col = blockIdx.x*32 + threadIdx.x;
    int st  = threadIdx.y;                       // 0..7
    float* Ab = Ad + (size_t)b*LL*LL;
    const int RP = LL/8;                         // 288
    __shared__ float red[8][33];

    float mx = -3.4e38f;
    for (int r = st*RP; r < (st+1)*RP; r++)
        mx = fmaxf(mx, Ab[(size_t)r*LL + col]);
    red[st][threadIdx.x] = mx;
    __syncthreads();
    float m = red[0][threadIdx.x];
    #pragma unroll
    for (int s = 1; s < 8; s++) m = fmaxf(m, red[s][threadIdx.x]);
    m *= 10.f;
    __syncthreads();

    float sum = 0.f;
    for (int r = st*RP; r < (st+1)*RP; r++)
        sum += __expf(10.f*Ab[(size_t)r*LL + col] - m);
    red[st][threadIdx.x] = sum;
    __syncthreads();
    float tot = 0.f;
    #pragma unroll
    for (int s = 0; s < 8; s++) tot += red[s][threadIdx.x];
    float inv = 1.f / tot;

    for (int r = st*RP; r < (st+1)*RP; r++) {
        size_t o = (size_t)r*LL + col;
        Ab[o] = __expf(10.f*Ab[o] - m) * inv;
    }
}

// ---------------- deconv gather: y[c,yy,xx] = 0.25 * sum 2x2 taps of Tmp ----------------
__global__ void deconv_k(const float* __restrict__ Tmp, float* __restrict__ yout)
{
    int idx = blockIdx.x*blockDim.x + threadIdx.x;
    if (idx >= NB*NC*NPIX) return;
    int p = idx % NPIX; int t = idx / NPIX;
    int c = t % NC;     int b = t / NC;
    int yy = p / HW, xx = p % HW;
    const float* T = Tmp + (size_t)b*MM2*LL;
    float acc = 0.f;
    #pragma unroll
    for (int di = 0; di < 2; di++) {
        int i = (yy & 1) + 2*di;
        int d = yy + i - 2;
        if (d < 0) continue;
        int h = d >> 1; if (h >= HF) continue;
        #pragma unroll
        for (int dj = 0; dj < 2; dj++) {
            int j = (xx & 1) + 2*dj;
            int e = xx + j - 2;
            if (e < 0) continue;
            int w = e >> 1; if (w >= HF) continue;
            acc += T[(size_t)(c*16 + i*4 + j)*LL + h*HF + w];
        }
    }
    yout[idx] = acc * 0.25f;
}

// ---------------- im2col for 3x3 pad-1 conv on 96x96 ----------------
__global__ void im2col_k(const float* __restrict__ In, float* __restrict__ X)
{
    int idx = blockIdx.x*blockDim.x + threadIdx.x;
    if (idx >= NB*KK1*NPIX) return;
    int p = idx % NPIX; int t = idx / NPIX;
    int k = t % KK1;    int b = t / KK1;
    int c = k / 9; int tt = k % 9; int dh = tt/3 - 1, dw = tt%3 - 1;
    int yy = p / HW + dh, xx = p % HW + dw;
    float val = 0.f;
    if ((unsigned)yy < HW && (unsigned)xx < HW)
        val = In[(((size_t)b*NC + c)*HW + yy)*HW + xx];
    X[idx] = val;
}

// ---------------- launch ----------------
extern "C" void kernel_launch(void* const* d_in, const int* in_sizes, int n_in,
                              void* d_out, int out_size)
{
    const float* f   = (const float*)d_in[0];
    const float* bim = (const float*)d_in[1];
    const float* w1  = (const float*)d_in[2];
    const float* b1  = (const float*)d_in[3];
    const float* w2  = (const float*)d_in[4];
    const float* b2  = (const float*)d_in[5];
    float* out = (float*)d_out;

    float *Wmat, *Xmat, *bufA, *bufB, *W2, *Tmp, *yb, *c1, *rn;
    cudaGetSymbolAddress((void**)&Wmat, g_Wmat);
    cudaGetSymbolAddress((void**)&Xmat, g_Xmat);
    cudaGetSymbolAddress((void**)&bufA, g_bufA);
    cudaGetSymbolAddress((void**)&bufB, g_bufB);
    cudaGetSymbolAddress((void**)&W2,   g_W2);
    cudaGetSymbolAddress((void**)&Tmp,  g_Tmp);
    cudaGetSymbolAddress((void**)&yb,   g_y);
    cudaGetSymbolAddress((void**)&c1,   g_c1);
    cudaGetSymbolAddress((void**)&rn,   g_rn);

    const int T = 256;

    build_X_k<<<(NB*KK1*NP + T-1)/T, T>>>(f, Xmat);
    build_W_k<<<(NB*LL*KK1 + T-1)/T, T>>>(bim, Wmat);
    rnorm_k  <<<(NB*LL*32  + T-1)/T, T>>>(Wmat, rn);

    // correlation GEMM: Y0 = diag(rnorm) * Wmat @ Xmat   -> bufA
    sgemm_k<<<dim3(NP/128, LL/128, NB), T>>>(Wmat, Xmat, bufA,
        LL, NP, KK1, (ll)LL*KK1, (ll)KK1*NP, (ll)LL*NP, rn, LL, nullptr);

    // fuse1 -> bufB ; perm -> bufA ; fuse2 -> bufB ; perm -> bufA
    fuse_k<<<(NB*LL*LL + T-1)/T, T>>>(bufA, bufB);
    perm_k<<<dim3(LL, 1, NB), T>>>(bufB, bufA);
    fuse_k<<<(NB*LL*LL + T-1)/T, T>>>(bufA, bufB);
    perm_k<<<dim3(LL, 1, NB), T>>>(bufB, bufA);

    // softmax over rows per column (in place, bufA = S)
    softmax_k<<<dim3(LL/32, 1, NB), dim3(32, 8)>>>(bufA);

    // deconv GEMM: Tmp = W2 @ S
    build_W2_k<<<(NB*MM2*LL + T-1)/T, T>>>(bim, W2);
    sgemm_k<<<dim3(LL/128, MM2/128, NB), T>>>(W2, bufA, Tmp,
        MM2, LL, LL, (ll)MM2*LL, (ll)LL*LL, (ll)MM2*LL, nullptr, 0, nullptr);

    // gather into y (÷4)
    deconv_k<<<(NB*NC*NPIX + T-1)/T, T>>>(Tmp, yb);

    // conv1: im2col(y) -> bufB ; (w1 @ X) + b1 -> c1
    im2col_k<<<(NB*KK1*NPIX + T-1)/T, T>>>(yb, bufB);
    sgemm_k<<<dim3(NPIX/128, 1, NB), T>>>(w1, bufB, c1,
        NC, NPIX, KK1, 0, (ll)KK1*NPIX, (ll)NC*NPIX, nullptr, 0, b1);

    // conv2: im2col(c1) -> bufB ; (w2 @ X) + b2 -> out
    im2col_k<<<(NB*KK1*NPIX + T-1)/T, T>>>(c1, bufB);
    sgemm_k<<<dim3(NPIX/128, 1, NB), T>>>(w2, bufB, out,
        NC, NPIX, KK1, 0, (ll)KK1*NPIX, (ll)NC*NPIX, nullptr, 0, b2);
}

// round 2
// speedup vs baseline: 1.1826x; 1.1826x over previous
#include <cuda_runtime.h>
#include <math.h>
#include <stdint.h>

#define NB   4
#define NC   64
#define HW   96
#define HF   48
#define LL   2304    /* 48*48 */
#define KK1  576     /* C*9   */
#define MM2  1024    /* C*16  */
#define NPIX 9216    /* 96*96 */

typedef long long ll;

// ---------------- scratch (device globals; no allocation) ----------------
__device__ float g_WmatT[(size_t)NB*KK1*LL];  // A of GEMM1, K-major (576 x 2304)
__device__ float g_Xmat [(size_t)NB*KK1*LL];  // B of GEMM1 (576 x 2304)
__device__ float g_bufA [(size_t)NB*LL*LL];
__device__ float g_bufB [(size_t)NB*LL*LL];   // also reused as im2col (same size)
__device__ float g_W2T  [(size_t)NB*LL*MM2];  // A of GEMM2, K-major (2304 x 1024)
__device__ float g_Tmp  [(size_t)NB*MM2*LL];
__device__ float g_y    [(size_t)NB*NC*NPIX];
__device__ float g_c1   [(size_t)NB*NC*NPIX];
__device__ float g_rn   [NB*LL];
__device__ float g_w1T  [KK1*NC];
__device__ float g_w2T  [KK1*NC];

// ---------------- builders ----------------
// Xmat[b][k=(c,dh,dw)][p=(fh,fw)] = fd_pad[c, fh+dh, fw+dw], fd = f[:,:,::2,::2]
__global__ void build_X_k(const float* __restrict__ f, float* __restrict__ X)
{
    int idx = blockIdx.x*blockDim.x + threadIdx.x;
    if (idx >= NB*KK1*LL) return;
    int p = idx % LL; int t = idx / LL;
    int k = t % KK1;  int b = t / KK1;
    int c  = k / 9;  int tt = k % 9; int dh = tt/3, dw = tt%3;
    int fh = p / HF, fw = p % HF;
    int u = fh + dh - 1, v = fw + dw - 1;
    float val = 0.f;
    if ((unsigned)u < HF && (unsigned)v < HF)
        val = f[(((size_t)b*NC + c)*HW + 2*u)*HW + 2*v];
    X[idx] = val;
}

// WmatT[b][k][n] : transposed weight matrix (K-major)
__global__ void build_WT_k(const float* __restrict__ bimg, float* __restrict__ W)
{
    int idx = blockIdx.x*blockDim.x + threadIdx.x;
    if (idx >= NB*KK1*LL) return;
    int n = idx % LL; int t = idx / LL;
    int k = t % KK1;  int b = t / KK1;
    int c  = k / 9;  int tt = k % 9; int dh = tt/3, dw = tt%3;
    int g = n*NC + c;
    int c0 = g / LL; int rr = g % LL; int h0 = rr / HF, w0 = rr % HF;
    int u = h0 + dh - 1, v = w0 + dw - 1;
    float val = 0.f;
    if ((unsigned)u < HF && (unsigned)v < HF)
        val = bimg[(((size_t)b*NC + c0)*HW + 2*u)*HW + 2*v];
    W[idx] = val;
}

// W2T[b][l][m=c*16+i*4+j] = b[c0, 2h0+2-i, 2w0+2-j], g = l*64+c  (K-major)
__global__ void build_W2T_k(const float* __restrict__ bimg, float* __restrict__ W2)
{
    int idx = blockIdx.x*blockDim.x + threadIdx.x;
    if (idx >= NB*LL*MM2) return;
    int m = idx % MM2; int t = idx / MM2;
    int l = t % LL;    int b = t / LL;
    int c = m / 16; int tt = m % 16; int i = tt/4, j = tt%4;
    int g = l*NC + c;
    int c0 = g / LL; int rr = g % LL; int h0 = rr / HF, w0 = rr % HF;
    int u = 2*h0 + 2 - i, v = 2*w0 + 2 - j;
    float val = 0.f;
    if ((unsigned)u < HW && (unsigned)v < HW)
        val = bimg[(((size_t)b*NC + c0)*HW + u)*HW + v];
    W2[idx] = val;
}

// rnorm from K-major WmatT: column n, coalesced across threads
__global__ void rnorm_k(const float* __restrict__ W, float* __restrict__ rn)
{
    int idx = blockIdx.x*blockDim.x + threadIdx.x;
    if (idx >= NB*LL) return;
    int b = idx / LL, n = idx % LL;
    const float* col = W + (size_t)b*KK1*LL + n;
    float s = 0.f;
    #pragma unroll 4
    for (int k = 0; k < KK1; k++) { float v = col[(size_t)k*LL]; s += v*v; }
    rn[idx] = 1.0f / fmaxf(sqrtf(s), 1e-4f);
}

// transpose conv weight: w[NC][KK1] -> wT[KK1][NC]
__global__ void transpose_w_k(const float* __restrict__ w, float* __restrict__ wT)
{
    int idx = blockIdx.x*blockDim.x + threadIdx.x;
    if (idx >= NC*KK1) return;
    int k = idx % KK1, c = idx / KK1;
    wT[(size_t)k*NC + c] = w[idx];
}

// ---------------- cp.async helper ----------------
__device__ __forceinline__ void cpa16(float* s, const float* g, int bytes)
{
    uint32_t sa = (uint32_t)__cvta_generic_to_shared(s);
    asm volatile("cp.async.cg.shared.global [%0], [%1], 16, %2;\n"
                 :: "r"(sa), "l"(g), "r"(bytes));
}
__device__ __forceinline__ void cp_commit() { asm volatile("cp.async.commit_group;\n"); }
__device__ __forceinline__ void cp_wait0()  { asm volatile("cp.async.wait_group 0;\n"); }

// ---------------- NT fp32 SGEMM: C = rowscale(A^T@B) + bias ----------------
// A: K x M (K-major), B: K x N (K-major). Tile 128x128x16, double-buffered cp.async.
__global__ __launch_bounds__(256, 2) void sgemm_nt_k(
    const float* __restrict__ Ag, const float* __restrict__ Bg, float* __restrict__ Cg,
    int M, int N, int K, ll sA, ll sB, ll sC,
    const float* __restrict__ rowscale, int sRS, const float* __restrict__ bias)
{
    int bz = blockIdx.z;
    const float* A = Ag + (ll)bz*sA;
    const float* B = Bg + (ll)bz*sB;
    float*       C = Cg + (ll)bz*sC;
    int bm = blockIdx.y*128, bn = blockIdx.x*128;
    int tid = threadIdx.x;
    int tx = tid & 15, ty = tid >> 4;

    __shared__ float As[2][16][132];
    __shared__ float Bs[2][16][132];

    float acc[8][8];
    #pragma unroll
    for (int i=0;i<8;i++)
        #pragma unroll
        for (int j=0;j<8;j++) acc[i][j]=0.f;

    // per-thread load coords: 512 float4 per operand per stage, 2 each
    int k_a0 = tid >> 5,            c4_0 = (tid & 31)*4;
    int k_a1 = (tid+256) >> 5,      c4_1 = (tid & 31)*4;   // (tid+256)&31 == tid&31

#define LOAD_STAGE(st, k0)                                                      \
    {                                                                           \
        int mb0 = bm + c4_0;                                                    \
        const float* ga0 = A + (ll)((k0)+k_a0)*M + (mb0 < M ? mb0 : 0);         \
        cpa16(&As[st][k_a0][c4_0], ga0, (mb0 < M) ? 16 : 0);                    \
        const float* gb0 = B + (ll)((k0)+k_a0)*N + bn + c4_0;                   \
        cpa16(&Bs[st][k_a0][c4_0], gb0, 16);                                    \
        int mb1 = bm + c4_1;                                                    \
        const float* ga1 = A + (ll)((k0)+k_a1)*M + (mb1 < M ? mb1 : 0);         \
        cpa16(&As[st][k_a1][c4_1], ga1, (mb1 < M) ? 16 : 0);                    \
        const float* gb1 = B + (ll)((k0)+k_a1)*N + bn + c4_1;                   \
        cpa16(&Bs[st][k_a1][c4_1], gb1, 16);                                    \
    }

    int nk = K >> 4;
    LOAD_STAGE(0, 0);
    cp_commit();
    cp_wait0();
    __syncthreads();

    for (int kt = 0; kt < nk; kt++) {
        int cur = kt & 1;
        if (kt + 1 < nk) { LOAD_STAGE(cur^1, (kt+1)<<4); cp_commit(); }
        #pragma unroll
        for (int kk = 0; kk < 16; kk++) {
            float ar[8], br[8];
            *(float4*)(ar)   = *(const float4*)&As[cur][kk][ty*8];
            *(float4*)(ar+4) = *(const float4*)&As[cur][kk][ty*8+4];
            *(float4*)(br)   = *(const float4*)&Bs[cur][kk][tx*8];
            *(float4*)(br+4) = *(const float4*)&Bs[cur][kk][tx*8+4];
            #pragma unroll
            for (int i=0;i<8;i++)
                #pragma unroll
                for (int j=0;j<8;j++)
                    acc[i][j] = fmaf(ar[i], br[j], acc[i][j]);
        }
        if (kt + 1 < nk) cp_wait0();
        __syncthreads();
    }
#undef LOAD_STAGE

    #pragma unroll
    for (int i=0;i<8;i++){
        int row = bm + ty*8 + i;
        if (row < M) {
            float sc = rowscale ? rowscale[bz*sRS + row] : 1.f;
            float bb = bias ? bias[row] : 0.f;
            float* cp = C + (ll)row*N + bn + tx*8;
            float4 v0, v1;
            v0.x=acc[i][0]*sc+bb; v0.y=acc[i][1]*sc+bb; v0.z=acc[i][2]*sc+bb; v0.w=acc[i][3]*sc+bb;
            v1.x=acc[i][4]*sc+bb; v1.y=acc[i][5]*sc+bb; v1.z=acc[i][6]*sc+bb; v1.w=acc[i][7]*sc+bb;
            *(float4*)cp = v0; *(float4*)(cp+4) = v1;
        }
    }
}

// ---------------- fuse1 (diagonal 3-tap, flat 2304x2304) ----------------
__global__ void fuse_k(const float* __restrict__ In, float* __restrict__ Out)
{
    int idx = blockIdx.x*blockDim.x + threadIdx.x;
    if (idx >= NB*LL*LL) return;
    int rem = idx % (LL*LL);
    int b   = idx / (LL*LL);
    int r = rem / LL, s = rem % LL;
    const float* base = In + (size_t)b*LL*LL;
    float v = base[rem];
    if (r > 0     && s > 0)     v += base[rem - LL - 1];
    if (r < LL-1  && s < LL-1)  v += base[rem + LL + 1];
    Out[idx] = v;
}

// ---------------- fuse48: the perm-fuse-perm collapsed stencil ----------------
// Out[r][s] = In[r][s] + In[prev r][prev s] (if sig(r)>0 && sig(s)>0)
//                      + In[next r][next s] (if sig(r)<LL-1 && sig(s)<LL-1)
// sig(x) = (x%48)*48 + x/48 (involution); prev(x)=sig(sig(x)-1), next(x)=sig(sig(x)+1)
__global__ void fuse48_k(const float* __restrict__ In, float* __restrict__ Out)
{
    int idx = blockIdx.x*blockDim.x + threadIdx.x;
    if (idx >= NB*LL*LL) return;
    int rem = idx % (LL*LL);
    int b   = idx / (LL*LL);
    int r = rem / LL, s = rem % LL;
    const float* base = In + (size_t)b*LL*LL;
    float v = base[rem];
    int qr = (r % HF)*HF + r / HF;
    int qs = (s % HF)*HF + s / HF;
    if (qr > 0 && qs > 0) {
        int pr = ((qr-1) % HF)*HF + (qr-1) / HF;
        int ps = ((qs-1) % HF)*HF + (qs-1) / HF;
        v += base[(size_t)pr*LL + ps];
    }
    if (qr < LL-1 && qs < LL-1) {
        int nr = ((qr+1) % HF)*HF + (qr+1) / HF;
        int ns = ((qs+1) % HF)*HF + (qs+1) / HF;
        v += base[(size_t)nr*LL + ns];
    }
    Out[idx] = v;
}

// ---------------- column softmax over rows, scale 10, in-place ----------------
__global__ void softmax_k(float* __restrict__ Ad)
{
    int b   = blockIdx.z;
    int col = blockIdx.x*32 + threadIdx.x;
    int st  = threadIdx.y;                       // 0..7
    float* Ab = Ad + (size_t)b*LL*LL;
    const int RP = LL/8;                         // 288
    __shared__ float red[8][33];

    float mx = -3.4e38f;
    for (int r = st*RP; r < (st+1)*RP; r++)
        mx = fmaxf(mx, Ab[(size_t)r*LL + col]);
    red[st][threadIdx.x] = mx;
    __syncthreads();
    float m = red[0][threadIdx.x];
    #pragma unroll
    for (int s = 1; s < 8; s++) m = fmaxf(m, red[s][threadIdx.x]);
    m *= 10.f;
    __syncthreads();

    float sum = 0.f;
    for (int r = st*RP; r < (st+1)*RP; r++)
        sum += __expf(10.f*Ab[(size_t)r*LL + col] - m);
    red[st][threadIdx.x] = sum;
    __syncthreads();
    float tot = 0.f;
    #pragma unroll
    for (int s = 0; s < 8; s++) tot += red[s][threadIdx.x];
    float inv = 1.f / tot;

    for (int r = st*RP; r < (st+1)*RP; r++) {
        size_t o = (size_t)r*LL + col;
        Ab[o] = __expf(10.f*Ab[o] - m) * inv;
    }
}

// ---------------- deconv gather: y[c,yy,xx] = 0.25 * sum 2x2 taps of Tmp ----------------
__global__ void deconv_k(const float* __restrict__ Tmp, float* __restrict__ yout)
{
    int idx = blockIdx.x*blockDim.x + threadIdx.x;
    if (idx >= NB*NC*NPIX) return;
    int p = idx % NPIX; int t = idx / NPIX;
    int c = t % NC;     int b = t / NC;
    int yy = p / HW, xx = p % HW;
    const float* T = Tmp + (size_t)b*MM2*LL;
    float acc = 0.f;
    #pragma unroll
    for (int di = 0; di < 2; di++) {
        int i = (yy & 1) + 2*di;
        int d = yy + i - 2;
        if (d < 0) continue;
        int h = d >> 1; if (h >= HF) continue;
        #pragma unroll
        for (int dj = 0; dj < 2; dj++) {
            int j = (xx & 1) + 2*dj;
            int e = xx + j - 2;
            if (e < 0) continue;
            int w = e >> 1; if (w >= HF) continue;
            acc += T[(size_t)(c*16 + i*4 + j)*LL + h*HF + w];
        }
    }
    yout[idx] = acc * 0.25f;
}

// ---------------- im2col for 3x3 pad-1 conv on 96x96 ----------------
__global__ void im2col_k(const float* __restrict__ In, float* __restrict__ X)
{
    int idx = blockIdx.x*blockDim.x + threadIdx.x;
    if (idx >= NB*KK1*NPIX) return;
    int p = idx % NPIX; int t = idx / NPIX;
    int k = t % KK1;    int b = t / KK1;
    int c = k / 9; int tt = k % 9; int dh = tt/3 - 1, dw = tt%3 - 1;
    int yy = p / HW + dh, xx = p % HW + dw;
    float val = 0.f;
    if ((unsigned)yy < HW && (unsigned)xx < HW)
        val = In[(((size_t)b*NC + c)*HW + yy)*HW + xx];
    X[idx] = val;
}

// ---------------- launch ----------------
extern "C" void kernel_launch(void* const* d_in, const int* in_sizes, int n_in,
                              void* d_out, int out_size)
{
    const float* f   = (const float*)d_in[0];
    const float* bim = (const float*)d_in[1];
    const float* w1  = (const float*)d_in[2];
    const float* b1  = (const float*)d_in[3];
    const float* w2  = (const float*)d_in[4];
    const float* b2  = (const float*)d_in[5];
    float* out = (float*)d_out;

    float *WmatT, *Xmat, *bufA, *bufB, *W2T, *Tmp, *yb, *c1, *rn, *w1T, *w2T;
    cudaGetSymbolAddress((void**)&WmatT, g_WmatT);
    cudaGetSymbolAddress((void**)&Xmat,  g_Xmat);
    cudaGetSymbolAddress((void**)&bufA,  g_bufA);
    cudaGetSymbolAddress((void**)&bufB,  g_bufB);
    cudaGetSymbolAddress((void**)&W2T,   g_W2T);
    cudaGetSymbolAddress((void**)&Tmp,   g_Tmp);
    cudaGetSymbolAddress((void**)&yb,    g_y);
    cudaGetSymbolAddress((void**)&c1,    g_c1);
    cudaGetSymbolAddress((void**)&rn,    g_rn);
    cudaGetSymbolAddress((void**)&w1T,   g_w1T);
    cudaGetSymbolAddress((void**)&w2T,   g_w2T);

    const int T = 256;

    build_X_k <<<(NB*KK1*LL + T-1)/T, T>>>(f, Xmat);
    build_WT_k<<<(NB*KK1*LL + T-1)/T, T>>>(bim, WmatT);
    rnorm_k   <<<(NB*LL + T-1)/T, T>>>(WmatT, rn);

    // GEMM1: Y0 = diag(rnorm) * Wmat @ Xmat   -> bufA
    sgemm_nt_k<<<dim3(LL/128, LL/128, NB), T>>>(WmatT, Xmat, bufA,
        LL, LL, KK1, (ll)KK1*LL, (ll)KK1*LL, (ll)LL*LL, rn, LL, nullptr);

    // fuse1 -> bufB ; fuse48 -> bufA  (permutations algebraically eliminated)
    fuse_k  <<<(NB*LL*LL + T-1)/T, T>>>(bufA, bufB);
    fuse48_k<<<(NB*LL*LL + T-1)/T, T>>>(bufB, bufA);

    // softmax over rows per column (in place, bufA = S)
    softmax_k<<<dim3(LL/32, 1, NB), dim3(32, 8)>>>(bufA);

    // GEMM2: Tmp = W2 @ S
    build_W2T_k<<<(NB*LL*MM2 + T-1)/T, T>>>(bim, W2T);
    sgemm_nt_k<<<dim3(LL/128, MM2/128, NB), T>>>(W2T, bufA, Tmp,
        MM2, LL, LL, (ll)LL*MM2, (ll)LL*LL, (ll)MM2*LL, nullptr, 0, nullptr);

    // gather into y (/4)
    deconv_k<<<(NB*NC*NPIX + T-1)/T, T>>>(Tmp, yb);

    // conv1: im2col(y) -> bufB ; (w1 @ X) + b1 -> c1
    transpose_w_k<<<(NC*KK1 + T-1)/T, T>>>(w1, w1T);
    im2col_k<<<(NB*KK1*NPIX + T-1)/T, T>>>(yb, bufB);
    sgemm_nt_k<<<dim3(NPIX/128, 1, NB), T>>>(w1T, bufB, c1,
        NC, NPIX, KK1, 0, (ll)KK1*NPIX, (ll)NC*NPIX, nullptr, 0, b1);

    // conv2: im2col(c1) -> bufB ; (w2 @ X) + b2 -> out
    transpose_w_k<<<(NC*KK1 + T-1)/T, T>>>(w2, w2T);
    im2col_k<<<(NB*KK1*NPIX + T-1)/T, T>>>(c1, bufB);
    sgemm_nt_k<<<dim3(NPIX/128, 1, NB), T>>>(w2T, bufB, out,
        NC, NPIX, KK1, 0, (ll)KK1*NPIX, (ll)NC*NPIX, nullptr, 0, b2);
}

// round 3
// speedup vs baseline: 1.1942x; 1.0098x over previous
#include <cuda_runtime.h>
#include <math.h>
#include <stdint.h>

#define NB   4
#define NC   64
#define HW   96
#define HF   48
#define LL   2304    /* 48*48 */
#define KK1  576     /* C*9   */
#define MM2  1024    /* C*16  */
#define NPIX 9216    /* 96*96 */

typedef long long ll;
typedef unsigned long long ull;

// ---------------- scratch (device globals; no allocation) ----------------
__device__ float g_WmatT[(size_t)NB*KK1*LL];
__device__ float g_Xmat [(size_t)NB*KK1*LL];
__device__ float g_bufA [(size_t)NB*LL*LL];
__device__ float g_bufB [(size_t)NB*LL*LL];
__device__ float g_W2T  [(size_t)NB*LL*MM2];
__device__ float g_Tmp  [(size_t)NB*MM2*LL];
__device__ float g_y    [(size_t)NB*NC*NPIX];
__device__ float g_c1   [(size_t)NB*NC*NPIX];
__device__ float g_rn   [NB*LL];
__device__ float g_w1T  [KK1*NC];
__device__ float g_w2T  [KK1*NC];

// ---------------- builders ----------------
__global__ void build_X_k(const float* __restrict__ f, float* __restrict__ X)
{
    int idx = blockIdx.x*blockDim.x + threadIdx.x;
    if (idx >= NB*KK1*LL) return;
    int p = idx % LL; int t = idx / LL;
    int k = t % KK1;  int b = t / KK1;
    int c  = k / 9;  int tt = k % 9; int dh = tt/3, dw = tt%3;
    int fh = p / HF, fw = p % HF;
    int u = fh + dh - 1, v = fw + dw - 1;
    float val = 0.f;
    if ((unsigned)u < HF && (unsigned)v < HF)
        val = f[(((size_t)b*NC + c)*HW + 2*u)*HW + 2*v];
    X[idx] = val;
}

__global__ void build_WT_k(const float* __restrict__ bimg, float* __restrict__ W)
{
    int idx = blockIdx.x*blockDim.x + threadIdx.x;
    if (idx >= NB*KK1*LL) return;
    int n = idx % LL; int t = idx / LL;
    int k = t % KK1;  int b = t / KK1;
    int c  = k / 9;  int tt = k % 9; int dh = tt/3, dw = tt%3;
    int g = n*NC + c;
    int c0 = g / LL; int rr = g % LL; int h0 = rr / HF, w0 = rr % HF;
    int u = h0 + dh - 1, v = w0 + dw - 1;
    float val = 0.f;
    if ((unsigned)u < HF && (unsigned)v < HF)
        val = bimg[(((size_t)b*NC + c0)*HW + 2*u)*HW + 2*v];
    W[idx] = val;
}

__global__ void build_W2T_k(const float* __restrict__ bimg, float* __restrict__ W2)
{
    int idx = blockIdx.x*blockDim.x + threadIdx.x;
    if (idx >= NB*LL*MM2) return;
    int m = idx % MM2; int t = idx / MM2;
    int l = t % LL;    int b = t / LL;
    int c = m / 16; int tt = m % 16; int i = tt/4, j = tt%4;
    int g = l*NC + c;
    int c0 = g / LL; int rr = g % LL; int h0 = rr / HF, w0 = rr % HF;
    int u = 2*h0 + 2 - i, v = 2*w0 + 2 - j;
    float val = 0.f;
    if ((unsigned)u < HW && (unsigned)v < HW)
        val = bimg[(((size_t)b*NC + c0)*HW + u)*HW + v];
    W2[idx] = val;
}

__global__ void rnorm_k(const float* __restrict__ W, float* __restrict__ rn)
{
    int idx = blockIdx.x*blockDim.x + threadIdx.x;
    if (idx >= NB*LL) return;
    int b = idx / LL, n = idx % LL;
    const float* col = W + (size_t)b*KK1*LL + n;
    float s = 0.f;
    #pragma unroll 4
    for (int k = 0; k < KK1; k++) { float v = col[(size_t)k*LL]; s += v*v; }
    rn[idx] = 1.0f / fmaxf(sqrtf(s), 1e-4f);
}

__global__ void transpose_w_k(const float* __restrict__ w, float* __restrict__ wT)
{
    int idx = blockIdx.x*blockDim.x + threadIdx.x;
    if (idx >= NC*KK1) return;
    int k = idx % KK1, c = idx / KK1;
    wT[(size_t)k*NC + c] = w[idx];
}

// ---------------- cp.async helpers ----------------
__device__ __forceinline__ void cpa16(float* s, const float* g, int bytes)
{
    uint32_t sa = (uint32_t)__cvta_generic_to_shared(s);
    asm volatile("cp.async.cg.shared.global [%0], [%1], 16, %2;\n"
                 :: "r"(sa), "l"(g), "r"(bytes));
}
__device__ __forceinline__ void cp_commit() { asm volatile("cp.async.commit_group;\n"); }
__device__ __forceinline__ void cp_wait0()  { asm volatile("cp.async.wait_group 0;\n"); }

// packed fp32x2 FMA (sm_100+): d = a*b + c elementwise on 2 lanes
#define FMA_F32X2(d, a, b, c) \
    asm("fma.rn.f32x2 %0, %1, %2, %3;" : "=l"(d) : "l"(a), "l"(b), "l"(c))
#define DUP_F32X2(d, r) \
    asm("mov.b64 %0, {%1, %1};" : "=l"(d) : "r"(r))

// ---------------- NT fp32 SGEMM with FFMA2: C = rowscale(A^T@B) + bias ----------------
// A: K x M (K-major), B: K x N (K-major). Tile BM x 128 x 16, double-buffered cp.async.
template<int BM>
__global__ __launch_bounds__(256, 2) void sgemm_nt_k(
    const float* __restrict__ Ag, const float* __restrict__ Bg, float* __restrict__ Cg,
    int M, int N, int K, ll sA, ll sB, ll sC,
    const float* __restrict__ rowscale, int sRS, const float* __restrict__ bias)
{
    constexpr int BN = 128, BK = 16;
    constexpr int MI = BM / 16;       // rows per thread (8 or 4)
    int bz = blockIdx.z;
    const float* A = Ag + (ll)bz*sA;
    const float* B = Bg + (ll)bz*sB;
    float*       C = Cg + (ll)bz*sC;
    int bm = blockIdx.y*BM, bn = blockIdx.x*BN;
    int tid = threadIdx.x;
    int tx = tid & 15, ty = tid >> 4;

    __shared__ float As[2][BK][BM+4];
    __shared__ float Bs[2][BK][BN+4];

    ull acc2[MI][4];
    #pragma unroll
    for (int i=0;i<MI;i++)
        #pragma unroll
        for (int j=0;j<4;j++) acc2[i][j] = 0ull;

    constexpr int A4 = BK*BM/4;       // float4 count per A stage
    constexpr int B4 = BK*BN/4;

#define LOAD_STAGE(st, k0)                                                      \
    {                                                                           \
        _Pragma("unroll")                                                       \
        for (int q = 0; q < A4/256; q++) {                                      \
            int idx = q*256 + tid;                                              \
            int k = idx / (BM/4), c4 = (idx % (BM/4))*4;                        \
            int mb = bm + c4;                                                   \
            const float* ga = A + (ll)((k0)+k)*M + (mb < M ? mb : 0);           \
            cpa16(&As[st][k][c4], ga, (mb < M) ? 16 : 0);                       \
        }                                                                       \
        _Pragma("unroll")                                                       \
        for (int q = 0; q < B4/256; q++) {                                      \
            int idx = q*256 + tid;                                              \
            int k = idx / (BN/4), c4 = (idx % (BN/4))*4;                        \
            const float* gb = B + (ll)((k0)+k)*N + bn + c4;                     \
            cpa16(&Bs[st][k][c4], gb, 16);                                      \
        }                                                                       \
    }

    int nk = K >> 4;
    LOAD_STAGE(0, 0);
    cp_commit();
    cp_wait0();
    __syncthreads();

    for (int kt = 0; kt < nk; kt++) {
        int cur = kt & 1;
        if (kt + 1 < nk) { LOAD_STAGE(cur^1, (kt+1)<<4); cp_commit(); }
        #pragma unroll
        for (int kk = 0; kk < BK; kk++) {
            uint32_t au[MI];
            #pragma unroll
            for (int i = 0; i < MI; i += 4)
                *(uint4*)&au[i] = *(const uint4*)&As[cur][kk][ty*MI + i];
            ulonglong2 b01 = *(const ulonglong2*)&Bs[cur][kk][tx*8];
            ulonglong2 b23 = *(const ulonglong2*)&Bs[cur][kk][tx*8+4];
            ull br2[4] = { b01.x, b01.y, b23.x, b23.y };
            #pragma unroll
            for (int i = 0; i < MI; i++) {
                ull a2;
                DUP_F32X2(a2, au[i]);
                #pragma unroll
                for (int j = 0; j < 4; j++)
                    FMA_F32X2(acc2[i][j], a2, br2[j], acc2[i][j]);
            }
        }
        if (kt + 1 < nk) cp_wait0();
        __syncthreads();
    }
#undef LOAD_STAGE

    #pragma unroll
    for (int i=0;i<MI;i++){
        int row = bm + ty*MI + i;
        if (row < M) {
            float sc = rowscale ? rowscale[bz*sRS + row] : 1.f;
            float bb = bias ? bias[row] : 0.f;
            float* cp = C + (ll)row*N + bn + tx*8;
            float2 p0 = *(float2*)&acc2[i][0];
            float2 p1 = *(float2*)&acc2[i][1];
            float2 p2 = *(float2*)&acc2[i][2];
            float2 p3 = *(float2*)&acc2[i][3];
            float4 v0, v1;
            v0.x=p0.x*sc+bb; v0.y=p0.y*sc+bb; v0.z=p1.x*sc+bb; v0.w=p1.y*sc+bb;
            v1.x=p2.x*sc+bb; v1.y=p2.y*sc+bb; v1.z=p3.x*sc+bb; v1.w=p3.y*sc+bb;
            *(float4*)cp = v0; *(float4*)(cp+4) = v1;
        }
    }
}

// ---------------- fuse1 (diagonal 3-tap, flat 2304x2304) ----------------
__global__ void fuse_k(const float* __restrict__ In, float* __restrict__ Out)
{
    int idx = blockIdx.x*blockDim.x + threadIdx.x;
    if (idx >= NB*LL*LL) return;
    int rem = idx % (LL*LL);
    int b   = idx / (LL*LL);
    int r = rem / LL, s = rem % LL;
    const float* base = In + (size_t)b*LL*LL;
    float v = base[rem];
    if (r > 0     && s > 0)     v += base[rem - LL - 1];
    if (r < LL-1  && s < LL-1)  v += base[rem + LL + 1];
    Out[idx] = v;
}

// ---------------- fuse48: perm-fuse-perm collapsed stencil ----------------
__global__ void fuse48_k(const float* __restrict__ In, float* __restrict__ Out)
{
    int idx = blockIdx.x*blockDim.x + threadIdx.x;
    if (idx >= NB*LL*LL) return;
    int rem = idx % (LL*LL);
    int b   = idx / (LL*LL);
    int r = rem / LL, s = rem % LL;
    const float* base = In + (size_t)b*LL*LL;
    float v = base[rem];
    int qr = (r % HF)*HF + r / HF;
    int qs = (s % HF)*HF + s / HF;
    if (qr > 0 && qs > 0) {
        int pr = ((qr-1) % HF)*HF + (qr-1) / HF;
        int ps = ((qs-1) % HF)*HF + (qs-1) / HF;
        v += base[(size_t)pr*LL + ps];
    }
    if (qr < LL-1 && qs < LL-1) {
        int nr = ((qr+1) % HF)*HF + (qr+1) / HF;
        int ns = ((qs+1) % HF)*HF + (qs+1) / HF;
        v += base[(size_t)nr*LL + ns];
    }
    Out[idx] = v;
}

// ---------------- column softmax over rows, scale 10, in-place ----------------
__global__ void softmax_k(float* __restrict__ Ad)
{
    int b   = blockIdx.z;
    int col = blockIdx.x*32 + threadIdx.x;
    int st  = threadIdx.y;
    float* Ab = Ad + (size_t)b*LL*LL;
    const int RP = LL/8;
    __shared__ float red[8][33];

    float mx = -3.4e38f;
    for (int r = st*RP; r < (st+1)*RP; r++)
        mx = fmaxf(mx, Ab[(size_t)r*LL + col]);
    red[st][threadIdx.x] = mx;
    __syncthreads();
    float m = red[0][threadIdx.x];
    #pragma unroll
    for (int s = 1; s < 8; s++) m = fmaxf(m, red[s][threadIdx.x]);
    m *= 10.f;
    __syncthreads();

    float sum = 0.f;
    for (int r = st*RP; r < (st+1)*RP; r++)
        sum += __expf(10.f*Ab[(size_t)r*LL + col] - m);
    red[st][threadIdx.x] = sum;
    __syncthreads();
    float tot = 0.f;
    #pragma unroll
    for (int s = 0; s < 8; s++) tot += red[s][threadIdx.x];
    float inv = 1.f / tot;

    for (int r = st*RP; r < (st+1)*RP; r++) {
        size_t o = (size_t)r*LL + col;
        Ab[o] = __expf(10.f*Ab[o] - m) * inv;
    }
}

// ---------------- deconv gather ----------------
__global__ void deconv_k(const float* __restrict__ Tmp, float* __restrict__ yout)
{
    int idx = blockIdx.x*blockDim.x + threadIdx.x;
    if (idx >= NB*NC*NPIX) return;
    int p = idx % NPIX; int t = idx / NPIX;
    int c = t % NC;     int b = t / NC;
    int yy = p / HW, xx = p % HW;
    const float* T = Tmp + (size_t)b*MM2*LL;
    float acc = 0.f;
    #pragma unroll
    for (int di = 0; di < 2; di++) {
        int i = (yy & 1) + 2*di;
        int d = yy + i - 2;
        if (d < 0) continue;
        int h = d >> 1; if (h >= HF) continue;
        #pragma unroll
        for (int dj = 0; dj < 2; dj++) {
            int j = (xx & 1) + 2*dj;
            int e = xx + j - 2;
            if (e < 0) continue;
            int w = e >> 1; if (w >= HF) continue;
            acc += T[(size_t)(c*16 + i*4 + j)*LL + h*HF + w];
        }
    }
    yout[idx] = acc * 0.25f;
}

// ---------------- im2col for 3x3 pad-1 conv on 96x96 ----------------
__global__ void im2col_k(const float* __restrict__ In, float* __restrict__ X)
{
    int idx = blockIdx.x*blockDim.x + threadIdx.x;
    if (idx >= NB*KK1*NPIX) return;
    int p = idx % NPIX; int t = idx / NPIX;
    int k = t % KK1;    int b = t / KK1;
    int c = k / 9; int tt = k % 9; int dh = tt/3 - 1, dw = tt%3 - 1;
    int yy = p / HW + dh, xx = p % HW + dw;
    float val = 0.f;
    if ((unsigned)yy < HW && (unsigned)xx < HW)
        val = In[(((size_t)b*NC + c)*HW + yy)*HW + xx];
    X[idx] = val;
}

// ---------------- launch ----------------
extern "C" void kernel_launch(void* const* d_in, const int* in_sizes, int n_in,
                              void* d_out, int out_size)
{
    const float* f   = (const float*)d_in[0];
    const float* bim = (const float*)d_in[1];
    const float* w1  = (const float*)d_in[2];
    const float* b1  = (const float*)d_in[3];
    const float* w2  = (const float*)d_in[4];
    const float* b2  = (const float*)d_in[5];
    float* out = (float*)d_out;

    float *WmatT, *Xmat, *bufA, *bufB, *W2T, *Tmp, *yb, *c1, *rn, *w1T, *w2T;
    cudaGetSymbolAddress((void**)&WmatT, g_WmatT);
    cudaGetSymbolAddress((void**)&Xmat,  g_Xmat);
    cudaGetSymbolAddress((void**)&bufA,  g_bufA);
    cudaGetSymbolAddress((void**)&bufB,  g_bufB);
    cudaGetSymbolAddress((void**)&W2T,   g_W2T);
    cudaGetSymbolAddress((void**)&Tmp,   g_Tmp);
    cudaGetSymbolAddress((void**)&yb,    g_y);
    cudaGetSymbolAddress((void**)&c1,    g_c1);
    cudaGetSymbolAddress((void**)&rn,    g_rn);
    cudaGetSymbolAddress((void**)&w1T,   g_w1T);
    cudaGetSymbolAddress((void**)&w2T,   g_w2T);

    const int T = 256;

    build_X_k <<<(NB*KK1*LL + T-1)/T, T>>>(f, Xmat);
    build_WT_k<<<(NB*KK1*LL + T-1)/T, T>>>(bim, WmatT);
    rnorm_k   <<<(NB*LL + T-1)/T, T>>>(WmatT, rn);

    // GEMM1: Y0 = diag(rnorm) * Wmat @ Xmat   -> bufA
    sgemm_nt_k<128><<<dim3(LL/128, LL/128, NB), T>>>(WmatT, Xmat, bufA,
        LL, LL, KK1, (ll)KK1*LL, (ll)KK1*LL, (ll)LL*LL, rn, LL, nullptr);

    // fuse1 -> bufB ; fuse48 -> bufA
    fuse_k  <<<(NB*LL*LL + T-1)/T, T>>>(bufA, bufB);
    fuse48_k<<<(NB*LL*LL + T-1)/T, T>>>(bufB, bufA);

    // softmax (in place, bufA = S)
    softmax_k<<<dim3(LL/32, 1, NB), dim3(32, 8)>>>(bufA);

    // GEMM2: Tmp = W2 @ S
    build_W2T_k<<<(NB*LL*MM2 + T-1)/T, T>>>(bim, W2T);
    sgemm_nt_k<128><<<dim3(LL/128, MM2/128, NB), T>>>(W2T, bufA, Tmp,
        MM2, LL, LL, (ll)LL*MM2, (ll)LL*LL, (ll)MM2*LL, nullptr, 0, nullptr);

    // gather into y (/4)
    deconv_k<<<(NB*NC*NPIX + T-1)/T, T>>>(Tmp, yb);

    // conv1: im2col(y) -> bufB ; (w1 @ X) + b1 -> c1   (BM=64, M=64 exact)
    transpose_w_k<<<(NC*KK1 + T-1)/T, T>>>(w1, w1T);
    im2col_k<<<(NB*KK1*NPIX + T-1)/T, T>>>(yb, bufB);
    sgemm_nt_k<64><<<dim3(NPIX/128, 1, NB), T>>>(w1T, bufB, c1,
        NC, NPIX, KK1, 0, (ll)KK1*NPIX, (ll)NC*NPIX, nullptr, 0, b1);

    // conv2: im2col(c1) -> bufB ; (w2 @ X) + b2 -> out
    transpose_w_k<<<(NC*KK1 + T-1)/T, T>>>(w2, w2T);
    im2col_k<<<(NB*KK1*NPIX + T-1)/T, T>>>(c1, bufB);
    sgemm_nt_k<64><<<dim3(NPIX/128, 1, NB), T>>>(w2T, bufB, out,
        NC, NPIX, KK1, 0, (ll)KK1*NPIX, (ll)NC*NPIX, nullptr, 0, b2);
}

// round 5
// speedup vs baseline: 1.2205x; 1.0220x over previous
#include <cuda_runtime.h>
#include <math.h>
#include <stdint.h>

#define NB   4
#define NC   64
#define HW   96
#define HF   48
#define LL   2304    /* 48*48 */
#define KK1  576     /* C*9   */
#define MM2  1024    /* C*16  */
#define NPIX 9216    /* 96*96 */

typedef long long ll;
typedef unsigned long long ull;

// ---------------- scratch (device globals; no allocation) ----------------
__device__ float g_Xp  [(size_t)NB*LL*KK1];   // A of GEMM1: rows=pixel l, cols=k
__device__ float g_Wm  [(size_t)NB*LL*KK1];   // B of GEMM1: rows=patch n, cols=k
__device__ float g_W2  [(size_t)NB*MM2*LL];   // A of GEMM2: rows=m, cols=l'
__device__ float g_bufA[(size_t)NB*LL*LL];
__device__ float g_bufB[(size_t)NB*LL*LL];
__device__ float g_Tmp [(size_t)NB*MM2*LL];
__device__ float g_y   [(size_t)NB*NC*NPIX];
__device__ float g_c1  [(size_t)NB*NC*NPIX];
__device__ float g_rn  [NB*LL];
__device__ float g_w1T [KK1*NC];
__device__ float g_w2T [KK1*NC];

// ---------------- builders ----------------
// Xp[b][p][k] = fd_pad[c, fh+dh, fw+dw], p=(fh,fw), k=(c,dh,dw)
__global__ void build_Xp_k(const float* __restrict__ f, float* __restrict__ X)
{
    int idx = blockIdx.x*blockDim.x + threadIdx.x;
    if (idx >= NB*LL*KK1) return;
    int k = idx % KK1; int t = idx / KK1;
    int p = t % LL;    int b = t / LL;
    int c  = k / 9;  int tt = k % 9; int dh = tt/3, dw = tt%3;
    int fh = p / HF, fw = p % HF;
    int u = fh + dh - 1, v = fw + dw - 1;
    float val = 0.f;
    if ((unsigned)u < HF && (unsigned)v < HF)
        val = f[(((size_t)b*NC + c)*HW + 2*u)*HW + 2*v];
    X[idx] = val;
}

// Wm[b][n][k] : g=n*64+c -> (c0,h0,w0); value = bd_pad[c0,h0+dh,w0+dw]
__global__ void build_W_k(const float* __restrict__ bimg, float* __restrict__ W)
{
    int idx = blockIdx.x*blockDim.x + threadIdx.x;
    if (idx >= NB*LL*KK1) return;
    int k = idx % KK1; int t = idx / KK1;
    int n = t % LL;    int b = t / LL;
    int c  = k / 9;  int tt = k % 9; int dh = tt/3, dw = tt%3;
    int g = n*NC + c;
    int c0 = g / LL; int rr = g % LL; int h0 = rr / HF, w0 = rr % HF;
    int u = h0 + dh - 1, v = w0 + dw - 1;
    float val = 0.f;
    if ((unsigned)u < HF && (unsigned)v < HF)
        val = bimg[(((size_t)b*NC + c0)*HW + 2*u)*HW + 2*v];
    W[idx] = val;
}

// W2[b][m][l'] = b[c0, 2h0+2-i, 2w0+2-j], m=c*16+i*4+j, g=l'*64+c
__global__ void build_W2_k(const float* __restrict__ bimg, float* __restrict__ W2)
{
    int idx = blockIdx.x*blockDim.x + threadIdx.x;
    if (idx >= NB*MM2*LL) return;
    int l = idx % LL; int t = idx / LL;
    int m = t % MM2;  int b = t / MM2;
    int c = m / 16; int tt = m % 16; int i = tt/4, j = tt%4;
    int g = l*NC + c;
    int c0 = g / LL; int rr = g % LL; int h0 = rr / HF, w0 = rr % HF;
    int u = 2*h0 + 2 - i, v = 2*w0 + 2 - j;
    float val = 0.f;
    if ((unsigned)u < HW && (unsigned)v < HW)
        val = bimg[(((size_t)b*NC + c0)*HW + u)*HW + v];
    W2[idx] = val;
}

// rnorm: warp per (b,n) row of Wm (row-contiguous)
__global__ void rnorm_k(const float* __restrict__ W, float* __restrict__ rn)
{
    int warp = (blockIdx.x*blockDim.x + threadIdx.x) >> 5;
    int lane = threadIdx.x & 31;
    if (warp >= NB*LL) return;
    const float* row = W + (size_t)warp*KK1;
    float s = 0.f;
    for (int k = lane; k < KK1; k += 32) { float v = row[k]; s += v*v; }
    #pragma unroll
    for (int o = 16; o; o >>= 1) s += __shfl_xor_sync(0xffffffffu, s, o);
    if (lane == 0) rn[warp] = 1.0f / fmaxf(sqrtf(s), 1e-4f);
}

__global__ void transpose_w_k(const float* __restrict__ w, float* __restrict__ wT)
{
    int idx = blockIdx.x*blockDim.x + threadIdx.x;
    if (idx >= NC*KK1) return;
    int k = idx % KK1, c = idx / KK1;
    wT[(size_t)k*NC + c] = w[idx];
}

// ---------------- PTX helpers ----------------
__device__ __forceinline__ void cpa16f(float* s, const float* g)
{
    uint32_t sa = (uint32_t)__cvta_generic_to_shared(s);
    asm volatile("cp.async.cg.shared.global [%0], [%1], 16;\n" :: "r"(sa), "l"(g));
}
__device__ __forceinline__ void cpa16p(float* s, const float* g, int bytes)
{
    uint32_t sa = (uint32_t)__cvta_generic_to_shared(s);
    asm volatile("cp.async.cg.shared.global [%0], [%1], 16, %2;\n"
                 :: "r"(sa), "l"(g), "r"(bytes));
}
__device__ __forceinline__ void cp_commit() { asm volatile("cp.async.commit_group;\n"); }
__device__ __forceinline__ void cp_wait0()  { asm volatile("cp.async.wait_group 0;\n"); }

#define FMA_F32X2(d, a, b, c) \
    asm("fma.rn.f32x2 %0, %1, %2, %3;" : "=l"(d) : "l"(a), "l"(b), "l"(c))
#define DUP_F32X2(d, r) \
    asm("mov.b64 %0, {%1, %1};" : "=l"(d) : "r"(r))

// split fp32 into two tf32 terms (hi + lo, each as tf32 bit patterns)
__device__ __forceinline__ void split_tf32(float v, uint32_t& hi, uint32_t& lo)
{
    asm("cvt.rna.tf32.f32 %0, %1;" : "=r"(hi) : "f"(v));
    float r = v - __uint_as_float(hi);
    asm("cvt.rna.tf32.f32 %0, %1;" : "=r"(lo) : "f"(r));
}

__device__ __forceinline__ void mma8(float* c, const uint32_t* a, const uint32_t* b)
{
    asm("mma.sync.aligned.m16n8k8.row.col.f32.tf32.tf32.f32 "
        "{%0,%1,%2,%3}, {%4,%5,%6,%7}, {%8,%9}, {%0,%1,%2,%3};"
        : "+f"(c[0]), "+f"(c[1]), "+f"(c[2]), "+f"(c[3])
        : "r"(a[0]), "r"(a[1]), "r"(a[2]), "r"(a[3]), "r"(b[0]), "r"(b[1]));
}

// ---------------- mma.sync tf32 3-split GEMM (NT): C = colscale(n)*(A@B^T) ----------------
// A: M x K row-major (K contig), B: N x K row-major (K contig). M,N mult of 128; K mult of 16.
#define PIT 20
__global__ __launch_bounds__(256) void mmagemm_k(
    const float* __restrict__ Ag, const float* __restrict__ Bg, float* __restrict__ Cg,
    int M, int N, int K, ll sA, ll sB, ll sC,
    const float* __restrict__ colscale, int sCS)
{
    int bz = blockIdx.z;
    const float* A = Ag + (ll)bz*sA;
    const float* B = Bg + (ll)bz*sB;
    float*       C = Cg + (ll)bz*sC;
    int bm = blockIdx.y*128, bn = blockIdx.x*128;
    int tid = threadIdx.x;
    int wid = tid >> 5, lane = tid & 31;
    int wm = wid & 1, wn = wid >> 1;          // warp grid 2(M) x 4(N); warp tile 64x32
    int lm = lane >> 2, lk = lane & 3;

    __shared__ float As[2][128][PIT];
    __shared__ float Bs[2][128][PIT];

    float acc[4][4][4];                        // [mf][nf][c0..c3]
    #pragma unroll
    for (int i=0;i<4;i++)
        #pragma unroll
        for (int j=0;j<4;j++)
            #pragma unroll
            for (int q=0;q<4;q++) acc[i][j][q] = 0.f;

#define LOADSTAGE(st, kc)                                                       \
    {                                                                           \
        int k0 = (kc)*16;                                                       \
        _Pragma("unroll")                                                       \
        for (int q = 0; q < 2; q++) {                                           \
            int idx = q*256 + tid;                                              \
            int row = idx >> 2, ko = (idx & 3)*4;                               \
            cpa16f(&As[st][row][ko], A + (ll)(bm+row)*K + k0 + ko);             \
            cpa16f(&Bs[st][row][ko], B + (ll)(bn+row)*K + k0 + ko);             \
        }                                                                       \
        cp_commit();                                                            \
    }

    int nk = K >> 4;
    LOADSTAGE(0, 0);
    cp_wait0();
    __syncthreads();

    for (int kt = 0; kt < nk; kt++) {
        int cur = kt & 1;
        if (kt + 1 < nk) LOADSTAGE(cur^1, kt+1);
        #pragma unroll
        for (int ks = 0; ks < 2; ks++) {
            int kb = ks*8 + lk;
            uint32_t ah[4][4], al[4][4], bh[4][2], bl[4][2];
            #pragma unroll
            for (int mf = 0; mf < 4; mf++) {
                int m = wm*64 + mf*16 + lm;
                split_tf32(As[cur][m  ][kb  ], ah[mf][0], al[mf][0]);
                split_tf32(As[cur][m+8][kb  ], ah[mf][1], al[mf][1]);
                split_tf32(As[cur][m  ][kb+4], ah[mf][2], al[mf][2]);
                split_tf32(As[cur][m+8][kb+4], ah[mf][3], al[mf][3]);
            }
            #pragma unroll
            for (int nf = 0; nf < 4; nf++) {
                int n = wn*32 + nf*8 + lm;
                split_tf32(Bs[cur][n][kb  ], bh[nf][0], bl[nf][0]);
                split_tf32(Bs[cur][n][kb+4], bh[nf][1], bl[nf][1]);
            }
            #pragma unroll
            for (int mf = 0; mf < 4; mf++)
                #pragma unroll
                for (int nf = 0; nf < 4; nf++) {
                    mma8(acc[mf][nf], ah[mf], bh[nf]);
                    mma8(acc[mf][nf], ah[mf], bl[nf]);
                    mma8(acc[mf][nf], al[mf], bh[nf]);
                }
        }
        if (kt + 1 < nk) cp_wait0();
        __syncthreads();
    }
#undef LOADSTAGE

    // epilogue
    #pragma unroll
    for (int nf = 0; nf < 4; nf++) {
        int n0 = bn + wn*32 + nf*8 + 2*lk;
        float s0 = 1.f, s1 = 1.f;
        if (colscale) {
            s0 = __ldg(&colscale[bz*sCS + n0]);
            s1 = __ldg(&colscale[bz*sCS + n0 + 1]);
        }
        #pragma unroll
        for (int mf = 0; mf < 4; mf++) {
            int m0 = bm + wm*64 + mf*16 + lm;
            float2 v0 = make_float2(acc[mf][nf][0]*s0, acc[mf][nf][1]*s1);
            float2 v1 = make_float2(acc[mf][nf][2]*s0, acc[mf][nf][3]*s1);
            *(float2*)&C[(ll)m0*N + n0]     = v0;
            *(float2*)&C[(ll)(m0+8)*N + n0] = v1;
        }
    }
}

// ---------------- scalar NT SGEMM (FFMA2) for the conv layers ----------------
template<int BM>
__global__ __launch_bounds__(256, 2) void sgemm_nt_k(
    const float* __restrict__ Ag, const float* __restrict__ Bg, float* __restrict__ Cg,
    int M, int N, int K, ll sA, ll sB, ll sC,
    const float* __restrict__ bias)
{
    constexpr int BN = 128, BK = 16;
    constexpr int MI = BM / 16;
    int bz = blockIdx.z;
    const float* A = Ag + (ll)bz*sA;
    const float* B = Bg + (ll)bz*sB;
    float*       C = Cg + (ll)bz*sC;
    int bm = blockIdx.y*BM, bn = blockIdx.x*BN;
    int tid = threadIdx.x;
    int tx = tid & 15, ty = tid >> 4;

    __shared__ float As[2][BK][BM+4];
    __shared__ float Bs[2][BK][BN+4];

    ull acc2[MI][4];
    #pragma unroll
    for (int i=0;i<MI;i++)
        #pragma unroll
        for (int j=0;j<4;j++) acc2[i][j] = 0ull;

    constexpr int A4 = BK*BM/4;
    constexpr int B4 = BK*BN/4;

#define LOAD_STAGE(st, k0)                                                      \
    {                                                                           \
        _Pragma("unroll")                                                       \
        for (int q = 0; q < A4/256; q++) {                                      \
            int idx = q*256 + tid;                                              \
            int k = idx / (BM/4), c4 = (idx % (BM/4))*4;                        \
            int mb = bm + c4;                                                   \
            const float* ga = A + (ll)((k0)+k)*M + (mb < M ? mb : 0);           \
            cpa16p(&As[st][k][c4], ga, (mb < M) ? 16 : 0);                      \
        }                                                                       \
        _Pragma("unroll")                                                       \
        for (int q = 0; q < B4/256; q++) {                                      \
            int idx = q*256 + tid;                                              \
            int k = idx / (BN/4), c4 = (idx % (BN/4))*4;                        \
            const float* gb = B + (ll)((k0)+k)*N + bn + c4;                     \
            cpa16p(&Bs[st][k][c4], gb, 16);                                     \
        }                                                                       \
    }

    int nk = K >> 4;
    LOAD_STAGE(0, 0);
    cp_commit();
    cp_wait0();
    __syncthreads();

    for (int kt = 0; kt < nk; kt++) {
        int cur = kt & 1;
        if (kt + 1 < nk) { LOAD_STAGE(cur^1, (kt+1)<<4); cp_commit(); }
        #pragma unroll
        for (int kk = 0; kk < BK; kk++) {
            uint32_t au[MI];
            #pragma unroll
            for (int i = 0; i < MI; i += 4)
                *(uint4*)&au[i] = *(const uint4*)&As[cur][kk][ty*MI + i];
            ulonglong2 b01 = *(const ulonglong2*)&Bs[cur][kk][tx*8];
            ulonglong2 b23 = *(const ulonglong2*)&Bs[cur][kk][tx*8+4];
            ull br2[4] = { b01.x, b01.y, b23.x, b23.y };
            #pragma unroll
            for (int i = 0; i < MI; i++) {
                ull a2;
                DUP_F32X2(a2, au[i]);
                #pragma unroll
                for (int j = 0; j < 4; j++)
                    FMA_F32X2(acc2[i][j], a2, br2[j], acc2[i][j]);
            }
        }
        if (kt + 1 < nk) cp_wait0();
        __syncthreads();
    }
#undef LOAD_STAGE

    #pragma unroll
    for (int i=0;i<MI;i++){
        int row = bm + ty*MI + i;
        if (row < M) {
            float bb = bias ? bias[row] : 0.f;
            float* cp = C + (ll)row*N + bn + tx*8;
            float2 p0 = *(float2*)&acc2[i][0];
            float2 p1 = *(float2*)&acc2[i][1];
            float2 p2 = *(float2*)&acc2[i][2];
            float2 p3 = *(float2*)&acc2[i][3];
            float4 v0, v1;
            v0.x=p0.x+bb; v0.y=p0.y+bb; v0.z=p1.x+bb; v0.w=p1.y+bb;
            v1.x=p2.x+bb; v1.y=p2.y+bb; v1.z=p3.x+bb; v1.w=p3.y+bb;
            *(float4*)cp = v0; *(float4*)(cp+4) = v1;
        }
    }
}

// ---------------- merged fuse: A2 = F48(F1(Y)) in one pass ----------------
__device__ __forceinline__ float loadT(const float* __restrict__ base, int a, int b)
{
    float v = base[(size_t)a*LL + b];
    if (a > 0    && b > 0)    v += base[(size_t)(a-1)*LL + (b-1)];
    if (a < LL-1 && b < LL-1) v += base[(size_t)(a+1)*LL + (b+1)];
    return v;
}
__global__ void fuse2_k(const float* __restrict__ In, float* __restrict__ Out)
{
    int idx = blockIdx.x*blockDim.x + threadIdx.x;
    if (idx >= NB*LL*LL) return;
    int rem = idx % (LL*LL);
    int b   = idx / (LL*LL);
    int r = rem / LL, s = rem % LL;
    const float* base = In + (size_t)b*LL*LL;
    float v = loadT(base, r, s);
    int qr = (r % HF)*HF + r / HF;
    int qs = (s % HF)*HF + s / HF;
    if (qr > 0 && qs > 0) {
        int pr = ((qr-1) % HF)*HF + (qr-1) / HF;
        int ps = ((qs-1) % HF)*HF + (qs-1) / HF;
        v += loadT(base, pr, ps);
    }
    if (qr < LL-1 && qs < LL-1) {
        int nr = ((qr+1) % HF)*HF + (qr+1) / HF;
        int ns = ((qs+1) % HF)*HF + (qs+1) / HF;
        v += loadT(base, nr, ns);
    }
    Out[idx] = v;
}

// ---------------- row softmax (contiguous), scale 10, in-place ----------------
__global__ void softmax_row_k(float* __restrict__ S)
{
    int row = blockIdx.x;
    int b   = blockIdx.y;
    float* src = S + ((size_t)b*LL + row)*LL;
    int tid = threadIdx.x;
    __shared__ float red[32];

    float x[9];
    float mx = -3.4e38f;
    #pragma unroll
    for (int q = 0; q < 9; q++) {
        x[q] = src[q*256 + tid];
        mx = fmaxf(mx, x[q]);
    }
    #pragma unroll
    for (int o = 16; o; o >>= 1) mx = fmaxf(mx, __shfl_xor_sync(0xffffffffu, mx, o));
    if ((tid & 31) == 0) red[tid >> 5] = mx;
    __syncthreads();
    if (tid < 32) {
        float m2 = red[tid & 7];
        #pragma unroll
        for (int o = 4; o; o >>= 1) m2 = fmaxf(m2, __shfl_xor_sync(0xffffffffu, m2, o));
        red[tid] = m2;
    }
    __syncthreads();
    float m = red[0] * 10.f;

    float e[9], sum = 0.f;
    #pragma unroll
    for (int q = 0; q < 9; q++) { e[q] = __expf(10.f*x[q] - m); sum += e[q]; }
    #pragma unroll
    for (int o = 16; o; o >>= 1) sum += __shfl_xor_sync(0xffffffffu, sum, o);
    __syncthreads();
    if ((tid & 31) == 0) red[tid >> 5] = sum;
    __syncthreads();
    if (tid < 32) {
        float s2 = red[tid & 7];
        #pragma unroll
        for (int o = 4; o; o >>= 1) s2 += __shfl_xor_sync(0xffffffffu, s2, o);
        red[tid] = s2;
    }
    __syncthreads();
    float inv = 1.f / red[0];

    #pragma unroll
    for (int q = 0; q < 9; q++)
        src[q*256 + tid] = e[q] * inv;
}

// ---------------- deconv gather ----------------
__global__ void deconv_k(const float* __restrict__ Tmp, float* __restrict__ yout)
{
    int idx = blockIdx.x*blockDim.x + threadIdx.x;
    if (idx >= NB*NC*NPIX) return;
    int p = idx % NPIX; int t = idx / NPIX;
    int c = t % NC;     int b = t / NC;
    int yy = p / HW, xx = p % HW;
    const float* T = Tmp + (size_t)b*MM2*LL;
    float acc = 0.f;
    #pragma unroll
    for (int di = 0; di < 2; di++) {
        int i = (yy & 1) + 2*di;
        int d = yy + i - 2;
        if (d < 0) continue;
        int h = d >> 1; if (h >= HF) continue;
        #pragma unroll
        for (int dj = 0; dj < 2; dj++) {
            int j = (xx & 1) + 2*dj;
            int e = xx + j - 2;
            if (e < 0) continue;
            int w = e >> 1; if (w >= HF) continue;
            acc += T[(size_t)(c*16 + i*4 + j)*LL + h*HF + w];
        }
    }
    yout[idx] = acc * 0.25f;
}

// ---------------- im2col for 3x3 pad-1 conv on 96x96 (K-major) ----------------
__global__ void im2col_k(const float* __restrict__ In, float* __restrict__ X)
{
    int idx = blockIdx.x*blockDim.x + threadIdx.x;
    if (idx >= NB*KK1*NPIX) return;
    int p = idx % NPIX; int t = idx / NPIX;
    int k = t % KK1;    int b = t / KK1;
    int c = k / 9; int tt = k % 9; int dh = tt/3 - 1, dw = tt%3 - 1;
    int yy = p / HW + dh, xx = p % HW + dw;
    float val = 0.f;
    if ((unsigned)yy < HW && (unsigned)xx < HW)
        val = In[(((size_t)b*NC + c)*HW + yy)*HW + xx];
    X[idx] = val;
}

// ---------------- launch ----------------
extern "C" void kernel_launch(void* const* d_in, const int* in_sizes, int n_in,
                              void* d_out, int out_size)
{
    const float* f   = (const float*)d_in[0];
    const float* bim = (const float*)d_in[1];
    const float* w1  = (const float*)d_in[2];
    const float* b1  = (const float*)d_in[3];
    const float* w2  = (const float*)d_in[4];
    const float* b2  = (const float*)d_in[5];
    float* out = (float*)d_out;

    float *Xp,*Wm,*W2,*bufA,*bufB,*Tmp,*yb,*c1,*rn,*w1T,*w2T;
    cudaGetSymbolAddress((void**)&Xp,   g_Xp);
    cudaGetSymbolAddress((void**)&Wm,   g_Wm);
    cudaGetSymbolAddress((void**)&W2,   g_W2);
    cudaGetSymbolAddress((void**)&bufA, g_bufA);
    cudaGetSymbolAddress((void**)&bufB, g_bufB);
    cudaGetSymbolAddress((void**)&Tmp,  g_Tmp);
    cudaGetSymbolAddress((void**)&yb,   g_y);
    cudaGetSymbolAddress((void**)&c1,   g_c1);
    cudaGetSymbolAddress((void**)&rn,   g_rn);
    cudaGetSymbolAddress((void**)&w1T,  g_w1T);
    cudaGetSymbolAddress((void**)&w2T,  g_w2T);

    const int T = 256;

    build_Xp_k<<<(NB*LL*KK1 + T-1)/T, T>>>(f, Xp);
    build_W_k <<<(NB*LL*KK1 + T-1)/T, T>>>(bim, Wm);
    rnorm_k   <<<(NB*LL*32 + T-1)/T, T>>>(Wm, rn);

    // GEMM1 (mma.sync tf32 3-split): bufA[l][n] = rn[n] * Xp[l]·Wm[n]  (= Y0^T)
    mmagemm_k<<<dim3(LL/128, LL/128, NB), T>>>(Xp, Wm, bufA,
        LL, LL, KK1, (ll)LL*KK1, (ll)LL*KK1, (ll)LL*LL, rn, LL);

    // merged fuse chain (one pass)
    fuse2_k<<<(NB*LL*LL + T-1)/T, T>>>(bufA, bufB);

    // row softmax in-place -> S = bufB
    softmax_row_k<<<dim3(LL, NB), 256>>>(bufB);

    // GEMM2 (mma.sync tf32 3-split): Tmp[m][l] = sum_l' W2[m][l'] * S[l][l']
    build_W2_k<<<(NB*MM2*LL + T-1)/T, T>>>(bim, W2);
    mmagemm_k<<<dim3(LL/128, MM2/128, NB), T>>>(W2, bufB, Tmp,
        MM2, LL, LL, (ll)MM2*LL, (ll)LL*LL, (ll)MM2*LL, nullptr, 0);

    // gather into y (/4)
    deconv_k<<<(NB*NC*NPIX + T-1)/T, T>>>(Tmp, yb);

    // conv1 / conv2 (scalar FFMA2 path), im2col staged in bufA (free now)
    transpose_w_k<<<(NC*KK1 + T-1)/T, T>>>(w1, w1T);
    im2col_k<<<(NB*KK1*NPIX + T-1)/T, T>>>(yb, bufA);
    sgemm_nt_k<64><<<dim3(NPIX/128, 1, NB), T>>>(w1T, bufA, c1,
        NC, NPIX, KK1, 0, (ll)KK1*NPIX, (ll)NC*NPIX, b1);

    transpose_w_k<<<(NC*KK1 + T-1)/T, T>>>(w2, w2T);
    im2col_k<<<(NB*KK1*NPIX + T-1)/T, T>>>(c1, bufA);
    sgemm_nt_k<64><<<dim3(NPIX/128, 1, NB), T>>>(w2T, bufA, out,
        NC, NPIX, KK1, 0, (ll)KK1*NPIX, (ll)NC*NPIX, b2);
}

// round 7
// speedup vs baseline: 1.2517x; 1.0256x over previous
#include <cuda_runtime.h>
#include <math.h>
#include <stdint.h>

#define NB   4
#define NC   64
#define HW   96
#define HF   48
#define LL   2304    /* 48*48 */
#define KK1  576     /* C*9   */
#define MM2  1024    /* C*16  */
#define NPIX 9216    /* 96*96 */

typedef long long ll;
typedef unsigned long long ull;

// ---------------- scratch (device globals; no allocation) ----------------
__device__ uint2 g_Xp  [(size_t)NB*LL*KK1];   // (hi,lo) tf32 pairs
__device__ uint2 g_Wm  [(size_t)NB*LL*KK1];
__device__ uint2 g_W2  [(size_t)NB*MM2*LL];
__device__ uint2 g_Sp  [(size_t)NB*LL*LL];
__device__ float g_bufA[(size_t)NB*LL*LL];
__device__ float g_bufB[(size_t)NB*LL*LL];
__device__ float g_Tmp [(size_t)NB*MM2*LL];
__device__ float g_y   [(size_t)NB*NC*NPIX];
__device__ float g_c1  [(size_t)NB*NC*NPIX];
__device__ float g_rn  [NB*LL];
__device__ float g_w1T [KK1*NC];
__device__ float g_w2T [KK1*NC];

// split fp32 into two tf32 terms (bit patterns)
__device__ __forceinline__ uint2 split2_tf32(float v)
{
    uint32_t hi, lo;
    asm("cvt.rna.tf32.f32 %0, %1;" : "=r"(hi) : "f"(v));
    float r = v - __uint_as_float(hi);
    asm("cvt.rna.tf32.f32 %0, %1;" : "=r"(lo) : "f"(r));
    return make_uint2(hi, lo);
}

// ---------------- builders ----------------
__global__ void build_Xp_k(const float* __restrict__ f, uint2* __restrict__ X)
{
    int idx = blockIdx.x*blockDim.x + threadIdx.x;
    if (idx >= NB*LL*KK1) return;
    int k = idx % KK1; int t = idx / KK1;
    int p = t % LL;    int b = t / LL;
    int c  = k / 9;  int tt = k % 9; int dh = tt/3, dw = tt%3;
    int fh = p / HF, fw = p % HF;
    int u = fh + dh - 1, v = fw + dw - 1;
    float val = 0.f;
    if ((unsigned)u < HF && (unsigned)v < HF)
        val = f[(((size_t)b*NC + c)*HW + 2*u)*HW + 2*v];
    X[idx] = split2_tf32(val);
}

__global__ void build_W_k(const float* __restrict__ bimg, uint2* __restrict__ W)
{
    int idx = blockIdx.x*blockDim.x + threadIdx.x;
    if (idx >= NB*LL*KK1) return;
    int k = idx % KK1; int t = idx / KK1;
    int n = t % LL;    int b = t / LL;
    int c  = k / 9;  int tt = k % 9; int dh = tt/3, dw = tt%3;
    int g = n*NC + c;
    int c0 = g / LL; int rr = g % LL; int h0 = rr / HF, w0 = rr % HF;
    int u = h0 + dh - 1, v = w0 + dw - 1;
    float val = 0.f;
    if ((unsigned)u < HF && (unsigned)v < HF)
        val = bimg[(((size_t)b*NC + c0)*HW + 2*u)*HW + 2*v];
    W[idx] = split2_tf32(val);
}

__global__ void build_W2_k(const float* __restrict__ bimg, uint2* __restrict__ W2)
{
    int idx = blockIdx.x*blockDim.x + threadIdx.x;
    if (idx >= NB*MM2*LL) return;
    int l = idx % LL; int t = idx / LL;
    int m = t % MM2;  int b = t / MM2;
    int c = m / 16; int tt = m % 16; int i = tt/4, j = tt%4;
    int g = l*NC + c;
    int c0 = g / LL; int rr = g % LL; int h0 = rr / HF, w0 = rr % HF;
    int u = 2*h0 + 2 - i, v = 2*w0 + 2 - j;
    float val = 0.f;
    if ((unsigned)u < HW && (unsigned)v < HW)
        val = bimg[(((size_t)b*NC + c0)*HW + u)*HW + v];
    W2[idx] = split2_tf32(val);
}

// rnorm: warp per (b,n) row of Wm pairs (hi+lo ~ exact)
__global__ void rnorm_k(const uint2* __restrict__ W, float* __restrict__ rn)
{
    int warp = (blockIdx.x*blockDim.x + threadIdx.x) >> 5;
    int lane = threadIdx.x & 31;
    if (warp >= NB*LL) return;
    const uint2* row = W + (size_t)warp*KK1;
    float s = 0.f;
    for (int k = lane; k < KK1; k += 32) {
        uint2 p = row[k];
        float v = __uint_as_float(p.x) + __uint_as_float(p.y);
        s += v*v;
    }
    #pragma unroll
    for (int o = 16; o; o >>= 1) s += __shfl_xor_sync(0xffffffffu, s, o);
    if (lane == 0) rn[warp] = 1.0f / fmaxf(sqrtf(s), 1e-4f);
}

__global__ void transpose_w_k(const float* __restrict__ w, float* __restrict__ wT)
{
    int idx = blockIdx.x*blockDim.x + threadIdx.x;
    if (idx >= NC*KK1) return;
    int k = idx % KK1, c = idx / KK1;
    wT[(size_t)k*NC + c] = w[idx];
}

// ---------------- PTX helpers ----------------
__device__ __forceinline__ void cpa16(void* s, const void* g)
{
    uint32_t sa = (uint32_t)__cvta_generic_to_shared(s);
    asm volatile("cp.async.cg.shared.global [%0], [%1], 16;\n" :: "r"(sa), "l"(g));
}
__device__ __forceinline__ void cpa16p(void* s, const void* g, int bytes)
{
    uint32_t sa = (uint32_t)__cvta_generic_to_shared(s);
    asm volatile("cp.async.cg.shared.global [%0], [%1], 16, %2;\n"
                 :: "r"(sa), "l"(g), "r"(bytes));
}
__device__ __forceinline__ void cp_commit() { asm volatile("cp.async.commit_group;\n"); }
__device__ __forceinline__ void cp_wait0()  { asm volatile("cp.async.wait_group 0;\n"); }

#define FMA_F32X2(d, a, b, c) \
    asm("fma.rn.f32x2 %0, %1, %2, %3;" : "=l"(d) : "l"(a), "l"(b), "l"(c))
#define DUP_F32X2(d, r) \
    asm("mov.b64 %0, {%1, %1};" : "=l"(d) : "r"(r))

__device__ __forceinline__ void mma8(float* c, const uint32_t* a, const uint32_t* b)
{
    asm("mma.sync.aligned.m16n8k8.row.col.f32.tf32.tf32.f32 "
        "{%0,%1,%2,%3}, {%4,%5,%6,%7}, {%8,%9}, {%0,%1,%2,%3};"
        : "+f"(c[0]), "+f"(c[1]), "+f"(c[2]), "+f"(c[3])
        : "r"(a[0]), "r"(a[1]), "r"(a[2]), "r"(a[3]), "r"(b[0]), "r"(b[1]));
}

// ---------------- mma.sync tf32 pair GEMM (NT): C = colscale(n)*(A@B^T) ----------------
// A: M x K pairs row-major, B: N x K pairs row-major. M,N mult of 128; K mult of 16 (pairs).
#define PITP 20   /* pair pitch: row stride = 40 words == 8 mod 32 -> conflict-free frags */
#define MMASMEM (2*128*PITP*8*2)   /* 81920 B: As + Bs, 2 stages */

__global__ __launch_bounds__(256, 2) void mmagemm_k(
    const uint2* __restrict__ Ag, const uint2* __restrict__ Bg, float* __restrict__ Cg,
    int M, int N, int K, ll sA, ll sB, ll sC,
    const float* __restrict__ colscale, int sCS)
{
    extern __shared__ uint2 sm[];
    uint2* As = sm;                    // [2][128][PITP]
    uint2* Bs = sm + 2*128*PITP;
    int bz = blockIdx.z;
    const uint2* A = Ag + (ll)bz*sA;
    const uint2* B = Bg + (ll)bz*sB;
    float*       C = Cg + (ll)bz*sC;
    int bm = blockIdx.y*128, bn = blockIdx.x*128;
    int tid = threadIdx.x;
    int wid = tid >> 5, lane = tid & 31;
    int wm = wid & 1, wn = wid >> 1;          // warp grid 2(M) x 4(N); warp tile 64x32
    int lm = lane >> 2, lk = lane & 3;

    float acc[4][4][4];
    #pragma unroll
    for (int i=0;i<4;i++)
        #pragma unroll
        for (int j=0;j<4;j++)
            #pragma unroll
            for (int q=0;q<4;q++) acc[i][j][q] = 0.f;

    // per-stage load: A,B tiles 128 rows x 16 pairs; 16B = 2 pairs; 1024 chunks/matrix/stage
#define LOADSTAGE(st, kc)                                                       \
    {                                                                           \
        int k0 = (kc)*16;                                                       \
        _Pragma("unroll")                                                       \
        for (int q = 0; q < 4; q++) {                                           \
            int idx = q*256 + tid;                                              \
            int row = idx >> 3, ch = (idx & 7)*2;                               \
            cpa16(&As[((st)*128+row)*PITP + ch], A + (ll)(bm+row)*K + k0 + ch); \
            cpa16(&Bs[((st)*128+row)*PITP + ch], B + (ll)(bn+row)*K + k0 + ch); \
        }                                                                       \
        cp_commit();                                                            \
    }

    int nk = K >> 4;
    LOADSTAGE(0, 0);
    cp_wait0();
    __syncthreads();

    for (int kt = 0; kt < nk; kt++) {
        int cur = kt & 1;
        if (kt + 1 < nk) LOADSTAGE(cur^1, kt+1);
        #pragma unroll
        for (int ks = 0; ks < 2; ks++) {
            int kb = ks*8 + lk;
            uint2 bf[4][2];
            #pragma unroll
            for (int nf = 0; nf < 4; nf++) {
                int n = wn*32 + nf*8 + lm;
                bf[nf][0] = Bs[(cur*128+n)*PITP + kb];
                bf[nf][1] = Bs[(cur*128+n)*PITP + kb + 4];
            }
            #pragma unroll
            for (int mf = 0; mf < 4; mf++) {
                int m = wm*64 + mf*16 + lm;
                uint2 a0 = As[(cur*128+m  )*PITP + kb];
                uint2 a1 = As[(cur*128+m+8)*PITP + kb];
                uint2 a2 = As[(cur*128+m  )*PITP + kb + 4];
                uint2 a3 = As[(cur*128+m+8)*PITP + kb + 4];
                uint32_t ah[4] = {a0.x, a1.x, a2.x, a3.x};
                uint32_t al[4] = {a0.y, a1.y, a2.y, a3.y};
                #pragma unroll
                for (int nf = 0; nf < 4; nf++) {
                    uint32_t bh[2] = {bf[nf][0].x, bf[nf][1].x};
                    uint32_t bl[2] = {bf[nf][0].y, bf[nf][1].y};
                    mma8(acc[mf][nf], ah, bh);
                    mma8(acc[mf][nf], ah, bl);
                    mma8(acc[mf][nf], al, bh);
                }
            }
        }
        if (kt + 1 < nk) cp_wait0();
        __syncthreads();
    }
#undef LOADSTAGE

    // epilogue
    #pragma unroll
    for (int nf = 0; nf < 4; nf++) {
        int n0 = bn + wn*32 + nf*8 + 2*lk;
        float s0 = 1.f, s1 = 1.f;
        if (colscale) {
            s0 = __ldg(&colscale[bz*sCS + n0]);
            s1 = __ldg(&colscale[bz*sCS + n0 + 1]);
        }
        #pragma unroll
        for (int mf = 0; mf < 4; mf++) {
            int m0 = bm + wm*64 + mf*16 + lm;
            float2 v0 = make_float2(acc[mf][nf][0]*s0, acc[mf][nf][1]*s1);
            float2 v1 = make_float2(acc[mf][nf][2]*s0, acc[mf][nf][3]*s1);
            *(float2*)&C[(ll)m0*N + n0]     = v0;
            *(float2*)&C[(ll)(m0+8)*N + n0] = v1;
        }
    }
}

// ---------------- scalar NT SGEMM (FFMA2) for the conv layers ----------------
template<int BM>
__global__ __launch_bounds__(256, 2) void sgemm_nt_k(
    const float* __restrict__ Ag, const float* __restrict__ Bg, float* __restrict__ Cg,
    int M, int N, int K, ll sA, ll sB, ll sC,
    const float* __restrict__ bias)
{
    constexpr int BN = 128, BK = 16;
    constexpr int MI = BM / 16;
    int bz = blockIdx.z;
    const float* A = Ag + (ll)bz*sA;
    const float* B = Bg + (ll)bz*sB;
    float*       C = Cg + (ll)bz*sC;
    int bm = blockIdx.y*BM, bn = blockIdx.x*BN;
    int tid = threadIdx.x;
    int tx = tid & 15, ty = tid >> 4;

    __shared__ float As[2][BK][BM+4];
    __shared__ float Bs[2][BK][BN+4];

    ull acc2[MI][4];
    #pragma unroll
    for (int i=0;i<MI;i++)
        #pragma unroll
        for (int j=0;j<4;j++) acc2[i][j] = 0ull;

    constexpr int A4 = BK*BM/4;
    constexpr int B4 = BK*BN/4;

#define LOAD_STAGE(st, k0)                                                      \
    {                                                                           \
        _Pragma("unroll")                                                       \
        for (int q = 0; q < A4/256; q++) {                                      \
            int idx = q*256 + tid;                                              \
            int k = idx / (BM/4), c4 = (idx % (BM/4))*4;                        \
            int mb = bm + c4;                                                   \
            const float* ga = A + (ll)((k0)+k)*M + (mb < M ? mb : 0);           \
            cpa16p(&As[st][k][c4], ga, (mb < M) ? 16 : 0);                      \
        }                                                                       \
        _Pragma("unroll")                                                       \
        for (int q = 0; q < B4/256; q++) {                                      \
            int idx = q*256 + tid;                                              \
            int k = idx / (BN/4), c4 = (idx % (BN/4))*4;                        \
            const float* gb = B + (ll)((k0)+k)*N + bn + c4;                     \
            cpa16p(&Bs[st][k][c4], gb, 16);                                     \
        }                                                                       \
    }

    int nk = K >> 4;
    LOAD_STAGE(0, 0);
    cp_commit();
    cp_wait0();
    __syncthreads();

    for (int kt = 0; kt < nk; kt++) {
        int cur = kt & 1;
        if (kt + 1 < nk) { LOAD_STAGE(cur^1, (kt+1)<<4); cp_commit(); }
        #pragma unroll
        for (int kk = 0; kk < BK; kk++) {
            uint32_t au[MI];
            #pragma unroll
            for (int i = 0; i < MI; i += 4)
                *(uint4*)&au[i] = *(const uint4*)&As[cur][kk][ty*MI + i];
            ulonglong2 b01 = *(const ulonglong2*)&Bs[cur][kk][tx*8];
            ulonglong2 b23 = *(const ulonglong2*)&Bs[cur][kk][tx*8+4];
            ull br2[4] = { b01.x, b01.y, b23.x, b23.y };
            #pragma unroll
            for (int i = 0; i < MI; i++) {
                ull a2;
                DUP_F32X2(a2, au[i]);
                #pragma unroll
                for (int j = 0; j < 4; j++)
                    FMA_F32X2(acc2[i][j], a2, br2[j], acc2[i][j]);
            }
        }
        if (kt + 1 < nk) cp_wait0();
        __syncthreads();
    }
#undef LOAD_STAGE

    #pragma unroll
    for (int i=0;i<MI;i++){
        int row = bm + ty*MI + i;
        if (row < M) {
            float bb = bias ? bias[row] : 0.f;
            float* cp = C + (ll)row*N + bn + tx*8;
            float2 p0 = *(float2*)&acc2[i][0];
            float2 p1 = *(float2*)&acc2[i][1];
            float2 p2 = *(float2*)&acc2[i][2];
            float2 p3 = *(float2*)&acc2[i][3];
            float4 v0, v1;
            v0.x=p0.x+bb; v0.y=p0.y+bb; v0.z=p1.x+bb; v0.w=p1.y+bb;
            v1.x=p2.x+bb; v1.y=p2.y+bb; v1.z=p3.x+bb; v1.w=p3.y+bb;
            *(float4*)cp = v0; *(float4*)(cp+4) = v1;
        }
    }
}

// ---------------- merged fuse: A2 = F48(F1(Y)) in one pass ----------------
__device__ __forceinline__ float loadT(const float* __restrict__ base, int a, int b)
{
    float v = base[(size_t)a*LL + b];
    if (a > 0    && b > 0)    v += base[(size_t)(a-1)*LL + (b-1)];
    if (a < LL-1 && b < LL-1) v += base[(size_t)(a+1)*LL + (b+1)];
    return v;
}
__global__ void fuse2_k(const float* __restrict__ In, float* __restrict__ Out)
{
    int idx = blockIdx.x*blockDim.x + threadIdx.x;
    if (idx >= NB*LL*LL) return;
    int rem = idx % (LL*LL);
    int b   = idx / (LL*LL);
    int r = rem / LL, s = rem % LL;
    const float* base = In + (size_t)b*LL*LL;
    float v = loadT(base, r, s);
    int qr = (r % HF)*HF + r / HF;
    int qs = (s % HF)*HF + s / HF;
    if (qr > 0 && qs > 0) {
        int pr = ((qr-1) % HF)*HF + (qr-1) / HF;
        int ps = ((qs-1) % HF)*HF + (qs-1) / HF;
        v += loadT(base, pr, ps);
    }
    if (qr < LL-1 && qs < LL-1) {
        int nr = ((qr+1) % HF)*HF + (qr+1) / HF;
        int ns = ((qs+1) % HF)*HF + (qs+1) / HF;
        v += loadT(base, nr, ns);
    }
    Out[idx] = v;
}

// ---------------- row softmax, scale 10, writes (hi,lo) pairs ----------------
__global__ void softmax_row_k(const float* __restrict__ In, uint2* __restrict__ Sp)
{
    int row = blockIdx.x;
    int b   = blockIdx.y;
    const float* src = In + ((size_t)b*LL + row)*LL;
    uint2* dst = Sp + ((size_t)b*LL + row)*LL;
    int tid = threadIdx.x;
    __shared__ float red[32];

    float x[9];
    float mx = -3.4e38f;
    #pragma unroll
    for (int q = 0; q < 9; q++) {
        x[q] = src[q*256 + tid];
        mx = fmaxf(mx, x[q]);
    }
    #pragma unroll
    for (int o = 16; o; o >>= 1) mx = fmaxf(mx, __shfl_xor_sync(0xffffffffu, mx, o));
    if ((tid & 31) == 0) red[tid >> 5] = mx;
    __syncthreads();
    if (tid < 32) {
        float m2 = red[tid & 7];
        #pragma unroll
        for (int o = 4; o; o >>= 1) m2 = fmaxf(m2, __shfl_xor_sync(0xffffffffu, m2, o));
        red[tid] = m2;
    }
    __syncthreads();
    float m = red[0] * 10.f;

    float e[9], sum = 0.f;
    #pragma unroll
    for (int q = 0; q < 9; q++) { e[q] = __expf(10.f*x[q] - m); sum += e[q]; }
    #pragma unroll
    for (int o = 16; o; o >>= 1) sum += __shfl_xor_sync(0xffffffffu, sum, o);
    __syncthreads();
    if ((tid & 31) == 0) red[tid >> 5] = sum;
    __syncthreads();
    if (tid < 32) {
        float s2 = red[tid & 7];
        #pragma unroll
        for (int o = 4; o; o >>= 1) s2 += __shfl_xor_sync(0xffffffffu, s2, o);
        red[tid] = s2;
    }
    __syncthreads();
    float inv = 1.f / red[0];

    #pragma unroll
    for (int q = 0; q < 9; q++)
        dst[q*256 + tid] = split2_tf32(e[q] * inv);
}

// ---------------- deconv gather ----------------
__global__ void deconv_k(const float* __restrict__ Tmp, float* __restrict__ yout)
{
    int idx = blockIdx.x*blockDim.x + threadIdx.x;
    if (idx >= NB*NC*NPIX) return;
    int p = idx % NPIX; int t = idx / NPIX;
    int c = t % NC;     int b = t / NC;
    int yy = p / HW, xx = p % HW;
    const float* T = Tmp + (size_t)b*MM2*LL;
    float acc = 0.f;
    #pragma unroll
    for (int di = 0; di < 2; di++) {
        int i = (yy & 1) + 2*di;
        int d = yy + i - 2;
        if (d < 0) continue;
        int h = d >> 1; if (h >= HF) continue;
        #pragma unroll
        for (int dj = 0; dj < 2; dj++) {
            int j = (xx & 1) + 2*dj;
            int e = xx + j - 2;
            if (e < 0) continue;
            int w = e >> 1; if (w >= HF) continue;
            acc += T[(size_t)(c*16 + i*4 + j)*LL + h*HF + w];
        }
    }
    yout[idx] = acc * 0.25f;
}

// ---------------- im2col for 3x3 pad-1 conv on 96x96 (K-major) ----------------
__global__ void im2col_k(const float* __restrict__ In, float* __restrict__ X)
{
    int idx = blockIdx.x*blockDim.x + threadIdx.x;
    if (idx >= NB*KK1*NPIX) return;
    int p = idx % NPIX; int t = idx / NPIX;
    int k = t % KK1;    int b = t / KK1;
    int c = k / 9; int tt = k % 9; int dh = tt/3 - 1, dw = tt%3 - 1;
    int yy = p / HW + dh, xx = p % HW + dw;
    float val = 0.f;
    if ((unsigned)yy < HW && (unsigned)xx < HW)
        val = In[(((size_t)b*NC + c)*HW + yy)*HW + xx];
    X[idx] = val;
}

// ---------------- launch ----------------
extern "C" void kernel_launch(void* const* d_in, const int* in_sizes, int n_in,
                              void* d_out, int out_size)
{
    const float* f   = (const float*)d_in[0];
    const float* bim = (const float*)d_in[1];
    const float* w1  = (const float*)d_in[2];
    const float* b1  = (const float*)d_in[3];
    const float* w2  = (const float*)d_in[4];
    const float* b2  = (const float*)d_in[5];
    float* out = (float*)d_out;

    uint2 *Xp, *Wm, *W2, *Sp;
    float *bufA, *bufB, *Tmp, *yb, *c1, *rn, *w1T, *w2T;
    cudaGetSymbolAddress((void**)&Xp,   g_Xp);
    cudaGetSymbolAddress((void**)&Wm,   g_Wm);
    cudaGetSymbolAddress((void**)&W2,   g_W2);
    cudaGetSymbolAddress((void**)&Sp,   g_Sp);
    cudaGetSymbolAddress((void**)&bufA, g_bufA);
    cudaGetSymbolAddress((void**)&bufB, g_bufB);
    cudaGetSymbolAddress((void**)&Tmp,  g_Tmp);
    cudaGetSymbolAddress((void**)&yb,   g_y);
    cudaGetSymbolAddress((void**)&c1,   g_c1);
    cudaGetSymbolAddress((void**)&rn,   g_rn);
    cudaGetSymbolAddress((void**)&w1T,  g_w1T);
    cudaGetSymbolAddress((void**)&w2T,  g_w2T);

    cudaFuncSetAttribute(mmagemm_k, cudaFuncAttributeMaxDynamicSharedMemorySize, MMASMEM);

    const int T = 256;

    build_Xp_k<<<(NB*LL*KK1 + T-1)/T, T>>>(f, Xp);
    build_W_k <<<(NB*LL*KK1 + T-1)/T, T>>>(bim, Wm);
    rnorm_k   <<<(NB*LL*32 + T-1)/T, T>>>(Wm, rn);

    // GEMM1: bufA[l][n] = rn[n] * Xp[l]·Wm[n]  (= Y0^T)
    mmagemm_k<<<dim3(LL/128, LL/128, NB), T, MMASMEM>>>(Xp, Wm, bufA,
        LL, LL, KK1, (ll)LL*KK1, (ll)LL*KK1, (ll)LL*LL, rn, LL);

    // merged fuse chain (one pass)
    fuse2_k<<<(NB*LL*LL + T-1)/T, T>>>(bufA, bufB);

    // row softmax -> Sp pairs
    softmax_row_k<<<dim3(LL, NB), 256>>>(bufB, Sp);

    // GEMM2: Tmp[m][l] = sum_l' W2[m][l'] * S[l][l']
    build_W2_k<<<(NB*MM2*LL + T-1)/T, T>>>(bim, W2);
    mmagemm_k<<<dim3(LL/128, MM2/128, NB), T, MMASMEM>>>(W2, Sp, Tmp,
        MM2, LL, LL, (ll)MM2*LL, (ll)LL*LL, (ll)MM2*LL, nullptr, 0);

    // gather into y (/4)
    deconv_k<<<(NB*NC*NPIX + T-1)/T, T>>>(Tmp, yb);

    // conv1 / conv2 (scalar FFMA2 path), im2col staged in bufA (free now)
    transpose_w_k<<<(NC*KK1 + T-1)/T, T>>>(w1, w1T);
    im2col_k<<<(NB*KK1*NPIX + T-1)/T, T>>>(yb, bufA);
    sgemm_nt_k<64><<<dim3(NPIX/128, 1, NB), T>>>(w1T, bufA, c1,
        NC, NPIX, KK1, 0, (ll)KK1*NPIX, (ll)NC*NPIX, b1);

    transpose_w_k<<<(NC*KK1 + T-1)/T, T>>>(w2, w2T);
    im2col_k<<<(NB*KK1*NPIX + T-1)/T, T>>>(c1, bufA);
    sgemm_nt_k<64><<<dim3(NPIX/128, 1, NB), T>>>(w2T, bufA, out,
        NC, NPIX, KK1, 0, (ll)KK1*NPIX, (ll)NC*NPIX, b2);
}

// round 8
// speedup vs baseline: 1.2791x; 1.0219x over previous
#include <cuda_runtime.h>
#include <math.h>
#include <stdint.h>

#define NB   4
#define NC   64
#define HW   96
#define HF   48
#define LL   2304    /* 48*48 */
#define KK1  576     /* C*9   */
#define MM2  1024    /* C*16  */
#define NPIX 9216    /* 96*96 */

typedef long long ll;
typedef unsigned long long ull;

// ---------------- scratch (device globals; no allocation) ----------------
__device__ uint2 g_Xp  [(size_t)NB*LL*KK1];   // (hi,lo) tf32 pairs
__device__ uint2 g_Wm  [(size_t)NB*LL*KK1];
__device__ uint2 g_W2  [(size_t)NB*MM2*LL];
__device__ uint2 g_Sp  [(size_t)NB*LL*LL];
__device__ float g_bufA[(size_t)NB*LL*LL];
__device__ float g_bufB[(size_t)NB*LL*LL];
__device__ float g_Tmp [(size_t)NB*MM2*LL];
__device__ float g_y   [(size_t)NB*NC*NPIX];
__device__ float g_c1  [(size_t)NB*NC*NPIX];
__device__ float g_rn  [NB*LL];
__device__ float g_w1T [KK1*NC];
__device__ float g_w2T [KK1*NC];

// split fp32 into two tf32 terms (bit patterns)
__device__ __forceinline__ uint2 split2_tf32(float v)
{
    uint32_t hi, lo;
    asm("cvt.rna.tf32.f32 %0, %1;" : "=r"(hi) : "f"(v));
    float r = v - __uint_as_float(hi);
    asm("cvt.rna.tf32.f32 %0, %1;" : "=r"(lo) : "f"(r));
    return make_uint2(hi, lo);
}

// ---------------- builders ----------------
__global__ void build_Xp_k(const float* __restrict__ f, uint2* __restrict__ X)
{
    int idx = blockIdx.x*blockDim.x + threadIdx.x;
    if (idx >= NB*LL*KK1) return;
    int k = idx % KK1; int t = idx / KK1;
    int p = t % LL;    int b = t / LL;
    int c  = k / 9;  int tt = k % 9; int dh = tt/3, dw = tt%3;
    int fh = p / HF, fw = p % HF;
    int u = fh + dh - 1, v = fw + dw - 1;
    float val = 0.f;
    if ((unsigned)u < HF && (unsigned)v < HF)
        val = f[(((size_t)b*NC + c)*HW + 2*u)*HW + 2*v];
    X[idx] = split2_tf32(val);
}

__global__ void build_W_k(const float* __restrict__ bimg, uint2* __restrict__ W)
{
    int idx = blockIdx.x*blockDim.x + threadIdx.x;
    if (idx >= NB*LL*KK1) return;
    int k = idx % KK1; int t = idx / KK1;
    int n = t % LL;    int b = t / LL;
    int c  = k / 9;  int tt = k % 9; int dh = tt/3, dw = tt%3;
    int g = n*NC + c;
    int c0 = g / LL; int rr = g % LL; int h0 = rr / HF, w0 = rr % HF;
    int u = h0 + dh - 1, v = w0 + dw - 1;
    float val = 0.f;
    if ((unsigned)u < HF && (unsigned)v < HF)
        val = bimg[(((size_t)b*NC + c0)*HW + 2*u)*HW + 2*v];
    W[idx] = split2_tf32(val);
}

__global__ void build_W2_k(const float* __restrict__ bimg, uint2* __restrict__ W2)
{
    int idx = blockIdx.x*blockDim.x + threadIdx.x;
    if (idx >= NB*MM2*LL) return;
    int l = idx % LL; int t = idx / LL;
    int m = t % MM2;  int b = t / MM2;
    int c = m / 16; int tt = m % 16; int i = tt/4, j = tt%4;
    int g = l*NC + c;
    int c0 = g / LL; int rr = g % LL; int h0 = rr / HF, w0 = rr % HF;
    int u = 2*h0 + 2 - i, v = 2*w0 + 2 - j;
    float val = 0.f;
    if ((unsigned)u < HW && (unsigned)v < HW)
        val = bimg[(((size_t)b*NC + c0)*HW + u)*HW + v];
    W2[idx] = split2_tf32(val);
}

// rnorm: warp per (b,n) row of Wm pairs (hi+lo ~ exact)
__global__ void rnorm_k(const uint2* __restrict__ W, float* __restrict__ rn)
{
    int warp = (blockIdx.x*blockDim.x + threadIdx.x) >> 5;
    int lane = threadIdx.x & 31;
    if (warp >= NB*LL) return;
    const uint2* row = W + (size_t)warp*KK1;
    float s = 0.f;
    for (int k = lane; k < KK1; k += 32) {
        uint2 p = row[k];
        float v = __uint_as_float(p.x) + __uint_as_float(p.y);
        s += v*v;
    }
    #pragma unroll
    for (int o = 16; o; o >>= 1) s += __shfl_xor_sync(0xffffffffu, s, o);
    if (lane == 0) rn[warp] = 1.0f / fmaxf(sqrtf(s), 1e-4f);
}

__global__ void transpose_w_k(const float* __restrict__ w, float* __restrict__ wT)
{
    int idx = blockIdx.x*blockDim.x + threadIdx.x;
    if (idx >= NC*KK1) return;
    int k = idx % KK1, c = idx / KK1;
    wT[(size_t)k*NC + c] = w[idx];
}

// ---------------- PTX helpers ----------------
__device__ __forceinline__ void cpa16(void* s, const void* g)
{
    uint32_t sa = (uint32_t)__cvta_generic_to_shared(s);
    asm volatile("cp.async.cg.shared.global [%0], [%1], 16;\n" :: "r"(sa), "l"(g));
}
__device__ __forceinline__ void cpa16p(void* s, const void* g, int bytes)
{
    uint32_t sa = (uint32_t)__cvta_generic_to_shared(s);
    asm volatile("cp.async.cg.shared.global [%0], [%1], 16, %2;\n"
                 :: "r"(sa), "l"(g), "r"(bytes));
}
__device__ __forceinline__ void cp_commit() { asm volatile("cp.async.commit_group;\n"); }
__device__ __forceinline__ void cp_wait0()  { asm volatile("cp.async.wait_group 0;\n"); }

#define FMA_F32X2(d, a, b, c) \
    asm("fma.rn.f32x2 %0, %1, %2, %3;" : "=l"(d) : "l"(a), "l"(b), "l"(c))
#define DUP_F32X2(d, r) \
    asm("mov.b64 %0, {%1, %1};" : "=l"(d) : "r"(r))

__device__ __forceinline__ void mma8(float* c, const uint32_t* a, uint32_t b0, uint32_t b1)
{
    asm("mma.sync.aligned.m16n8k8.row.col.f32.tf32.tf32.f32 "
        "{%0,%1,%2,%3}, {%4,%5,%6,%7}, {%8,%9}, {%0,%1,%2,%3};"
        : "+f"(c[0]), "+f"(c[1]), "+f"(c[2]), "+f"(c[3])
        : "r"(a[0]), "r"(a[1]), "r"(a[2]), "r"(a[3]), "r"(b0), "r"(b1));
}

// ---------------- mma.sync tf32 pair GEMM (NT): C = colscale(n)*(A@B^T) ----------------
// A: M x K pairs row-major, B: N x K pairs row-major. M,N mult of 128; K mult of 16 (pairs).
#define PITP 20   /* pair pitch: row stride = 40 words == 8 mod 32 -> conflict-free frags */
#define STPAIRS (128*PITP)          /* pairs per stage per matrix */
#define MMASMEM (2*STPAIRS*8*2)     /* 81920 B: As + Bs, 2 stages */

__global__ __launch_bounds__(256, 2) void mmagemm_k(
    const uint2* __restrict__ Ag, const uint2* __restrict__ Bg, float* __restrict__ Cg,
    int M, int N, int K, ll sA, ll sB, ll sC,
    const float* __restrict__ colscale, int sCS)
{
    extern __shared__ uint2 sm[];
    uint2* As = sm;                    // [2][128][PITP]
    uint2* Bs = sm + 2*STPAIRS;
    int bz = blockIdx.z;
    const uint2* A = Ag + (ll)bz*sA;
    const uint2* B = Bg + (ll)bz*sB;
    float*       C = Cg + (ll)bz*sC;
    int bm = blockIdx.y*128, bn = blockIdx.x*128;
    int tid = threadIdx.x;
    int wid = tid >> 5, lane = tid & 31;
    int wm = wid & 1, wn = wid >> 1;          // warp grid 2(M) x 4(N); warp tile 64x32
    int lm = lane >> 2, lk = lane & 3;

    float acc[4][4][4];
    #pragma unroll
    for (int i=0;i<4;i++)
        #pragma unroll
        for (int j=0;j<4;j++)
            #pragma unroll
            for (int q=0;q<4;q++) acc[i][j][q] = 0.f;

    // precomputed gmem pointers (advance by +16 pairs each kt) and smem targets
    int r0 = tid >> 3, chq = (tid & 7)*2;
    const uint2* gA[4]; const uint2* gB[4];
    uint2* sAp[4]; uint2* sBp[4];
    #pragma unroll
    for (int q = 0; q < 4; q++) {
        int row = r0 + q*32;
        gA[q] = A + (ll)(bm + row)*K + chq;
        gB[q] = B + (ll)(bn + row)*K + chq;
        sAp[q] = As + row*PITP + chq;
        sBp[q] = Bs + row*PITP + chq;
    }

#define LOADSTAGE(st)                                                           \
    {                                                                           \
        int so = (st)*STPAIRS;                                                  \
        _Pragma("unroll")                                                       \
        for (int q = 0; q < 4; q++) {                                           \
            cpa16(sAp[q] + so, gA[q]);                                          \
            cpa16(sBp[q] + so, gB[q]);                                          \
            gA[q] += 16; gB[q] += 16;                                           \
        }                                                                       \
        cp_commit();                                                            \
    }

    // LDS fragment bases (all loop offsets compile-time constants)
    const uint2* aB0 = As + (wm*64 + lm)*PITP + lk;
    const uint2* bB0 = Bs + (wn*32 + lm)*PITP + lk;

    int nk = K >> 4;
    LOADSTAGE(0);
    cp_wait0();
    __syncthreads();

    for (int kt = 0; kt < nk; kt++) {
        int cur = kt & 1;
        if (kt + 1 < nk) LOADSTAGE(cur^1);
        const uint2* aBc = aB0 + cur*STPAIRS;
        const uint2* bBc = bB0 + cur*STPAIRS;
        #pragma unroll
        for (int ks = 0; ks < 2; ks++) {
            uint2 bf0[4], bf1[4];
            #pragma unroll
            for (int nf = 0; nf < 4; nf++) {
                bf0[nf] = bBc[nf*8*PITP + ks*8];
                bf1[nf] = bBc[nf*8*PITP + ks*8 + 4];
            }
            #pragma unroll
            for (int mf = 0; mf < 4; mf++) {
                uint2 a0 = aBc[(mf*16    )*PITP + ks*8];
                uint2 a1 = aBc[(mf*16 + 8)*PITP + ks*8];
                uint2 a2 = aBc[(mf*16    )*PITP + ks*8 + 4];
                uint2 a3 = aBc[(mf*16 + 8)*PITP + ks*8 + 4];
                uint32_t ah[4] = {a0.x, a1.x, a2.x, a3.x};
                uint32_t al[4] = {a0.y, a1.y, a2.y, a3.y};
                // term-major within mf: same acc reused at distance 4
                #pragma unroll
                for (int nf = 0; nf < 4; nf++)
                    mma8(acc[mf][nf], ah, bf0[nf].x, bf1[nf].x);
                #pragma unroll
                for (int nf = 0; nf < 4; nf++)
                    mma8(acc[mf][nf], ah, bf0[nf].y, bf1[nf].y);
                #pragma unroll
                for (int nf = 0; nf < 4; nf++)
                    mma8(acc[mf][nf], al, bf0[nf].x, bf1[nf].x);
            }
        }
        if (kt + 1 < nk) cp_wait0();
        __syncthreads();
    }
#undef LOADSTAGE

    // epilogue
    #pragma unroll
    for (int nf = 0; nf < 4; nf++) {
        int n0 = bn + wn*32 + nf*8 + 2*lk;
        float s0 = 1.f, s1 = 1.f;
        if (colscale) {
            s0 = __ldg(&colscale[bz*sCS + n0]);
            s1 = __ldg(&colscale[bz*sCS + n0 + 1]);
        }
        #pragma unroll
        for (int mf = 0; mf < 4; mf++) {
            int m0 = bm + wm*64 + mf*16 + lm;
            float2 v0 = make_float2(acc[mf][nf][0]*s0, acc[mf][nf][1]*s1);
            float2 v1 = make_float2(acc[mf][nf][2]*s0, acc[mf][nf][3]*s1);
            *(float2*)&C[(ll)m0*N + n0]     = v0;
            *(float2*)&C[(ll)(m0+8)*N + n0] = v1;
        }
    }
}

// ---------------- scalar NT SGEMM (FFMA2) for the conv layers ----------------
template<int BM>
__global__ __launch_bounds__(256, 2) void sgemm_nt_k(
    const float* __restrict__ Ag, const float* __restrict__ Bg, float* __restrict__ Cg,
    int M, int N, int K, ll sA, ll sB, ll sC,
    const float* __restrict__ bias)
{
    constexpr int BN = 128, BK = 16;
    constexpr int MI = BM / 16;
    int bz = blockIdx.z;
    const float* A = Ag + (ll)bz*sA;
    const float* B = Bg + (ll)bz*sB;
    float*       C = Cg + (ll)bz*sC;
    int bm = blockIdx.y*BM, bn = blockIdx.x*BN;
    int tid = threadIdx.x;
    int tx = tid & 15, ty = tid >> 4;

    __shared__ float As[2][BK][BM+4];
    __shared__ float Bs[2][BK][BN+4];

    ull acc2[MI][4];
    #pragma unroll
    for (int i=0;i<MI;i++)
        #pragma unroll
        for (int j=0;j<4;j++) acc2[i][j] = 0ull;

    constexpr int A4 = BK*BM/4;
    constexpr int B4 = BK*BN/4;

#define LOAD_STAGE(st, k0)                                                      \
    {                                                                           \
        _Pragma("unroll")                                                       \
        for (int q = 0; q < A4/256; q++) {                                      \
            int idx = q*256 + tid;                                              \
            int k = idx / (BM/4), c4 = (idx % (BM/4))*4;                        \
            int mb = bm + c4;                                                   \
            const float* ga = A + (ll)((k0)+k)*M + (mb < M ? mb : 0);           \
            cpa16p(&As[st][k][c4], ga, (mb < M) ? 16 : 0);                      \
        }                                                                       \
        _Pragma("unroll")                                                       \
        for (int q = 0; q < B4/256; q++) {                                      \
            int idx = q*256 + tid;                                              \
            int k = idx / (BN/4), c4 = (idx % (BN/4))*4;                        \
            const float* gb = B + (ll)((k0)+k)*N + bn + c4;                     \
            cpa16p(&Bs[st][k][c4], gb, 16);                                     \
        }                                                                       \
    }

    int nk = K >> 4;
    LOAD_STAGE(0, 0);
    cp_commit();
    cp_wait0();
    __syncthreads();

    for (int kt = 0; kt < nk; kt++) {
        int cur = kt & 1;
        if (kt + 1 < nk) { LOAD_STAGE(cur^1, (kt+1)<<4); cp_commit(); }
        #pragma unroll
        for (int kk = 0; kk < BK; kk++) {
            uint32_t au[MI];
            #pragma unroll
            for (int i = 0; i < MI; i += 4)
                *(uint4*)&au[i] = *(const uint4*)&As[cur][kk][ty*MI + i];
            ulonglong2 b01 = *(const ulonglong2*)&Bs[cur][kk][tx*8];
            ulonglong2 b23 = *(const ulonglong2*)&Bs[cur][kk][tx*8+4];
            ull br2[4] = { b01.x, b01.y, b23.x, b23.y };
            #pragma unroll
            for (int i = 0; i < MI; i++) {
                ull a2;
                DUP_F32X2(a2, au[i]);
                #pragma unroll
                for (int j = 0; j < 4; j++)
                    FMA_F32X2(acc2[i][j], a2, br2[j], acc2[i][j]);
            }
        }
        if (kt + 1 < nk) cp_wait0();
        __syncthreads();
    }
#undef LOAD_STAGE

    #pragma unroll
    for (int i=0;i<MI;i++){
        int row = bm + ty*MI + i;
        if (row < M) {
            float bb = bias ? bias[row] : 0.f;
            float* cp = C + (ll)row*N + bn + tx*8;
            float2 p0 = *(float2*)&acc2[i][0];
            float2 p1 = *(float2*)&acc2[i][1];
            float2 p2 = *(float2*)&acc2[i][2];
            float2 p3 = *(float2*)&acc2[i][3];
            float4 v0, v1;
            v0.x=p0.x+bb; v0.y=p0.y+bb; v0.z=p1.x+bb; v0.w=p1.y+bb;
            v1.x=p2.x+bb; v1.y=p2.y+bb; v1.z=p3.x+bb; v1.w=p3.y+bb;
            *(float4*)cp = v0; *(float4*)(cp+4) = v1;
        }
    }
}

// ---------------- merged fuse: A2 = F48(F1(Y)) in one pass ----------------
__device__ __forceinline__ float loadT(const float* __restrict__ base, int a, int b)
{
    float v = base[(size_t)a*LL + b];
    if (a > 0    && b > 0)    v += base[(size_t)(a-1)*LL + (b-1)];
    if (a < LL-1 && b < LL-1) v += base[(size_t)(a+1)*LL + (b+1)];
    return v;
}
__global__ void fuse2_k(const float* __restrict__ In, float* __restrict__ Out)
{
    int idx = blockIdx.x*blockDim.x + threadIdx.x;
    if (idx >= NB*LL*LL) return;
    int rem = idx % (LL*LL);
    int b   = idx / (LL*LL);
    int r = rem / LL, s = rem % LL;
    const float* base = In + (size_t)b*LL*LL;
    float v = loadT(base, r, s);
    int qr = (r % HF)*HF + r / HF;
    int qs = (s % HF)*HF + s / HF;
    if (qr > 0 && qs > 0) {
        int pr = ((qr-1) % HF)*HF + (qr-1) / HF;
        int ps = ((qs-1) % HF)*HF + (qs-1) / HF;
        v += loadT(base, pr, ps);
    }
    if (qr < LL-1 && qs < LL-1) {
        int nr = ((qr+1) % HF)*HF + (qr+1) / HF;
        int ns = ((qs+1) % HF)*HF + (qs+1) / HF;
        v += loadT(base, nr, ns);
    }
    Out[idx] = v;
}

// ---------------- row softmax, scale 10, writes (hi,lo) pairs ----------------
__global__ void softmax_row_k(const float* __restrict__ In, uint2* __restrict__ Sp)
{
    int row = blockIdx.x;
    int b   = blockIdx.y;
    const float* src = In + ((size_t)b*LL + row)*LL;
    uint2* dst = Sp + ((size_t)b*LL + row)*LL;
    int tid = threadIdx.x;
    __shared__ float red[32];

    float x[9];
    float mx = -3.4e38f;
    #pragma unroll
    for (int q = 0; q < 9; q++) {
        x[q] = src[q*256 + tid];
        mx = fmaxf(mx, x[q]);
    }
    #pragma unroll
    for (int o = 16; o; o >>= 1) mx = fmaxf(mx, __shfl_xor_sync(0xffffffffu, mx, o));
    if ((tid & 31) == 0) red[tid >> 5] = mx;
    __syncthreads();
    if (tid < 32) {
        float m2 = red[tid & 7];
        #pragma unroll
        for (int o = 4; o; o >>= 1) m2 = fmaxf(m2, __shfl_xor_sync(0xffffffffu, m2, o));
        red[tid] = m2;
    }
    __syncthreads();
    float m = red[0] * 10.f;

    float e[9], sum = 0.f;
    #pragma unroll
    for (int q = 0; q < 9; q++) { e[q] = __expf(10.f*x[q] - m); sum += e[q]; }
    #pragma unroll
    for (int o = 16; o; o >>= 1) sum += __shfl_xor_sync(0xffffffffu, sum, o);
    __syncthreads();
    if ((tid & 31) == 0) red[tid >> 5] = sum;
    __syncthreads();
    if (tid < 32) {
        float s2 = red[tid & 7];
        #pragma unroll
        for (int o = 4; o; o >>= 1) s2 += __shfl_xor_sync(0xffffffffu, s2, o);
        red[tid] = s2;
    }
    __syncthreads();
    float inv = 1.f / red[0];

    #pragma unroll
    for (int q = 0; q < 9; q++)
        dst[q*256 + tid] = split2_tf32(e[q] * inv);
}

// ---------------- deconv gather ----------------
__global__ void deconv_k(const float* __restrict__ Tmp, float* __restrict__ yout)
{
    int idx = blockIdx.x*blockDim.x + threadIdx.x;
    if (idx >= NB*NC*NPIX) return;
    int p = idx % NPIX; int t = idx / NPIX;
    int c = t % NC;     int b = t / NC;
    int yy = p / HW, xx = p % HW;
    const float* T = Tmp + (size_t)b*MM2*LL;
    float acc = 0.f;
    #pragma unroll
    for (int di = 0; di < 2; di++) {
        int i = (yy & 1) + 2*di;
        int d = yy + i - 2;
        if (d < 0) continue;
        int h = d >> 1; if (h >= HF) continue;
        #pragma unroll
        for (int dj = 0; dj < 2; dj++) {
            int j = (xx & 1) + 2*dj;
            int e = xx + j - 2;
            if (e < 0) continue;
            int w = e >> 1; if (w >= HF) continue;
            acc += T[(size_t)(c*16 + i*4 + j)*LL + h*HF + w];
        }
    }
    yout[idx] = acc * 0.25f;
}

// ---------------- im2col for 3x3 pad-1 conv on 96x96 (K-major) ----------------
__global__ void im2col_k(const float* __restrict__ In, float* __restrict__ X)
{
    int idx = blockIdx.x*blockDim.x + threadIdx.x;
    if (idx >= NB*KK1*NPIX) return;
    int p = idx % NPIX; int t = idx / NPIX;
    int k = t % KK1;    int b = t / KK1;
    int c = k / 9; int tt = k % 9; int dh = tt/3 - 1, dw = tt%3 - 1;
    int yy = p / HW + dh, xx = p % HW + dw;
    float val = 0.f;
    if ((unsigned)yy < HW && (unsigned)xx < HW)
        val = In[(((size_t)b*NC + c)*HW + yy)*HW + xx];
    X[idx] = val;
}

// ---------------- launch ----------------
extern "C" void kernel_launch(void* const* d_in, const int* in_sizes, int n_in,
                              void* d_out, int out_size)
{
    const float* f   = (const float*)d_in[0];
    const float* bim = (const float*)d_in[1];
    const float* w1  = (const float*)d_in[2];
    const float* b1  = (const float*)d_in[3];
    const float* w2  = (const float*)d_in[4];
    const float* b2  = (const float*)d_in[5];
    float* out = (float*)d_out;

    uint2 *Xp, *Wm, *W2, *Sp;
    float *bufA, *bufB, *Tmp, *yb, *c1, *rn, *w1T, *w2T;
    cudaGetSymbolAddress((void**)&Xp,   g_Xp);
    cudaGetSymbolAddress((void**)&Wm,   g_Wm);
    cudaGetSymbolAddress((void**)&W2,   g_W2);
    cudaGetSymbolAddress((void**)&Sp,   g_Sp);
    cudaGetSymbolAddress((void**)&bufA, g_bufA);
    cudaGetSymbolAddress((void**)&bufB, g_bufB);
    cudaGetSymbolAddress((void**)&Tmp,  g_Tmp);
    cudaGetSymbolAddress((void**)&yb,   g_y);
    cudaGetSymbolAddress((void**)&c1,   g_c1);
    cudaGetSymbolAddress((void**)&rn,   g_rn);
    cudaGetSymbolAddress((void**)&w1T,  g_w1T);
    cudaGetSymbolAddress((void**)&w2T,  g_w2T);

    cudaFuncSetAttribute(mmagemm_k, cudaFuncAttributeMaxDynamicSharedMemorySize, MMASMEM);

    const int T = 256;

    build_Xp_k<<<(NB*LL*KK1 + T-1)/T, T>>>(f, Xp);
    build_W_k <<<(NB*LL*KK1 + T-1)/T, T>>>(bim, Wm);
    rnorm_k   <<<(NB*LL*32 + T-1)/T, T>>>(Wm, rn);

    // GEMM1: bufA[l][n] = rn[n] * Xp[l]·Wm[n]  (= Y0^T)
    mmagemm_k<<<dim3(LL/128, LL/128, NB), T, MMASMEM>>>(Xp, Wm, bufA,
        LL, LL, KK1, (ll)LL*KK1, (ll)LL*KK1, (ll)LL*LL, rn, LL);

    // merged fuse chain (one pass)
    fuse2_k<<<(NB*LL*LL + T-1)/T, T>>>(bufA, bufB);

    // row softmax -> Sp pairs
    softmax_row_k<<<dim3(LL, NB), 256>>>(bufB, Sp);

    // GEMM2: Tmp[m][l] = sum_l' W2[m][l'] * S[l][l']
    build_W2_k<<<(NB*MM2*LL + T-1)/T, T>>>(bim, W2);
    mmagemm_k<<<dim3(LL/128, MM2/128, NB), T, MMASMEM>>>(W2, Sp, Tmp,
        MM2, LL, LL, (ll)MM2*LL, (ll)LL*LL, (ll)MM2*LL, nullptr, 0);

    // gather into y (/4)
    deconv_k<<<(NB*NC*NPIX + T-1)/T, T>>>(Tmp, yb);

    // conv1 / conv2 (scalar FFMA2 path), im2col staged in bufA (free now)
    transpose_w_k<<<(NC*KK1 + T-1)/T, T>>>(w1, w1T);
    im2col_k<<<(NB*KK1*NPIX + T-1)/T, T>>>(yb, bufA);
    sgemm_nt_k<64><<<dim3(NPIX/128, 1, NB), T>>>(w1T, bufA, c1,
        NC, NPIX, KK1, 0, (ll)KK1*NPIX, (ll)NC*NPIX, b1);

    transpose_w_k<<<(NC*KK1 + T-1)/T, T>>>(w2, w2T);
    im2col_k<<<(NB*KK1*NPIX + T-1)/T, T>>>(c1, bufA);
    sgemm_nt_k<64><<<dim3(NPIX/128, 1, NB), T>>>(w2T, bufA, out,
        NC, NPIX, KK1, 0, (ll)KK1*NPIX, (ll)NC*NPIX, b2);
}

// round 10
// speedup vs baseline: 1.5242x; 1.1916x over previous
#include <cuda_runtime.h>
#include <math.h>
#include <stdint.h>

#define NB   4
#define NC   64
#define HW   96
#define HF   48
#define LL   2304    /* 48*48 */
#define KK1  576     /* C*9   */
#define MM2  1024    /* C*16  */
#define NPIX 9216    /* 96*96 */

typedef long long ll;
typedef unsigned long long ull;

// ---------------- scratch (device globals; no allocation) ----------------
__device__ uint2 g_Xp  [(size_t)NB*LL*KK1];   // (hi,lo) tf32 pairs
__device__ uint2 g_Wm  [(size_t)NB*LL*KK1];
__device__ uint2 g_W2  [(size_t)NB*MM2*LL];
__device__ uint2 g_Sp  [(size_t)NB*LL*LL];
__device__ float g_bufA[(size_t)NB*LL*LL];
__device__ float g_bufB[(size_t)NB*LL*LL];
__device__ float g_Tmp [(size_t)NB*MM2*LL];
__device__ float g_y   [(size_t)NB*NC*NPIX];
__device__ float g_c1  [(size_t)NB*NC*NPIX];
__device__ float g_rn  [NB*LL];
__device__ float g_w1T [KK1*NC];
__device__ float g_w2T [KK1*NC];

// split fp32 into two tf32 terms (bit patterns)
__device__ __forceinline__ uint2 split2_tf32(float v)
{
    uint32_t hi, lo;
    asm("cvt.rna.tf32.f32 %0, %1;" : "=r"(hi) : "f"(v));
    float r = v - __uint_as_float(hi);
    asm("cvt.rna.tf32.f32 %0, %1;" : "=r"(lo) : "f"(r));
    return make_uint2(hi, lo);
}

// ---------------- builders ----------------
__global__ void build_Xp_k(const float* __restrict__ f, uint2* __restrict__ X)
{
    int idx = blockIdx.x*blockDim.x + threadIdx.x;
    if (idx >= NB*LL*KK1) return;
    int k = idx % KK1; int t = idx / KK1;
    int p = t % LL;    int b = t / LL;
    int c  = k / 9;  int tt = k % 9; int dh = tt/3, dw = tt%3;
    int fh = p / HF, fw = p % HF;
    int u = fh + dh - 1, v = fw + dw - 1;
    float val = 0.f;
    if ((unsigned)u < HF && (unsigned)v < HF)
        val = f[(((size_t)b*NC + c)*HW + 2*u)*HW + 2*v];
    X[idx] = split2_tf32(val);
}

__global__ void build_W_k(const float* __restrict__ bimg, uint2* __restrict__ W)
{
    int idx = blockIdx.x*blockDim.x + threadIdx.x;
    if (idx >= NB*LL*KK1) return;
    int k = idx % KK1; int t = idx / KK1;
    int n = t % LL;    int b = t / LL;
    int c  = k / 9;  int tt = k % 9; int dh = tt/3, dw = tt%3;
    int g = n*NC + c;
    int c0 = g / LL; int rr = g % LL; int h0 = rr / HF, w0 = rr % HF;
    int u = h0 + dh - 1, v = w0 + dw - 1;
    float val = 0.f;
    if ((unsigned)u < HF && (unsigned)v < HF)
        val = bimg[(((size_t)b*NC + c0)*HW + 2*u)*HW + 2*v];
    W[idx] = split2_tf32(val);
}

__global__ void build_W2_k(const float* __restrict__ bimg, uint2* __restrict__ W2)
{
    int idx = blockIdx.x*blockDim.x + threadIdx.x;
    if (idx >= NB*MM2*LL) return;
    int l = idx % LL; int t = idx / LL;
    int m = t % MM2;  int b = t / MM2;
    int c = m / 16; int tt = m % 16; int i = tt/4, j = tt%4;
    int g = l*NC + c;
    int c0 = g / LL; int rr = g % LL; int h0 = rr / HF, w0 = rr % HF;
    int u = 2*h0 + 2 - i, v = 2*w0 + 2 - j;
    float val = 0.f;
    if ((unsigned)u < HW && (unsigned)v < HW)
        val = bimg[(((size_t)b*NC + c0)*HW + u)*HW + v];
    W2[idx] = split2_tf32(val);
}

// rnorm: warp per (b,n) row of Wm pairs (hi+lo ~ exact)
__global__ void rnorm_k(const uint2* __restrict__ W, float* __restrict__ rn)
{
    int warp = (blockIdx.x*blockDim.x + threadIdx.x) >> 5;
    int lane = threadIdx.x & 31;
    if (warp >= NB*LL) return;
    const uint2* row = W + (size_t)warp*KK1;
    float s = 0.f;
    for (int k = lane; k < KK1; k += 32) {
        uint2 p = row[k];
        float v = __uint_as_float(p.x) + __uint_as_float(p.y);
        s += v*v;
    }
    #pragma unroll
    for (int o = 16; o; o >>= 1) s += __shfl_xor_sync(0xffffffffu, s, o);
    if (lane == 0) rn[warp] = 1.0f / fmaxf(sqrtf(s), 1e-4f);
}

__global__ void transpose_w_k(const float* __restrict__ w, float* __restrict__ wT)
{
    int idx = blockIdx.x*blockDim.x + threadIdx.x;
    if (idx >= NC*KK1) return;
    int k = idx % KK1, c = idx / KK1;
    wT[(size_t)k*NC + c] = w[idx];
}

// ---------------- PTX helpers ----------------
__device__ __forceinline__ void cpa16(void* s, const void* g)
{
    uint32_t sa = (uint32_t)__cvta_generic_to_shared(s);
    asm volatile("cp.async.cg.shared.global [%0], [%1], 16;\n" :: "r"(sa), "l"(g));
}
__device__ __forceinline__ void cpa16p(void* s, const void* g, int bytes)
{
    uint32_t sa = (uint32_t)__cvta_generic_to_shared(s);
    asm volatile("cp.async.cg.shared.global [%0], [%1], 16, %2;\n"
                 :: "r"(sa), "l"(g), "r"(bytes));
}
__device__ __forceinline__ void cp_commit() { asm volatile("cp.async.commit_group;\n"); }
__device__ __forceinline__ void cp_wait0()  { asm volatile("cp.async.wait_group 0;\n"); }

#define FMA_F32X2(d, a, b, c) \
    asm("fma.rn.f32x2 %0, %1, %2, %3;" : "=l"(d) : "l"(a), "l"(b), "l"(c))
#define DUP_F32X2(d, r) \
    asm("mov.b64 %0, {%1, %1};" : "=l"(d) : "r"(r))

__device__ __forceinline__ void mma8(float* c, const uint32_t* a, uint32_t b0, uint32_t b1)
{
    asm("mma.sync.aligned.m16n8k8.row.col.f32.tf32.tf32.f32 "
        "{%0,%1,%2,%3}, {%4,%5,%6,%7}, {%8,%9}, {%0,%1,%2,%3};"
        : "+f"(c[0]), "+f"(c[1]), "+f"(c[2]), "+f"(c[3])
        : "r"(a[0]), "r"(a[1]), "r"(a[2]), "r"(a[3]), "r"(b0), "r"(b1));
}

// ---------------- mma.sync tf32 pair GEMM (NT): C = colscale(n)*(A@B^T) ----------------
// A: M x K pairs row-major, B: N x K pairs row-major. M,N mult of 128; K mult of 16 (pairs).
// TERMS=3: ah*bh + ah*bl + al*bh (fp32-grade). TERMS=2: ah*bh + ah*bl (b-corrected only).
#define PITP 20   /* pair pitch: row stride = 40 words == 8 mod 32 -> conflict-free frags */
#define STPAIRS (128*PITP)          /* pairs per stage per matrix */
#define MMASMEM (2*STPAIRS*8*2)     /* 81920 B: As + Bs, 2 stages */

template<int TERMS>
__global__ __launch_bounds__(256, 2) void mmagemm_k(
    const uint2* __restrict__ Ag, const uint2* __restrict__ Bg, float* __restrict__ Cg,
    int M, int N, int K, ll sA, ll sB, ll sC,
    const float* __restrict__ colscale, int sCS)
{
    extern __shared__ uint2 sm[];
    uint2* As = sm;                    // [2][128][PITP]
    uint2* Bs = sm + 2*STPAIRS;
    int bz = blockIdx.z;
    const uint2* A = Ag + (ll)bz*sA;
    const uint2* B = Bg + (ll)bz*sB;
    float*       C = Cg + (ll)bz*sC;
    int bm = blockIdx.y*128, bn = blockIdx.x*128;
    int tid = threadIdx.x;
    int wid = tid >> 5, lane = tid & 31;
    int wm = wid & 1, wn = wid >> 1;          // warp grid 2(M) x 4(N); warp tile 64x32
    int lm = lane >> 2, lk = lane & 3;

    float acc[4][4][4];
    #pragma unroll
    for (int i=0;i<4;i++)
        #pragma unroll
        for (int j=0;j<4;j++)
            #pragma unroll
            for (int q=0;q<4;q++) acc[i][j][q] = 0.f;

    // precomputed gmem pointers (advance by +16 pairs each kt) and smem targets
    int r0 = tid >> 3, chq = (tid & 7)*2;
    const uint2* gA[4]; const uint2* gB[4];
    uint2* sAp[4]; uint2* sBp[4];
    #pragma unroll
    for (int q = 0; q < 4; q++) {
        int row = r0 + q*32;
        gA[q] = A + (ll)(bm + row)*K + chq;
        gB[q] = B + (ll)(bn + row)*K + chq;
        sAp[q] = As + row*PITP + chq;
        sBp[q] = Bs + row*PITP + chq;
    }

#define LOADSTAGE(st)                                                           \
    {                                                                           \
        int so = (st)*STPAIRS;                                                  \
        _Pragma("unroll")                                                       \
        for (int q = 0; q < 4; q++) {                                           \
            cpa16(sAp[q] + so, gA[q]);                                          \
            cpa16(sBp[q] + so, gB[q]);                                          \
            gA[q] += 16; gB[q] += 16;                                           \
        }                                                                       \
        cp_commit();                                                            \
    }

    // LDS fragment bases (all loop offsets compile-time constants)
    const uint2* aB0 = As + (wm*64 + lm)*PITP + lk;
    const uint2* bB0 = Bs + (wn*32 + lm)*PITP + lk;

    int nk = K >> 4;
    LOADSTAGE(0);
    cp_wait0();
    __syncthreads();

    for (int kt = 0; kt < nk; kt++) {
        int cur = kt & 1;
        if (kt + 1 < nk) LOADSTAGE(cur^1);
        const uint2* aBc = aB0 + cur*STPAIRS;
        const uint2* bBc = bB0 + cur*STPAIRS;
        #pragma unroll
        for (int ks = 0; ks < 2; ks++) {
            uint2 bf0[4], bf1[4];
            #pragma unroll
            for (int nf = 0; nf < 4; nf++) {
                bf0[nf] = bBc[nf*8*PITP + ks*8];
                bf1[nf] = bBc[nf*8*PITP + ks*8 + 4];
            }
            #pragma unroll
            for (int mf = 0; mf < 4; mf++) {
                uint2 a0 = aBc[(mf*16    )*PITP + ks*8];
                uint2 a1 = aBc[(mf*16 + 8)*PITP + ks*8];
                uint2 a2 = aBc[(mf*16    )*PITP + ks*8 + 4];
                uint2 a3 = aBc[(mf*16 + 8)*PITP + ks*8 + 4];
                uint32_t ah[4] = {a0.x, a1.x, a2.x, a3.x};
                // term-major within mf: same acc reused at distance 4
                #pragma unroll
                for (int nf = 0; nf < 4; nf++)
                    mma8(acc[mf][nf], ah, bf0[nf].x, bf1[nf].x);
                #pragma unroll
                for (int nf = 0; nf < 4; nf++)
                    mma8(acc[mf][nf], ah, bf0[nf].y, bf1[nf].y);
                if (TERMS == 3) {
                    uint32_t al[4] = {a0.y, a1.y, a2.y, a3.y};
                    #pragma unroll
                    for (int nf = 0; nf < 4; nf++)
                        mma8(acc[mf][nf], al, bf0[nf].x, bf1[nf].x);
                }
            }
        }
        if (kt + 1 < nk) cp_wait0();
        __syncthreads();
    }
#undef LOADSTAGE

    // epilogue
    #pragma unroll
    for (int nf = 0; nf < 4; nf++) {
        int n0 = bn + wn*32 + nf*8 + 2*lk;
        float s0 = 1.f, s1 = 1.f;
        if (colscale) {
            s0 = __ldg(&colscale[bz*sCS + n0]);
            s1 = __ldg(&colscale[bz*sCS + n0 + 1]);
        }
        #pragma unroll
        for (int mf = 0; mf < 4; mf++) {
            int m0 = bm + wm*64 + mf*16 + lm;
            float2 v0 = make_float2(acc[mf][nf][0]*s0, acc[mf][nf][1]*s1);
            float2 v1 = make_float2(acc[mf][nf][2]*s0, acc[mf][nf][3]*s1);
            *(float2*)&C[(ll)m0*N + n0]     = v0;
            *(float2*)&C[(ll)(m0+8)*N + n0] = v1;
        }
    }
}

// ---------------- scalar NT SGEMM (FFMA2) for the conv layers ----------------
template<int BM>
__global__ __launch_bounds__(256, 2) void sgemm_nt_k(
    const float* __restrict__ Ag, const float* __restrict__ Bg, float* __restrict__ Cg,
    int M, int N, int K, ll sA, ll sB, ll sC,
    const float* __restrict__ bias)
{
    constexpr int BN = 128, BK = 16;
    constexpr int MI = BM / 16;
    int bz = blockIdx.z;
    const float* A = Ag + (ll)bz*sA;
    const float* B = Bg + (ll)bz*sB;
    float*       C = Cg + (ll)bz*sC;
    int bm = blockIdx.y*BM, bn = blockIdx.x*BN;
    int tid = threadIdx.x;
    int tx = tid & 15, ty = tid >> 4;

    __shared__ float As[2][BK][BM+4];
    __shared__ float Bs[2][BK][BN+4];

    ull acc2[MI][4];
    #pragma unroll
    for (int i=0;i<MI;i++)
        #pragma unroll
        for (int j=0;j<4;j++) acc2[i][j] = 0ull;

    constexpr int A4 = BK*BM/4;
    constexpr int B4 = BK*BN/4;

#define LOAD_STAGE(st, k0)                                                      \
    {                                                                           \
        _Pragma("unroll")                                                       \
        for (int q = 0; q < A4/256; q++) {                                      \
            int idx = q*256 + tid;                                              \
            int k = idx / (BM/4), c4 = (idx % (BM/4))*4;                        \
            int mb = bm + c4;                                                   \
            const float* ga = A + (ll)((k0)+k)*M + (mb < M ? mb : 0);           \
            cpa16p(&As[st][k][c4], ga, (mb < M) ? 16 : 0);                      \
        }                                                                       \
        _Pragma("unroll")                                                       \
        for (int q = 0; q < B4/256; q++) {                                      \
            int idx = q*256 + tid;                                              \
            int k = idx / (BN/4), c4 = (idx % (BN/4))*4;                        \
            const float* gb = B + (ll)((k0)+k)*N + bn + c4;                     \
            cpa16p(&Bs[st][k][c4], gb, 16);                                     \
        }                                                                       \
    }

    int nk = K >> 4;
    LOAD_STAGE(0, 0);
    cp_commit();
    cp_wait0();
    __syncthreads();

    for (int kt = 0; kt < nk; kt++) {
        int cur = kt & 1;
        if (kt + 1 < nk) { LOAD_STAGE(cur^1, (kt+1)<<4); cp_commit(); }
        #pragma unroll
        for (int kk = 0; kk < BK; kk++) {
            uint32_t au[MI];
            #pragma unroll
            for (int i = 0; i < MI; i += 4)
                *(uint4*)&au[i] = *(const uint4*)&As[cur][kk][ty*MI + i];
            ulonglong2 b01 = *(const ulonglong2*)&Bs[cur][kk][tx*8];
            ulonglong2 b23 = *(const ulonglong2*)&Bs[cur][kk][tx*8+4];
            ull br2[4] = { b01.x, b01.y, b23.x, b23.y };
            #pragma unroll
            for (int i = 0; i < MI; i++) {
                ull a2;
                DUP_F32X2(a2, au[i]);
                #pragma unroll
                for (int j = 0; j < 4; j++)
                    FMA_F32X2(acc2[i][j], a2, br2[j], acc2[i][j]);
            }
        }
        if (kt + 1 < nk) cp_wait0();
        __syncthreads();
    }
#undef LOAD_STAGE

    #pragma unroll
    for (int i=0;i<MI;i++){
        int row = bm + ty*MI + i;
        if (row < M) {
            float bb = bias ? bias[row] : 0.f;
            float* cp = C + (ll)row*N + bn + tx*8;
            float2 p0 = *(float2*)&acc2[i][0];
            float2 p1 = *(float2*)&acc2[i][1];
            float2 p2 = *(float2*)&acc2[i][2];
            float2 p3 = *(float2*)&acc2[i][3];
            float4 v0, v1;
            v0.x=p0.x+bb; v0.y=p0.y+bb; v0.z=p1.x+bb; v0.w=p1.y+bb;
            v1.x=p2.x+bb; v1.y=p2.y+bb; v1.z=p3.x+bb; v1.w=p3.y+bb;
            *(float4*)cp = v0; *(float4*)(cp+4) = v1;
        }
    }
}

// ---------------- merged fuse: A2 = F48(F1(Y)) in one pass ----------------
__device__ __forceinline__ float loadT(const float* __restrict__ base, int a, int b)
{
    float v = base[(size_t)a*LL + b];
    if (a > 0    && b > 0)    v += base[(size_t)(a-1)*LL + (b-1)];
    if (a < LL-1 && b < LL-1) v += base[(size_t)(a+1)*LL + (b+1)];
    return v;
}
__global__ void fuse2_k(const float* __restrict__ In, float* __restrict__ Out)
{
    int idx = blockIdx.x*blockDim.x + threadIdx.x;
    if (idx >= NB*LL*LL) return;
    int rem = idx % (LL*LL);
    int b   = idx / (LL*LL);
    int r = rem / LL, s = rem % LL;
    const float* base = In + (size_t)b*LL*LL;
    float v = loadT(base, r, s);
    int qr = (r % HF)*HF + r / HF;
    int qs = (s % HF)*HF + s / HF;
    if (qr > 0 && qs > 0) {
        int pr = ((qr-1) % HF)*HF + (qr-1) / HF;
        int ps = ((qs-1) % HF)*HF + (qs-1) / HF;
        v += loadT(base, pr, ps);
    }
    if (qr < LL-1 && qs < LL-1) {
        int nr = ((qr+1) % HF)*HF + (qr+1) / HF;
        int ns = ((qs+1) % HF)*HF + (qs+1) / HF;
        v += loadT(base, nr, ns);
    }
    Out[idx] = v;
}

// ---------------- row softmax, scale 10, writes (hi,lo) pairs ----------------
__global__ void softmax_row_k(const float* __restrict__ In, uint2* __restrict__ Sp)
{
    int row = blockIdx.x;
    int b   = blockIdx.y;
    const float* src = In + ((size_t)b*LL + row)*LL;
    uint2* dst = Sp + ((size_t)b*LL + row)*LL;
    int tid = threadIdx.x;
    __shared__ float red[32];

    float x[9];
    float mx = -3.4e38f;
    #pragma unroll
    for (int q = 0; q < 9; q++) {
        x[q] = src[q*256 + tid];
        mx = fmaxf(mx, x[q]);
    }
    #pragma unroll
    for (int o = 16; o; o >>= 1) mx = fmaxf(mx, __shfl_xor_sync(0xffffffffu, mx, o));
    if ((tid & 31) == 0) red[tid >> 5] = mx;
    __syncthreads();
    if (tid < 32) {
        float m2 = red[tid & 7];
        #pragma unroll
        for (int o = 4; o; o >>= 1) m2 = fmaxf(m2, __shfl_xor_sync(0xffffffffu, m2, o));
        red[tid] = m2;
    }
    __syncthreads();
    float m = red[0] * 10.f;

    float e[9], sum = 0.f;
    #pragma unroll
    for (int q = 0; q < 9; q++) { e[q] = __expf(10.f*x[q] - m); sum += e[q]; }
    #pragma unroll
    for (int o = 16; o; o >>= 1) sum += __shfl_xor_sync(0xffffffffu, sum, o);
    __syncthreads();
    if ((tid & 31) == 0) red[tid >> 5] = sum;
    __syncthreads();
    if (tid < 32) {
        float s2 = red[tid & 7];
        #pragma unroll
        for (int o = 4; o; o >>= 1) s2 += __shfl_xor_sync(0xffffffffu, s2, o);
        red[tid] = s2;
    }
    __syncthreads();
    float inv = 1.f / red[0];

    #pragma unroll
    for (int q = 0; q < 9; q++)
        dst[q*256 + tid] = split2_tf32(e[q] * inv);
}

// ---------------- deconv gather ----------------
__global__ void deconv_k(const float* __restrict__ Tmp, float* __restrict__ yout)
{
    int idx = blockIdx.x*blockDim.x + threadIdx.x;
    if (idx >= NB*NC*NPIX) return;
    int p = idx % NPIX; int t = idx / NPIX;
    int c = t % NC;     int b = t / NC;
    int yy = p / HW, xx = p % HW;
    const float* T = Tmp + (size_t)b*MM2*LL;
    float acc = 0.f;
    #pragma unroll
    for (int di = 0; di < 2; di++) {
        int i = (yy & 1) + 2*di;
        int d = yy + i - 2;
        if (d < 0) continue;
        int h = d >> 1; if (h >= HF) continue;
        #pragma unroll
        for (int dj = 0; dj < 2; dj++) {
            int j = (xx & 1) + 2*dj;
            int e = xx + j - 2;
            if (e < 0) continue;
            int w = e >> 1; if (w >= HF) continue;
            acc += T[(size_t)(c*16 + i*4 + j)*LL + h*HF + w];
        }
    }
    yout[idx] = acc * 0.25f;
}

// ---------------- im2col for 3x3 pad-1 conv on 96x96 (K-major) ----------------
__global__ void im2col_k(const float* __restrict__ In, float* __restrict__ X)
{
    int idx = blockIdx.x*blockDim.x + threadIdx.x;
    if (idx >= NB*KK1*NPIX) return;
    int p = idx % NPIX; int t = idx / NPIX;
    int k = t % KK1;    int b = t / KK1;
    int c = k / 9; int tt = k % 9; int dh = tt/3 - 1, dw = tt%3 - 1;
    int yy = p / HW + dh, xx = p % HW + dw;
    float val = 0.f;
    if ((unsigned)yy < HW && (unsigned)xx < HW)
        val = In[(((size_t)b*NC + c)*HW + yy)*HW + xx];
    X[idx] = val;
}

// ---------------- launch ----------------
extern "C" void kernel_launch(void* const* d_in, const int* in_sizes, int n_in,
                              void* d_out, int out_size)
{
    const float* f   = (const float*)d_in[0];
    const float* bim = (const float*)d_in[1];
    const float* w1  = (const float*)d_in[2];
    const float* b1  = (const float*)d_in[3];
    const float* w2  = (const float*)d_in[4];
    const float* b2  = (const float*)d_in[5];
    float* out = (float*)d_out;

    uint2 *Xp, *Wm, *W2, *Sp;
    float *bufA, *bufB, *Tmp, *yb, *c1, *rn, *w1T, *w2T;
    cudaGetSymbolAddress((void**)&Xp,   g_Xp);
    cudaGetSymbolAddress((void**)&Wm,   g_Wm);
    cudaGetSymbolAddress((void**)&W2,   g_W2);
    cudaGetSymbolAddress((void**)&Sp,   g_Sp);
    cudaGetSymbolAddress((void**)&bufA, g_bufA);
    cudaGetSymbolAddress((void**)&bufB, g_bufB);
    cudaGetSymbolAddress((void**)&Tmp,  g_Tmp);
    cudaGetSymbolAddress((void**)&yb,   g_y);
    cudaGetSymbolAddress((void**)&c1,   g_c1);
    cudaGetSymbolAddress((void**)&rn,   g_rn);
    cudaGetSymbolAddress((void**)&w1T,  g_w1T);
    cudaGetSymbolAddress((void**)&w2T,  g_w2T);

    cudaFuncSetAttribute(mmagemm_k<3>, cudaFuncAttributeMaxDynamicSharedMemorySize, MMASMEM);
    cudaFuncSetAttribute(mmagemm_k<2>, cudaFuncAttributeMaxDynamicSharedMemorySize, MMASMEM);

    const int T = 256;

    build_Xp_k<<<(NB*LL*KK1 + T-1)/T, T>>>(f, Xp);
    build_W_k <<<(NB*LL*KK1 + T-1)/T, T>>>(bim, Wm);
    rnorm_k   <<<(NB*LL*32 + T-1)/T, T>>>(Wm, rn);

    // GEMM1 (3-term, feeds softmax x10): bufA[l][n] = rn[n] * Xp[l]·Wm[n]  (= Y0^T)
    mmagemm_k<3><<<dim3(LL/128, LL/128, NB), T, MMASMEM>>>(Xp, Wm, bufA,
        LL, LL, KK1, (ll)LL*KK1, (ll)LL*KK1, (ll)LL*LL, rn, LL);

    // merged fuse chain (one pass)
    fuse2_k<<<(NB*LL*LL + T-1)/T, T>>>(bufA, bufB);

    // row softmax -> Sp pairs
    softmax_row_k<<<dim3(LL, NB), 256>>>(bufB, Sp);

    // GEMM2 (2-term, linear path): Tmp[m][l] = sum_l' W2[m][l'] * S[l][l']
    build_W2_k<<<(NB*MM2*LL + T-1)/T, T>>>(bim, W2);
    mmagemm_k<2><<<dim3(LL/128, MM2/128, NB), T, MMASMEM>>>(W2, Sp, Tmp,
        MM2, LL, LL, (ll)MM2*LL, (ll)LL*LL, (ll)MM2*LL, nullptr, 0);

    // gather into y (/4)
    deconv_k<<<(NB*NC*NPIX + T-1)/T, T>>>(Tmp, yb);

    // conv1 / conv2 (scalar FFMA2 path), im2col staged in bufA (free now)
    transpose_w_k<<<(NC*KK1 + T-1)/T, T>>>(w1, w1T);
    im2col_k<<<(NB*KK1*NPIX + T-1)/T, T>>>(yb, bufA);
    sgemm_nt_k<64><<<dim3(NPIX/128, 1, NB), T>>>(w1T, bufA, c1,
        NC, NPIX, KK1, 0, (ll)KK1*NPIX, (ll)NC*NPIX, b1);

    transpose_w_k<<<(NC*KK1 + T-1)/T, T>>>(w2, w2T);
    im2col_k<<<(NB*KK1*NPIX + T-1)/T, T>>>(c1, bufA);
    sgemm_nt_k<64><<<dim3(NPIX/128, 1, NB), T>>>(w2T, bufA, out,
        NC, NPIX, KK1, 0, (ll)KK1*NPIX, (ll)NC*NPIX, b2);
}

// round 11
// speedup vs baseline: 1.5329x; 1.0057x over previous
#include <cuda_runtime.h>
#include <math.h>
#include <stdint.h>

#define NB   4
#define NC   64
#define HW   96
#define HF   48
#define LL   2304    /* 48*48 */
#define KK1  576     /* C*9   */
#define MM2  1024    /* C*16  */
#define NPIX 9216    /* 96*96 */

typedef long long ll;
typedef unsigned long long ull;

// ---------------- scratch (device globals; no allocation) ----------------
__device__ uint2    g_Xp [(size_t)NB*LL*KK1];   // (hi,lo) tf32 pairs
__device__ uint2    g_Wm [(size_t)NB*LL*KK1];
__device__ uint32_t g_W2s[(size_t)NB*MM2*LL];   // tf32 hi only (2-term GEMM2 A)
__device__ uint2    g_Sp [(size_t)NB*LL*LL];
__device__ float    g_bufA[(size_t)NB*LL*LL];
__device__ float    g_Tmp [(size_t)NB*MM2*LL];
__device__ float    g_y   [(size_t)NB*NC*NPIX];
__device__ float    g_c1  [(size_t)NB*NC*NPIX];
__device__ float    g_rn  [NB*LL];
__device__ float    g_w1T [KK1*NC];
__device__ float    g_w2T [KK1*NC];
__device__ float    g_im  [(size_t)NB*KK1*NPIX]; // im2col staging

// split fp32 into two tf32 terms (bit patterns)
__device__ __forceinline__ uint2 split2_tf32(float v)
{
    uint32_t hi, lo;
    asm("cvt.rna.tf32.f32 %0, %1;" : "=r"(hi) : "f"(v));
    float r = v - __uint_as_float(hi);
    asm("cvt.rna.tf32.f32 %0, %1;" : "=r"(lo) : "f"(r));
    return make_uint2(hi, lo);
}

// ---------------- builders ----------------
__global__ void build_Xp_k(const float* __restrict__ f, uint2* __restrict__ X)
{
    int idx = blockIdx.x*blockDim.x + threadIdx.x;
    if (idx >= NB*LL*KK1) return;
    int k = idx % KK1; int t = idx / KK1;
    int p = t % LL;    int b = t / LL;
    int c  = k / 9;  int tt = k % 9; int dh = tt/3, dw = tt%3;
    int fh = p / HF, fw = p % HF;
    int u = fh + dh - 1, v = fw + dw - 1;
    float val = 0.f;
    if ((unsigned)u < HF && (unsigned)v < HF)
        val = f[(((size_t)b*NC + c)*HW + 2*u)*HW + 2*v];
    X[idx] = split2_tf32(val);
}

__global__ void build_W_k(const float* __restrict__ bimg, uint2* __restrict__ W)
{
    int idx = blockIdx.x*blockDim.x + threadIdx.x;
    if (idx >= NB*LL*KK1) return;
    int k = idx % KK1; int t = idx / KK1;
    int n = t % LL;    int b = t / LL;
    int c  = k / 9;  int tt = k % 9; int dh = tt/3, dw = tt%3;
    int g = n*NC + c;
    int c0 = g / LL; int rr = g % LL; int h0 = rr / HF, w0 = rr % HF;
    int u = h0 + dh - 1, v = w0 + dw - 1;
    float val = 0.f;
    if ((unsigned)u < HF && (unsigned)v < HF)
        val = bimg[(((size_t)b*NC + c0)*HW + 2*u)*HW + 2*v];
    W[idx] = split2_tf32(val);
}

// W2 stored as tf32-hi only (2-term GEMM2 never reads A-lo)
__global__ void build_W2s_k(const float* __restrict__ bimg, uint32_t* __restrict__ W2)
{
    int idx = blockIdx.x*blockDim.x + threadIdx.x;
    if (idx >= NB*MM2*LL) return;
    int l = idx % LL; int t = idx / LL;
    int m = t % MM2;  int b = t / MM2;
    int c = m / 16; int tt = m % 16; int i = tt/4, j = tt%4;
    int g = l*NC + c;
    int c0 = g / LL; int rr = g % LL; int h0 = rr / HF, w0 = rr % HF;
    int u = 2*h0 + 2 - i, v = 2*w0 + 2 - j;
    float val = 0.f;
    if ((unsigned)u < HW && (unsigned)v < HW)
        val = bimg[(((size_t)b*NC + c0)*HW + u)*HW + v];
    uint32_t hi;
    asm("cvt.rna.tf32.f32 %0, %1;" : "=r"(hi) : "f"(val));
    W2[idx] = hi;
}

// rnorm: warp per (b,n) row of Wm pairs (hi+lo ~ exact)
__global__ void rnorm_k(const uint2* __restrict__ W, float* __restrict__ rn)
{
    int warp = (blockIdx.x*blockDim.x + threadIdx.x) >> 5;
    int lane = threadIdx.x & 31;
    if (warp >= NB*LL) return;
    const uint2* row = W + (size_t)warp*KK1;
    float s = 0.f;
    for (int k = lane; k < KK1; k += 32) {
        uint2 p = row[k];
        float v = __uint_as_float(p.x) + __uint_as_float(p.y);
        s += v*v;
    }
    #pragma unroll
    for (int o = 16; o; o >>= 1) s += __shfl_xor_sync(0xffffffffu, s, o);
    if (lane == 0) rn[warp] = 1.0f / fmaxf(sqrtf(s), 1e-4f);
}

__global__ void transpose_w_k(const float* __restrict__ w, float* __restrict__ wT)
{
    int idx = blockIdx.x*blockDim.x + threadIdx.x;
    if (idx >= NC*KK1) return;
    int k = idx % KK1, c = idx / KK1;
    wT[(size_t)k*NC + c] = w[idx];
}

// ---------------- PTX helpers ----------------
__device__ __forceinline__ void cpa16(void* s, const void* g)
{
    uint32_t sa = (uint32_t)__cvta_generic_to_shared(s);
    asm volatile("cp.async.cg.shared.global [%0], [%1], 16;\n" :: "r"(sa), "l"(g));
}
__device__ __forceinline__ void cpa16p(void* s, const void* g, int bytes)
{
    uint32_t sa = (uint32_t)__cvta_generic_to_shared(s);
    asm volatile("cp.async.cg.shared.global [%0], [%1], 16, %2;\n"
                 :: "r"(sa), "l"(g), "r"(bytes));
}
__device__ __forceinline__ void cp_commit() { asm volatile("cp.async.commit_group;\n"); }
__device__ __forceinline__ void cp_wait0()  { asm volatile("cp.async.wait_group 0;\n"); }

#define FMA_F32X2(d, a, b, c) \
    asm("fma.rn.f32x2 %0, %1, %2, %3;" : "=l"(d) : "l"(a), "l"(b), "l"(c))
#define DUP_F32X2(d, r) \
    asm("mov.b64 %0, {%1, %1};" : "=l"(d) : "r"(r))

__device__ __forceinline__ void mma8(float* c, const uint32_t* a, uint32_t b0, uint32_t b1)
{
    asm("mma.sync.aligned.m16n8k8.row.col.f32.tf32.tf32.f32 "
        "{%0,%1,%2,%3}, {%4,%5,%6,%7}, {%8,%9}, {%0,%1,%2,%3};"
        : "+f"(c[0]), "+f"(c[1]), "+f"(c[2]), "+f"(c[3])
        : "r"(a[0]), "r"(a[1]), "r"(a[2]), "r"(a[3]), "r"(b0), "r"(b1));
}

// ---------------- GEMM1: 3-term pair GEMM (NT), C = colscale(n)*(A@B^T) ----------------
#define PITP 20   /* pair pitch */
#define STPAIRS (128*PITP)
#define MMASMEM (2*STPAIRS*8*2)   /* 81920 B */

__global__ __launch_bounds__(256, 2) void mmagemm_k(
    const uint2* __restrict__ Ag, const uint2* __restrict__ Bg, float* __restrict__ Cg,
    int M, int N, int K, ll sA, ll sB, ll sC,
    const float* __restrict__ colscale, int sCS)
{
    extern __shared__ uint2 sm[];
    uint2* As = sm;
    uint2* Bs = sm + 2*STPAIRS;
    int bz = blockIdx.z;
    const uint2* A = Ag + (ll)bz*sA;
    const uint2* B = Bg + (ll)bz*sB;
    float*       C = Cg + (ll)bz*sC;
    int bm = blockIdx.y*128, bn = blockIdx.x*128;
    int tid = threadIdx.x;
    int wid = tid >> 5, lane = tid & 31;
    int wm = wid & 1, wn = wid >> 1;
    int lm = lane >> 2, lk = lane & 3;

    float acc[4][4][4];
    #pragma unroll
    for (int i=0;i<4;i++)
        #pragma unroll
        for (int j=0;j<4;j++)
            #pragma unroll
            for (int q=0;q<4;q++) acc[i][j][q] = 0.f;

    int r0 = tid >> 3, chq = (tid & 7)*2;
    const uint2* gA[4]; const uint2* gB[4];
    uint2* sAp[4]; uint2* sBp[4];
    #pragma unroll
    for (int q = 0; q < 4; q++) {
        int row = r0 + q*32;
        gA[q] = A + (ll)(bm + row)*K + chq;
        gB[q] = B + (ll)(bn + row)*K + chq;
        sAp[q] = As + row*PITP + chq;
        sBp[q] = Bs + row*PITP + chq;
    }

#define LOADSTAGE(st)                                                           \
    {                                                                           \
        int so = (st)*STPAIRS;                                                  \
        _Pragma("unroll")                                                       \
        for (int q = 0; q < 4; q++) {                                           \
            cpa16(sAp[q] + so, gA[q]);                                          \
            cpa16(sBp[q] + so, gB[q]);                                          \
            gA[q] += 16; gB[q] += 16;                                           \
        }                                                                       \
        cp_commit();                                                            \
    }

    const uint2* aB0 = As + (wm*64 + lm)*PITP + lk;
    const uint2* bB0 = Bs + (wn*32 + lm)*PITP + lk;

    int nk = K >> 4;
    LOADSTAGE(0);
    cp_wait0();
    __syncthreads();

    for (int kt = 0; kt < nk; kt++) {
        int cur = kt & 1;
        if (kt + 1 < nk) LOADSTAGE(cur^1);
        const uint2* aBc = aB0 + cur*STPAIRS;
        const uint2* bBc = bB0 + cur*STPAIRS;
        #pragma unroll
        for (int ks = 0; ks < 2; ks++) {
            uint2 bf0[4], bf1[4];
            #pragma unroll
            for (int nf = 0; nf < 4; nf++) {
                bf0[nf] = bBc[nf*8*PITP + ks*8];
                bf1[nf] = bBc[nf*8*PITP + ks*8 + 4];
            }
            #pragma unroll
            for (int mf = 0; mf < 4; mf++) {
                uint2 a0 = aBc[(mf*16    )*PITP + ks*8];
                uint2 a1 = aBc[(mf*16 + 8)*PITP + ks*8];
                uint2 a2 = aBc[(mf*16    )*PITP + ks*8 + 4];
                uint2 a3 = aBc[(mf*16 + 8)*PITP + ks*8 + 4];
                uint32_t ah[4] = {a0.x, a1.x, a2.x, a3.x};
                #pragma unroll
                for (int nf = 0; nf < 4; nf++)
                    mma8(acc[mf][nf], ah, bf0[nf].x, bf1[nf].x);
                #pragma unroll
                for (int nf = 0; nf < 4; nf++)
                    mma8(acc[mf][nf], ah, bf0[nf].y, bf1[nf].y);
                {
                    uint32_t al[4] = {a0.y, a1.y, a2.y, a3.y};
                    #pragma unroll
                    for (int nf = 0; nf < 4; nf++)
                        mma8(acc[mf][nf], al, bf0[nf].x, bf1[nf].x);
                }
            }
        }
        if (kt + 1 < nk) cp_wait0();
        __syncthreads();
    }
#undef LOADSTAGE

    #pragma unroll
    for (int nf = 0; nf < 4; nf++) {
        int n0 = bn + wn*32 + nf*8 + 2*lk;
        float s0 = 1.f, s1 = 1.f;
        if (colscale) {
            s0 = __ldg(&colscale[bz*sCS + n0]);
            s1 = __ldg(&colscale[bz*sCS + n0 + 1]);
        }
        #pragma unroll
        for (int mf = 0; mf < 4; mf++) {
            int m0 = bm + wm*64 + mf*16 + lm;
            float2 v0 = make_float2(acc[mf][nf][0]*s0, acc[mf][nf][1]*s1);
            float2 v1 = make_float2(acc[mf][nf][2]*s0, acc[mf][nf][3]*s1);
            *(float2*)&C[(ll)m0*N + n0]     = v0;
            *(float2*)&C[(ll)(m0+8)*N + n0] = v1;
        }
    }
}

// ---------------- GEMM2: 2-term, A single tf32, B pairs ----------------
#define PITS 20                      /* word pitch for A singles */
#define STW_A (128*PITS)             /* words per A stage */
#define MMASMEM2 (2*STW_A*4 + 2*STPAIRS*8)   /* 20480 + 40960 = 61440 B */

__global__ __launch_bounds__(256, 2) void mmagemm2s_k(
    const uint32_t* __restrict__ Ag, const uint2* __restrict__ Bg, float* __restrict__ Cg,
    int M, int N, int K, ll sA, ll sB, ll sC)
{
    extern __shared__ char smraw[];
    uint32_t* As = (uint32_t*)smraw;                 // [2][128][PITS]
    uint2*    Bs = (uint2*)(smraw + 2*STW_A*4);      // [2][128][PITP]
    int bz = blockIdx.z;
    const uint32_t* A = Ag + (ll)bz*sA;
    const uint2*    B = Bg + (ll)bz*sB;
    float*          C = Cg + (ll)bz*sC;
    int bm = blockIdx.y*128, bn = blockIdx.x*128;
    int tid = threadIdx.x;
    int wid = tid >> 5, lane = tid & 31;
    int wm = wid & 1, wn = wid >> 1;
    int lm = lane >> 2, lk = lane & 3;

    float acc[4][4][4];
    #pragma unroll
    for (int i=0;i<4;i++)
        #pragma unroll
        for (int j=0;j<4;j++)
            #pragma unroll
            for (int q=0;q<4;q++) acc[i][j][q] = 0.f;

    // A: 128 rows x 16 words/stage = 512 x 16B chunks -> 2 per thread
    int r0a = tid >> 2, cha = (tid & 3)*4;
    const uint32_t* gA[2]; uint32_t* sApt[2];
    #pragma unroll
    for (int q = 0; q < 2; q++) {
        int row = r0a + q*64;
        gA[q] = A + (ll)(bm + row)*K + cha;
        sApt[q] = As + row*PITS + cha;
    }
    // B: 128 rows x 16 pairs/stage = 1024 x 16B chunks -> 4 per thread
    int r0b = tid >> 3, chb = (tid & 7)*2;
    const uint2* gB[4]; uint2* sBpt[4];
    #pragma unroll
    for (int q = 0; q < 4; q++) {
        int row = r0b + q*32;
        gB[q] = B + (ll)(bn + row)*K + chb;
        sBpt[q] = Bs + row*PITP + chb;
    }

#define LOADSTAGE2(st)                                                          \
    {                                                                           \
        int soA = (st)*STW_A;                                                   \
        int soB = (st)*STPAIRS;                                                 \
        _Pragma("unroll")                                                       \
        for (int q = 0; q < 2; q++) { cpa16(sApt[q] + soA, gA[q]); gA[q] += 16; } \
        _Pragma("unroll")                                                       \
        for (int q = 0; q < 4; q++) { cpa16(sBpt[q] + soB, gB[q]); gB[q] += 16; } \
        cp_commit();                                                            \
    }

    const uint32_t* aB0 = As + (wm*64 + lm)*PITS + lk;
    const uint2*    bB0 = Bs + (wn*32 + lm)*PITP + lk;

    int nk = K >> 4;
    LOADSTAGE2(0);
    cp_wait0();
    __syncthreads();

    for (int kt = 0; kt < nk; kt++) {
        int cur = kt & 1;
        if (kt + 1 < nk) LOADSTAGE2(cur^1);
        const uint32_t* aBc = aB0 + cur*STW_A;
        const uint2*    bBc = bB0 + cur*STPAIRS;
        #pragma unroll
        for (int ks = 0; ks < 2; ks++) {
            uint2 bf0[4], bf1[4];
            #pragma unroll
            for (int nf = 0; nf < 4; nf++) {
                bf0[nf] = bBc[nf*8*PITP + ks*8];
                bf1[nf] = bBc[nf*8*PITP + ks*8 + 4];
            }
            #pragma unroll
            for (int mf = 0; mf < 4; mf++) {
                uint32_t ah[4];
                ah[0] = aBc[(mf*16    )*PITS + ks*8];
                ah[1] = aBc[(mf*16 + 8)*PITS + ks*8];
                ah[2] = aBc[(mf*16    )*PITS + ks*8 + 4];
                ah[3] = aBc[(mf*16 + 8)*PITS + ks*8 + 4];
                #pragma unroll
                for (int nf = 0; nf < 4; nf++)
                    mma8(acc[mf][nf], ah, bf0[nf].x, bf1[nf].x);
                #pragma unroll
                for (int nf = 0; nf < 4; nf++)
                    mma8(acc[mf][nf], ah, bf0[nf].y, bf1[nf].y);
            }
        }
        if (kt + 1 < nk) cp_wait0();
        __syncthreads();
    }
#undef LOADSTAGE2

    #pragma unroll
    for (int nf = 0; nf < 4; nf++) {
        int n0 = bn + wn*32 + nf*8 + 2*lk;
        #pragma unroll
        for (int mf = 0; mf < 4; mf++) {
            int m0 = bm + wm*64 + mf*16 + lm;
            float2 v0 = make_float2(acc[mf][nf][0], acc[mf][nf][1]);
            float2 v1 = make_float2(acc[mf][nf][2], acc[mf][nf][3]);
            *(float2*)&C[(ll)m0*N + n0]     = v0;
            *(float2*)&C[(ll)(m0+8)*N + n0] = v1;
        }
    }
}

// ---------------- scalar NT SGEMM (FFMA2) for the conv layers ----------------
template<int BM>
__global__ __launch_bounds__(256, 2) void sgemm_nt_k(
    const float* __restrict__ Ag, const float* __restrict__ Bg, float* __restrict__ Cg,
    int M, int N, int K, ll sA, ll sB, ll sC,
    const float* __restrict__ bias)
{
    constexpr int BN = 128, BK = 16;
    constexpr int MI = BM / 16;
    int bz = blockIdx.z;
    const float* A = Ag + (ll)bz*sA;
    const float* B = Bg + (ll)bz*sB;
    float*       C = Cg + (ll)bz*sC;
    int bm = blockIdx.y*BM, bn = blockIdx.x*BN;
    int tid = threadIdx.x;
    int tx = tid & 15, ty = tid >> 4;

    __shared__ float As[2][BK][BM+4];
    __shared__ float Bs[2][BK][BN+4];

    ull acc2[MI][4];
    #pragma unroll
    for (int i=0;i<MI;i++)
        #pragma unroll
        for (int j=0;j<4;j++) acc2[i][j] = 0ull;

    constexpr int A4 = BK*BM/4;
    constexpr int B4 = BK*BN/4;

#define LOAD_STAGE(st, k0)                                                      \
    {                                                                           \
        _Pragma("unroll")                                                       \
        for (int q = 0; q < A4/256; q++) {                                      \
            int idx = q*256 + tid;                                              \
            int k = idx / (BM/4), c4 = (idx % (BM/4))*4;                        \
            int mb = bm + c4;                                                   \
            const float* ga = A + (ll)((k0)+k)*M + (mb < M ? mb : 0);           \
            cpa16p(&As[st][k][c4], ga, (mb < M) ? 16 : 0);                      \
        }                                                                       \
        _Pragma("unroll")                                                       \
        for (int q = 0; q < B4/256; q++) {                                      \
            int idx = q*256 + tid;                                              \
            int k = idx / (BN/4), c4 = (idx % (BN/4))*4;                        \
            const float* gb = B + (ll)((k0)+k)*N + bn + c4;                     \
            cpa16p(&Bs[st][k][c4], gb, 16);                                     \
        }                                                                       \
    }

    int nk = K >> 4;
    LOAD_STAGE(0, 0);
    cp_commit();
    cp_wait0();
    __syncthreads();

    for (int kt = 0; kt < nk; kt++) {
        int cur = kt & 1;
        if (kt + 1 < nk) { LOAD_STAGE(cur^1, (kt+1)<<4); cp_commit(); }
        #pragma unroll
        for (int kk = 0; kk < BK; kk++) {
            uint32_t au[MI];
            #pragma unroll
            for (int i = 0; i < MI; i += 4)
                *(uint4*)&au[i] = *(const uint4*)&As[cur][kk][ty*MI + i];
            ulonglong2 b01 = *(const ulonglong2*)&Bs[cur][kk][tx*8];
            ulonglong2 b23 = *(const ulonglong2*)&Bs[cur][kk][tx*8+4];
            ull br2[4] = { b01.x, b01.y, b23.x, b23.y };
            #pragma unroll
            for (int i = 0; i < MI; i++) {
                ull a2;
                DUP_F32X2(a2, au[i]);
                #pragma unroll
                for (int j = 0; j < 4; j++)
                    FMA_F32X2(acc2[i][j], a2, br2[j], acc2[i][j]);
            }
        }
        if (kt + 1 < nk) cp_wait0();
        __syncthreads();
    }
#undef LOAD_STAGE

    #pragma unroll
    for (int i=0;i<MI;i++){
        int row = bm + ty*MI + i;
        if (row < M) {
            float bb = bias ? bias[row] : 0.f;
            float* cp = C + (ll)row*N + bn + tx*8;
            float2 p0 = *(float2*)&acc2[i][0];
            float2 p1 = *(float2*)&acc2[i][1];
            float2 p2 = *(float2*)&acc2[i][2];
            float2 p3 = *(float2*)&acc2[i][3];
            float4 v0, v1;
            v0.x=p0.x+bb; v0.y=p0.y+bb; v0.z=p1.x+bb; v0.w=p1.y+bb;
            v1.x=p2.x+bb; v1.y=p2.y+bb; v1.z=p3.x+bb; v1.w=p3.y+bb;
            *(float4*)cp = v0; *(float4*)(cp+4) = v1;
        }
    }
}

// ---------------- fused stencil + row softmax -> Sp pairs ----------------
__device__ __forceinline__ float loadT(const float* __restrict__ base, int a, int b)
{
    float v = base[(size_t)a*LL + b];
    if (a > 0    && b > 0)    v += base[(size_t)(a-1)*LL + (b-1)];
    if (a < LL-1 && b < LL-1) v += base[(size_t)(a+1)*LL + (b+1)];
    return v;
}

__global__ void fused_softmax_k(const float* __restrict__ In, uint2* __restrict__ Sp)
{
    int r = blockIdx.x;
    int b = blockIdx.y;
    const float* base = In + (size_t)b*LL*LL;
    uint2* dst = Sp + ((size_t)b*LL + r)*LL;
    int tid = threadIdx.x;
    __shared__ float red[32];

    int qr = (r % HF)*HF + r / HF;
    bool hasP = (qr > 0), hasN = (qr < LL-1);
    int pr = 0, nr = 0;
    if (hasP) pr = ((qr-1) % HF)*HF + (qr-1) / HF;
    if (hasN) nr = ((qr+1) % HF)*HF + (qr+1) / HF;

    float x[9];
    float mx = -3.4e38f;
    #pragma unroll
    for (int q = 0; q < 9; q++) {
        int s = q*256 + tid;
        float v = loadT(base, r, s);
        int qs = (s % HF)*HF + s / HF;
        if (hasP && qs > 0) {
            int ps = ((qs-1) % HF)*HF + (qs-1) / HF;
            v += loadT(base, pr, ps);
        }
        if (hasN && qs < LL-1) {
            int ns = ((qs+1) % HF)*HF + (qs+1) / HF;
            v += loadT(base, nr, ns);
        }
        x[q] = v;
        mx = fmaxf(mx, v);
    }
    #pragma unroll
    for (int o = 16; o; o >>= 1) mx = fmaxf(mx, __shfl_xor_sync(0xffffffffu, mx, o));
    if ((tid & 31) == 0) red[tid >> 5] = mx;
    __syncthreads();
    if (tid < 32) {
        float m2 = red[tid & 7];
        #pragma unroll
        for (int o = 4; o; o >>= 1) m2 = fmaxf(m2, __shfl_xor_sync(0xffffffffu, m2, o));
        red[tid] = m2;
    }
    __syncthreads();
    float m = red[0] * 10.f;

    float e[9], sum = 0.f;
    #pragma unroll
    for (int q = 0; q < 9; q++) { e[q] = __expf(10.f*x[q] - m); sum += e[q]; }
    #pragma unroll
    for (int o = 16; o; o >>= 1) sum += __shfl_xor_sync(0xffffffffu, sum, o);
    __syncthreads();
    if ((tid & 31) == 0) red[tid >> 5] = sum;
    __syncthreads();
    if (tid < 32) {
        float s2 = red[tid & 7];
        #pragma unroll
        for (int o = 4; o; o >>= 1) s2 += __shfl_xor_sync(0xffffffffu, s2, o);
        red[tid] = s2;
    }
    __syncthreads();
    float inv = 1.f / red[0];

    #pragma unroll
    for (int q = 0; q < 9; q++)
        dst[q*256 + tid] = split2_tf32(e[q] * inv);
}

// ---------------- deconv gather ----------------
__global__ void deconv_k(const float* __restrict__ Tmp, float* __restrict__ yout)
{
    int idx = blockIdx.x*blockDim.x + threadIdx.x;
    if (idx >= NB*NC*NPIX) return;
    int p = idx % NPIX; int t = idx / NPIX;
    int c = t % NC;     int b = t / NC;
    int yy = p / HW, xx = p % HW;
    const float* T = Tmp + (size_t)b*MM2*LL;
    float acc = 0.f;
    #pragma unroll
    for (int di = 0; di < 2; di++) {
        int i = (yy & 1) + 2*di;
        int d = yy + i - 2;
        if (d < 0) continue;
        int h = d >> 1; if (h >= HF) continue;
        #pragma unroll
        for (int dj = 0; dj < 2; dj++) {
            int j = (xx & 1) + 2*dj;
            int e = xx + j - 2;
            if (e < 0) continue;
            int w = e >> 1; if (w >= HF) continue;
            acc += T[(size_t)(c*16 + i*4 + j)*LL + h*HF + w];
        }
    }
    yout[idx] = acc * 0.25f;
}

// ---------------- im2col for 3x3 pad-1 conv on 96x96 (K-major) ----------------
__global__ void im2col_k(const float* __restrict__ In, float* __restrict__ X)
{
    int idx = blockIdx.x*blockDim.x + threadIdx.x;
    if (idx >= NB*KK1*NPIX) return;
    int p = idx % NPIX; int t = idx / NPIX;
    int k = t % KK1;    int b = t / KK1;
    int c = k / 9; int tt = k % 9; int dh = tt/3 - 1, dw = tt%3 - 1;
    int yy = p / HW + dh, xx = p % HW + dw;
    float val = 0.f;
    if ((unsigned)yy < HW && (unsigned)xx < HW)
        val = In[(((size_t)b*NC + c)*HW + yy)*HW + xx];
    X[idx] = val;
}

// ---------------- launch ----------------
extern "C" void kernel_launch(void* const* d_in, const int* in_sizes, int n_in,
                              void* d_out, int out_size)
{
    const float* f   = (const float*)d_in[0];
    const float* bim = (const float*)d_in[1];
    const float* w1  = (const float*)d_in[2];
    const float* b1  = (const float*)d_in[3];
    const float* w2  = (const float*)d_in[4];
    const float* b2  = (const float*)d_in[5];
    float* out = (float*)d_out;

    uint2 *Xp, *Wm, *Sp;
    uint32_t *W2s;
    float *bufA, *Tmp, *yb, *c1, *rn, *w1T, *w2T, *im;
    cudaGetSymbolAddress((void**)&Xp,   g_Xp);
    cudaGetSymbolAddress((void**)&Wm,   g_Wm);
    cudaGetSymbolAddress((void**)&W2s,  g_W2s);
    cudaGetSymbolAddress((void**)&Sp,   g_Sp);
    cudaGetSymbolAddress((void**)&bufA, g_bufA);
    cudaGetSymbolAddress((void**)&Tmp,  g_Tmp);
    cudaGetSymbolAddress((void**)&yb,   g_y);
    cudaGetSymbolAddress((void**)&c1,   g_c1);
    cudaGetSymbolAddress((void**)&rn,   g_rn);
    cudaGetSymbolAddress((void**)&w1T,  g_w1T);
    cudaGetSymbolAddress((void**)&w2T,  g_w2T);
    cudaGetSymbolAddress((void**)&im,   g_im);

    cudaFuncSetAttribute(mmagemm_k,   cudaFuncAttributeMaxDynamicSharedMemorySize, MMASMEM);
    cudaFuncSetAttribute(mmagemm2s_k, cudaFuncAttributeMaxDynamicSharedMemorySize, MMASMEM2);

    const int T = 256;

    build_Xp_k<<<(NB*LL*KK1 + T-1)/T, T>>>(f, Xp);
    build_W_k <<<(NB*LL*KK1 + T-1)/T, T>>>(bim, Wm);
    rnorm_k   <<<(NB*LL*32 + T-1)/T, T>>>(Wm, rn);

    // GEMM1 (3-term): bufA[l][n] = rn[n] * Xp[l]·Wm[n]  (= Y0^T)
    mmagemm_k<<<dim3(LL/128, LL/128, NB), T, MMASMEM>>>(Xp, Wm, bufA,
        LL, LL, KK1, (ll)LL*KK1, (ll)LL*KK1, (ll)LL*LL, rn, LL);

    // fused stencil + row softmax -> Sp pairs
    fused_softmax_k<<<dim3(LL, NB), 256>>>(bufA, Sp);

    // GEMM2 (2-term, A single tf32): Tmp[m][l] = sum_l' W2[m][l'] * S[l][l']
    build_W2s_k<<<(NB*MM2*LL + T-1)/T, T>>>(bim, W2s);
    mmagemm2s_k<<<dim3(LL/128, MM2/128, NB), T, MMASMEM2>>>(W2s, Sp, Tmp,
        MM2, LL, LL, (ll)MM2*LL, (ll)LL*LL, (ll)MM2*LL);

    // gather into y (/4)
    deconv_k<<<(NB*NC*NPIX + T-1)/T, T>>>(Tmp, yb);

    // conv1 / conv2 (scalar FFMA2 path)
    transpose_w_k<<<(NC*KK1 + T-1)/T, T>>>(w1, w1T);
    im2col_k<<<(NB*KK1*NPIX + T-1)/T, T>>>(yb, im);
    sgemm_nt_k<64><<<dim3(NPIX/128, 1, NB), T>>>(w1T, im, c1,
        NC, NPIX, KK1, 0, (ll)KK1*NPIX, (ll)NC*NPIX, b1);

    transpose_w_k<<<(NC*KK1 + T-1)/T, T>>>(w2, w2T);
    im2col_k<<<(NB*KK1*NPIX + T-1)/T, T>>>(c1, im);
    sgemm_nt_k<64><<<dim3(NPIX/128, 1, NB), T>>>(w2T, im, out,
        NC, NPIX, KK1, 0, (ll)KK1*NPIX, (ll)NC*NPIX, b2);
}

// round 17
// speedup vs baseline: 1.9960x; 1.3021x over previous
#include <cuda_runtime.h>
#include <cuda_bf16.h>
#include <math.h>
#include <stdint.h>

#define NB   4
#define NC   64
#define HW   96
#define HF   48
#define LL   2304    /* 48*48 */
#define KK1  576     /* C*9   */
#define KW1  288     /* KK1/2 words */
#define MM2  1024    /* C*16  */
#define LW   1152    /* LL/2 words */
#define NPIX 9216    /* 96*96 */

typedef long long ll;
typedef unsigned long long ull;

// ---------------- scratch (device globals; no allocation) ----------------
__device__ uint32_t g_XH [(size_t)NB*LL*KW1];   // bf16x2 hi plane, packed along K
__device__ uint32_t g_XM [(size_t)NB*LL*KW1];   // bf16x2 mid plane
__device__ uint32_t g_WH [(size_t)NB*LL*KW1];
__device__ uint32_t g_WM [(size_t)NB*LL*KW1];
__device__ uint32_t g_W2H[(size_t)NB*MM2*LW];
__device__ uint32_t g_W2M[(size_t)NB*MM2*LW];
__device__ uint32_t g_SH [(size_t)NB*LL*LW];
__device__ uint32_t g_SM [(size_t)NB*LL*LW];
__device__ float    g_bufA[(size_t)NB*LL*LL];
__device__ float    g_Tmp [(size_t)NB*MM2*LL];
__device__ float    g_y   [(size_t)NB*NC*NPIX];
__device__ float    g_c1  [(size_t)NB*NC*NPIX];
__device__ float    g_rn  [NB*LL];
__device__ float    g_w1T [KK1*NC];
__device__ float    g_w2T [KK1*NC];
__device__ float    g_im  [(size_t)NB*KK1*NPIX];

// ---------------- bf16 split/pack helpers ----------------
__device__ __forceinline__ void split_pack(float v0, float v1, uint32_t& hw, uint32_t& mw)
{
    __nv_bfloat16 h0 = __float2bfloat16(v0);
    __nv_bfloat16 h1 = __float2bfloat16(v1);
    __nv_bfloat16 m0 = __float2bfloat16(v0 - __bfloat162float(h0));
    __nv_bfloat16 m1 = __float2bfloat16(v1 - __bfloat162float(h1));
    hw = (uint32_t)__bfloat16_as_ushort(h0) | ((uint32_t)__bfloat16_as_ushort(h1) << 16);
    mw = (uint32_t)__bfloat16_as_ushort(m0) | ((uint32_t)__bfloat16_as_ushort(m1) << 16);
}
__device__ __forceinline__ float unp_lo(uint32_t w)
{ return __bfloat162float(__ushort_as_bfloat16((unsigned short)(w & 0xFFFF))); }
__device__ __forceinline__ float unp_hi(uint32_t w)
{ return __bfloat162float(__ushort_as_bfloat16((unsigned short)(w >> 16))); }

// ---------------- element generators ----------------
__device__ __forceinline__ float xp_val(const float* f, int b, int p, int k)
{
    int c = k / 9; int tt = k % 9; int dh = tt/3, dw = tt%3;
    int fh = p / HF, fw = p % HF;
    int u = fh + dh - 1, v = fw + dw - 1;
    if ((unsigned)u < HF && (unsigned)v < HF)
        return f[(((size_t)b*NC + c)*HW + 2*u)*HW + 2*v];
    return 0.f;
}
__device__ __forceinline__ float wm_val(const float* bimg, int b, int n, int k)
{
    int c = k / 9; int tt = k % 9; int dh = tt/3, dw = tt%3;
    int g = n*NC + c;
    int c0 = g / LL; int rr = g % LL; int h0 = rr / HF, w0 = rr % HF;
    int u = h0 + dh - 1, v = w0 + dw - 1;
    if ((unsigned)u < HF && (unsigned)v < HF)
        return bimg[(((size_t)b*NC + c0)*HW + 2*u)*HW + 2*v];
    return 0.f;
}
__device__ __forceinline__ float w2_val(const float* bimg, int b, int m, int l)
{
    int c = m / 16; int tt = m % 16; int i = tt/4, j = tt%4;
    int g = l*NC + c;
    int c0 = g / LL; int rr = g % LL; int h0 = rr / HF, w0 = rr % HF;
    int u = 2*h0 + 2 - i, v = 2*w0 + 2 - j;
    if ((unsigned)u < HW && (unsigned)v < HW)
        return bimg[(((size_t)b*NC + c0)*HW + u)*HW + v];
    return 0.f;
}

// ---------------- builders (emit bf16 hi/mid planes) ----------------
__global__ void build_Xp_k(const float* __restrict__ f,
                           uint32_t* __restrict__ XH, uint32_t* __restrict__ XM)
{
    int idx = blockIdx.x*blockDim.x + threadIdx.x;
    if (idx >= NB*LL*KW1) return;
    int kw = idx % KW1; int t = idx / KW1;
    int p = t % LL;     int b = t / LL;
    float v0 = xp_val(f, b, p, 2*kw), v1 = xp_val(f, b, p, 2*kw+1);
    split_pack(v0, v1, XH[idx], XM[idx]);
}

__global__ void build_W_k(const float* __restrict__ bimg,
                          uint32_t* __restrict__ WH, uint32_t* __restrict__ WM)
{
    int idx = blockIdx.x*blockDim.x + threadIdx.x;
    if (idx >= NB*LL*KW1) return;
    int kw = idx % KW1; int t = idx / KW1;
    int n = t % LL;     int b = t / LL;
    float v0 = wm_val(bimg, b, n, 2*kw), v1 = wm_val(bimg, b, n, 2*kw+1);
    split_pack(v0, v1, WH[idx], WM[idx]);
}

__global__ void build_W2_k(const float* __restrict__ bimg,
                           uint32_t* __restrict__ WH, uint32_t* __restrict__ WM)
{
    int idx = blockIdx.x*blockDim.x + threadIdx.x;
    if (idx >= NB*MM2*LW) return;
    int lw = idx % LW; int t = idx / LW;
    int m = t % MM2;   int b = t / MM2;
    float v0 = w2_val(bimg, b, m, 2*lw), v1 = w2_val(bimg, b, m, 2*lw+1);
    split_pack(v0, v1, WH[idx], WM[idx]);
}

// rnorm: warp per (b,n) row (h+m ~ exact to 2^-16)
__global__ void rnorm_k(const uint32_t* __restrict__ WH, const uint32_t* __restrict__ WM,
                        float* __restrict__ rn)
{
    int warp = (blockIdx.x*blockDim.x + threadIdx.x) >> 5;
    int lane = threadIdx.x & 31;
    if (warp >= NB*LL) return;
    const uint32_t* rh = WH + (size_t)warp*KW1;
    const uint32_t* rm = WM + (size_t)warp*KW1;
    float s = 0.f;
    for (int kw = lane; kw < KW1; kw += 32) {
        uint32_t hw = rh[kw], mw = rm[kw];
        float v0 = unp_lo(hw) + unp_lo(mw);
        float v1 = unp_hi(hw) + unp_hi(mw);
        s += v0*v0 + v1*v1;
    }
    #pragma unroll
    for (int o = 16; o; o >>= 1) s += __shfl_xor_sync(0xffffffffu, s, o);
    if (lane == 0) rn[warp] = 1.0f / fmaxf(sqrtf(s), 1e-4f);
}

__global__ void transpose_w_k(const float* __restrict__ w, float* __restrict__ wT)
{
    int idx = blockIdx.x*blockDim.x + threadIdx.x;
    if (idx >= NC*KK1) return;
    int k = idx % KK1, c = idx / KK1;
    wT[(size_t)k*NC + c] = w[idx];
}

// ---------------- PTX helpers ----------------
__device__ __forceinline__ void cpa16(void* s, const void* g)
{
    uint32_t sa = (uint32_t)__cvta_generic_to_shared(s);
    asm volatile("cp.async.cg.shared.global [%0], [%1], 16;\n" :: "r"(sa), "l"(g));
}
__device__ __forceinline__ void cpa16p(void* s, const void* g, int bytes)
{
    uint32_t sa = (uint32_t)__cvta_generic_to_shared(s);
    asm volatile("cp.async.cg.shared.global [%0], [%1], 16, %2;\n"
                 :: "r"(sa), "l"(g), "r"(bytes));
}
__device__ __forceinline__ void cp_commit() { asm volatile("cp.async.commit_group;\n"); }
__device__ __forceinline__ void cp_wait0()  { asm volatile("cp.async.wait_group 0;\n"); }

#define FMA_F32X2(d, a, b, c) \
    asm("fma.rn.f32x2 %0, %1, %2, %3;" : "=l"(d) : "l"(a), "l"(b), "l"(c))
#define DUP_F32X2(d, r) \
    asm("mov.b64 %0, {%1, %1};" : "=l"(d) : "r"(r))

__device__ __forceinline__ void mmab(float* c, const uint32_t* a, const uint32_t* b)
{
    asm("mma.sync.aligned.m16n8k16.row.col.f32.bf16.bf16.f32 "
        "{%0,%1,%2,%3}, {%4,%5,%6,%7}, {%8,%9}, {%0,%1,%2,%3};"
        : "+f"(c[0]), "+f"(c[1]), "+f"(c[2]), "+f"(c[3])
        : "r"(a[0]), "r"(a[1]), "r"(a[2]), "r"(a[3]), "r"(b[0]), "r"(b[1]));
}

// ---------------- bf16 3-product GEMM (NT): C = colscale(n)*(A@B^T) ----------------
// Planes AH/AM: M x Kw words (bf16x2 along K), BH/BM: N x Kw. M,N mult 128, Kw mult 16.
#define PIT 20                    /* word pitch */
#define PLANE (128*PIT)           /* words per plane */
#define STAGEW (4*PLANE)          /* words per stage (AH,AM,BH,BM) */
#define MMASMEMB (2*STAGEW*4)     /* 81920 B */

__global__ __launch_bounds__(256, 2) void mmabf_k(
    const uint32_t* __restrict__ AHg, const uint32_t* __restrict__ AMg,
    const uint32_t* __restrict__ BHg, const uint32_t* __restrict__ BMg,
    float* __restrict__ Cg,
    int M, int N, int Kw, ll sA, ll sB, ll sC,
    const float* __restrict__ colscale, int sCS)
{
    extern __shared__ uint32_t smw[];
    int bz = blockIdx.z;
    const uint32_t* AH = AHg + (ll)bz*sA;
    const uint32_t* AM = AMg + (ll)bz*sA;
    const uint32_t* BH = BHg + (ll)bz*sB;
    const uint32_t* BM = BMg + (ll)bz*sB;
    float*           C = Cg  + (ll)bz*sC;
    int bm = blockIdx.y*128, bn = blockIdx.x*128;
    int tid = threadIdx.x;
    int wid = tid >> 5, lane = tid & 31;
    int wm = wid & 1, wn = wid >> 1;          // warp tile 64x32
    int lm = lane >> 2, lk = lane & 3;

    float acc[4][4][4];
    #pragma unroll
    for (int i=0;i<4;i++)
        #pragma unroll
        for (int j=0;j<4;j++)
            #pragma unroll
            for (int q=0;q<4;q++) acc[i][j][q] = 0.f;

    // 8 cp.async per thread per stage: 2 chunks per plane
    int r0 = tid >> 2, cw = (tid & 3)*4;
    const uint32_t* g[8]; uint32_t* sp[8];
    {
        const uint32_t* srcs[4] = {AH, AM, BH, BM};
        int bases[4] = {bm, bm, bn, bn};
        #pragma unroll
        for (int pl = 0; pl < 4; pl++) {
            g[pl*2]   = srcs[pl] + (ll)(bases[pl] + r0     )*Kw + cw;
            g[pl*2+1] = srcs[pl] + (ll)(bases[pl] + r0 + 64)*Kw + cw;
            sp[pl*2]   = smw + pl*PLANE + r0*PIT + cw;
            sp[pl*2+1] = smw + pl*PLANE + (r0+64)*PIT + cw;
        }
    }

#define LOADSTAGE(st)                                                           \
    {                                                                           \
        int so = (st)*STAGEW;                                                   \
        _Pragma("unroll")                                                       \
        for (int q = 0; q < 8; q++) { cpa16(sp[q] + so, g[q]); g[q] += 16; }    \
        cp_commit();                                                            \
    }

    const uint32_t* aH0 = smw + (wm*64 + lm)*PIT + lk;
    const uint32_t* aM0 = aH0 + PLANE;
    const uint32_t* bH0 = smw + 2*PLANE + (wn*32 + lm)*PIT + lk;
    const uint32_t* bM0 = bH0 + PLANE;

    int nk = Kw >> 4;   // chunks of 16 words = 32 K elements
    LOADSTAGE(0);
    cp_wait0();
    __syncthreads();

    for (int kt = 0; kt < nk; kt++) {
        int cur = kt & 1;
        if (kt + 1 < nk) LOADSTAGE(cur^1);
        int off = cur*STAGEW;
        #pragma unroll
        for (int ks = 0; ks < 2; ks++) {
            int kw0 = ks*8;
            uint32_t bh[4][2], bmf[4][2];
            #pragma unroll
            for (int nf = 0; nf < 4; nf++) {
                bh[nf][0]  = bH0[off + nf*8*PIT + kw0];
                bh[nf][1]  = bH0[off + nf*8*PIT + kw0 + 4];
                bmf[nf][0] = bM0[off + nf*8*PIT + kw0];
                bmf[nf][1] = bM0[off + nf*8*PIT + kw0 + 4];
            }
            #pragma unroll
            for (int mf = 0; mf < 4; mf++) {
                uint32_t ah[4], am[4];
                ah[0] = aH0[off + (mf*16    )*PIT + kw0];
                ah[1] = aH0[off + (mf*16 + 8)*PIT + kw0];
                ah[2] = aH0[off + (mf*16    )*PIT + kw0 + 4];
                ah[3] = aH0[off + (mf*16 + 8)*PIT + kw0 + 4];
                am[0] = aM0[off + (mf*16    )*PIT + kw0];
                am[1] = aM0[off + (mf*16 + 8)*PIT + kw0];
                am[2] = aM0[off + (mf*16    )*PIT + kw0 + 4];
                am[3] = aM0[off + (mf*16 + 8)*PIT + kw0 + 4];
                #pragma unroll
                for (int nf = 0; nf < 4; nf++)
                    mmab(acc[mf][nf], ah, bh[nf]);
                #pragma unroll
                for (int nf = 0; nf < 4; nf++)
                    mmab(acc[mf][nf], ah, bmf[nf]);
                #pragma unroll
                for (int nf = 0; nf < 4; nf++)
                    mmab(acc[mf][nf], am, bh[nf]);
            }
        }
        if (kt + 1 < nk) cp_wait0();
        __syncthreads();
    }
#undef LOADSTAGE

    #pragma unroll
    for (int nf = 0; nf < 4; nf++) {
        int n0 = bn + wn*32 + nf*8 + 2*lk;
        float s0 = 1.f, s1 = 1.f;
        if (colscale) {
            s0 = __ldg(&colscale[bz*sCS + n0]);
            s1 = __ldg(&colscale[bz*sCS + n0 + 1]);
        }
        #pragma unroll
        for (int mf = 0; mf < 4; mf++) {
            int m0 = bm + wm*64 + mf*16 + lm;
            float2 v0 = make_float2(acc[mf][nf][0]*s0, acc[mf][nf][1]*s1);
            float2 v1 = make_float2(acc[mf][nf][2]*s0, acc[mf][nf][3]*s1);
            *(float2*)&C[(ll)m0*N + n0]     = v0;
            *(float2*)&C[(ll)(m0+8)*N + n0] = v1;
        }
    }
}

// ---------------- scalar NT SGEMM (FFMA2) for the conv layers ----------------
template<int BM>
__global__ __launch_bounds__(256, 2) void sgemm_nt_k(
    const float* __restrict__ Ag, const float* __restrict__ Bg, float* __restrict__ Cg,
    int M, int N, int K, ll sA, ll sB, ll sC,
    const float* __restrict__ bias)
{
    constexpr int BN = 128, BK = 16;
    constexpr int MI = BM / 16;
    int bz = blockIdx.z;
    const float* A = Ag + (ll)bz*sA;
    const float* B = Bg + (ll)bz*sB;
    float*       C = Cg + (ll)bz*sC;
    int bm = blockIdx.y*BM, bn = blockIdx.x*BN;
    int tid = threadIdx.x;
    int tx = tid & 15, ty = tid >> 4;

    __shared__ float As[2][BK][BM+4];
    __shared__ float Bs[2][BK][BN+4];

    ull acc2[MI][4];
    #pragma unroll
    for (int i=0;i<MI;i++)
        #pragma unroll
        for (int j=0;j<4;j++) acc2[i][j] = 0ull;

    constexpr int A4 = BK*BM/4;
    constexpr int B4 = BK*BN/4;

#define LOAD_STAGE(st, k0)                                                      \
    {                                                                           \
        _Pragma("unroll")                                                       \
        for (int q = 0; q < A4/256; q++) {                                      \
            int idx = q*256 + tid;                                              \
            int k = idx / (BM/4), c4 = (idx % (BM/4))*4;                        \
            int mb = bm + c4;                                                   \
            const float* ga = A + (ll)((k0)+k)*M + (mb < M ? mb : 0);           \
            cpa16p(&As[st][k][c4], ga, (mb < M) ? 16 : 0);                      \
        }                                                                       \
        _Pragma("unroll")                                                       \
        for (int q = 0; q < B4/256; q++) {                                      \
            int idx = q*256 + tid;                                              \
            int k = idx / (BN/4), c4 = (idx % (BN/4))*4;                        \
            const float* gb = B + (ll)((k0)+k)*N + bn + c4;                     \
            cpa16p(&Bs[st][k][c4], gb, 16);                                     \
        }                                                                       \
    }

    int nk = K >> 4;
    LOAD_STAGE(0, 0);
    cp_commit();
    cp_wait0();
    __syncthreads();

    for (int kt = 0; kt < nk; kt++) {
        int cur = kt & 1;
        if (kt + 1 < nk) { LOAD_STAGE(cur^1, (kt+1)<<4); cp_commit(); }
        #pragma unroll
        for (int kk = 0; kk < BK; kk++) {
            uint32_t au[MI];
            #pragma unroll
            for (int i = 0; i < MI; i += 4)
                *(uint4*)&au[i] = *(const uint4*)&As[cur][kk][ty*MI + i];
            ulonglong2 b01 = *(const ulonglong2*)&Bs[cur][kk][tx*8];
            ulonglong2 b23 = *(const ulonglong2*)&Bs[cur][kk][tx*8+4];
            ull br2[4] = { b01.x, b01.y, b23.x, b23.y };
            #pragma unroll
            for (int i = 0; i < MI; i++) {
                ull a2;
                DUP_F32X2(a2, au[i]);
                #pragma unroll
                for (int j = 0; j < 4; j++)
                    FMA_F32X2(acc2[i][j], a2, br2[j], acc2[i][j]);
            }
        }
        if (kt + 1 < nk) cp_wait0();
        __syncthreads();
    }
#undef LOAD_STAGE

    #pragma unroll
    for (int i=0;i<MI;i++){
        int row = bm + ty*MI + i;
        if (row < M) {
            float bb = bias ? bias[row] : 0.f;
            float* cp = C + (ll)row*N + bn + tx*8;
            float2 p0 = *(float2*)&acc2[i][0];
            float2 p1 = *(float2*)&acc2[i][1];
            float2 p2 = *(float2*)&acc2[i][2];
            float2 p3 = *(float2*)&acc2[i][3];
            float4 v0, v1;
            v0.x=p0.x+bb; v0.y=p0.y+bb; v0.z=p1.x+bb; v0.w=p1.y+bb;
            v1.x=p2.x+bb; v1.y=p2.y+bb; v1.z=p3.x+bb; v1.w=p3.y+bb;
            *(float4*)cp = v0; *(float4*)(cp+4) = v1;
        }
    }
}

// ---------------- fused stencil + row softmax -> bf16 planes ----------------
__device__ __forceinline__ float loadT(const float* __restrict__ base, int a, int b)
{
    float v = base[(size_t)a*LL + b];
    if (a > 0    && b > 0)    v += base[(size_t)(a-1)*LL + (b-1)];
    if (a < LL-1 && b < LL-1) v += base[(size_t)(a+1)*LL + (b+1)];
    return v;
}
__device__ __forceinline__ float fusedval(const float* __restrict__ base,
                                          int r, int pr, int nr, bool hasP, bool hasN, int s)
{
    float v = loadT(base, r, s);
    int qs = (s % HF)*HF + s / HF;
    if (hasP && qs > 0) {
        int ps = ((qs-1) % HF)*HF + (qs-1) / HF;
        v += loadT(base, pr, ps);
    }
    if (hasN && qs < LL-1) {
        int ns = ((qs+1) % HF)*HF + (qs+1) / HF;
        v += loadT(base, nr, ns);
    }
    return v;
}

// blockDim = 288 (1152 words / 4 per thread, exact)
__global__ void fused_softmax_k(const float* __restrict__ In,
                                uint32_t* __restrict__ SHo, uint32_t* __restrict__ SMo)
{
    int r = blockIdx.x;
    int b = blockIdx.y;
    const float* base = In + (size_t)b*LL*LL;
    uint32_t* dh = SHo + ((size_t)b*LL + r)*LW;
    uint32_t* dm = SMo + ((size_t)b*LL + r)*LW;
    int tid = threadIdx.x;
    int wid = tid >> 5, lane = tid & 31;
    __shared__ float red[9];

    int qr = (r % HF)*HF + r / HF;
    bool hasP = (qr > 0), hasN = (qr < LL-1);
    int pr = 0, nr = 0;
    if (hasP) pr = ((qr-1) % HF)*HF + (qr-1) / HF;
    if (hasN) nr = ((qr+1) % HF)*HF + (qr+1) / HF;

    float x0[4], x1[4];
    float mx = -3.4e38f;
    #pragma unroll
    for (int q = 0; q < 4; q++) {
        int w = q*288 + tid;
        x0[q] = fusedval(base, r, pr, nr, hasP, hasN, 2*w);
        x1[q] = fusedval(base, r, pr, nr, hasP, hasN, 2*w + 1);
        mx = fmaxf(mx, fmaxf(x0[q], x1[q]));
    }
    #pragma unroll
    for (int o = 16; o; o >>= 1) mx = fmaxf(mx, __shfl_xor_sync(0xffffffffu, mx, o));
    if (lane == 0) red[wid] = mx;
    __syncthreads();
    float m = red[0];
    #pragma unroll
    for (int i = 1; i < 9; i++) m = fmaxf(m, red[i]);
    m *= 10.f;
    __syncthreads();

    float e0[4], e1[4], sum = 0.f;
    #pragma unroll
    for (int q = 0; q < 4; q++) {
        e0[q] = __expf(10.f*x0[q] - m);
        e1[q] = __expf(10.f*x1[q] - m);
        sum += e0[q] + e1[q];
    }
    #pragma unroll
    for (int o = 16; o; o >>= 1) sum += __shfl_xor_sync(0xffffffffu, sum, o);
    if (lane == 0) red[wid] = sum;
    __syncthreads();
    float tot = 0.f;
    #pragma unroll
    for (int i = 0; i < 9; i++) tot += red[i];
    float inv = 1.f / tot;

    #pragma unroll
    for (int q = 0; q < 4; q++) {
        int w = q*288 + tid;
        uint32_t hw, mw;
        split_pack(e0[q]*inv, e1[q]*inv, hw, mw);
        dh[w] = hw; dm[w] = mw;
    }
}

// ---------------- deconv gather ----------------
__global__ void deconv_k(const float* __restrict__ Tmp, float* __restrict__ yout)
{
    int idx = blockIdx.x*blockDim.x + threadIdx.x;
    if (idx >= NB*NC*NPIX) return;
    int p = idx % NPIX; int t = idx / NPIX;
    int c = t % NC;     int b = t / NC;
    int yy = p / HW, xx = p % HW;
    const float* T = Tmp + (size_t)b*MM2*LL;
    float acc = 0.f;
    #pragma unroll
    for (int di = 0; di < 2; di++) {
        int i = (yy & 1) + 2*di;
        int d = yy + i - 2;
        if (d < 0) continue;
        int h = d >> 1; if (h >= HF) continue;
        #pragma unroll
        for (int dj = 0; dj < 2; dj++) {
            int j = (xx & 1) + 2*dj;
            int e = xx + j - 2;
            if (e < 0) continue;
            int w = e >> 1; if (w >= HF) continue;
            acc += T[(size_t)(c*16 + i*4 + j)*LL + h*HF + w];
        }
    }
    yout[idx] = acc * 0.25f;
}

// ---------------- im2col for 3x3 pad-1 conv on 96x96 (K-major) ----------------
__global__ void im2col_k(const float* __restrict__ In, float* __restrict__ X)
{
    int idx = blockIdx.x*blockDim.x + threadIdx.x;
    if (idx >= NB*KK1*NPIX) return;
    int p = idx % NPIX; int t = idx / NPIX;
    int k = t % KK1;    int b = t / KK1;
    int c = k / 9; int tt = k % 9; int dh = tt/3 - 1, dw = tt%3 - 1;
    int yy = p / HW + dh, xx = p % HW + dw;
    float val = 0.f;
    if ((unsigned)yy < HW && (unsigned)xx < HW)
        val = In[(((size_t)b*NC + c)*HW + yy)*HW + xx];
    X[idx] = val;
}

// ---------------- launch ----------------
extern "C" void kernel_launch(void* const* d_in, const int* in_sizes, int n_in,
                              void* d_out, int out_size)
{
    const float* f   = (const float*)d_in[0];
    const float* bim = (const float*)d_in[1];
    const float* w1  = (const float*)d_in[2];
    const float* b1  = (const float*)d_in[3];
    const float* w2  = (const float*)d_in[4];
    const float* b2  = (const float*)d_in[5];
    float* out = (float*)d_out;

    uint32_t *XH,*XM,*WH,*WM,*W2H,*W2M,*SH,*SM;
    float *bufA,*Tmp,*yb,*c1,*rn,*w1T,*w2T,*im;
    cudaGetSymbolAddress((void**)&XH,   g_XH);
    cudaGetSymbolAddress((void**)&XM,   g_XM);
    cudaGetSymbolAddress((void**)&WH,   g_WH);
    cudaGetSymbolAddress((void**)&WM,   g_WM);
    cudaGetSymbolAddress((void**)&W2H,  g_W2H);
    cudaGetSymbolAddress((void**)&W2M,  g_W2M);
    cudaGetSymbolAddress((void**)&SH,   g_SH);
    cudaGetSymbolAddress((void**)&SM,   g_SM);
    cudaGetSymbolAddress((void**)&bufA, g_bufA);
    cudaGetSymbolAddress((void**)&Tmp,  g_Tmp);
    cudaGetSymbolAddress((void**)&yb,   g_y);
    cudaGetSymbolAddress((void**)&c1,   g_c1);
    cudaGetSymbolAddress((void**)&rn,   g_rn);
    cudaGetSymbolAddress((void**)&w1T,  g_w1T);
    cudaGetSymbolAddress((void**)&w2T,  g_w2T);
    cudaGetSymbolAddress((void**)&im,   g_im);

    cudaFuncSetAttribute(mmabf_k, cudaFuncAttributeMaxDynamicSharedMemorySize, MMASMEMB);

    const int T = 256;

    build_Xp_k<<<(NB*LL*KW1 + T-1)/T, T>>>(f, XH, XM);
    build_W_k <<<(NB*LL*KW1 + T-1)/T, T>>>(bim, WH, WM);
    rnorm_k   <<<(NB*LL*32 + T-1)/T, T>>>(WH, WM, rn);

    // GEMM1: bufA[l][n] = rn[n] * Xp[l]·Wm[n]  (= Y0^T), Kw=288
    mmabf_k<<<dim3(LL/128, LL/128, NB), T, MMASMEMB>>>(
        XH, XM, WH, WM, bufA,
        LL, LL, KW1, (ll)LL*KW1, (ll)LL*KW1, (ll)LL*LL, rn, LL);

    // fused stencil + row softmax -> S planes
    fused_softmax_k<<<dim3(LL, NB), 288>>>(bufA, SH, SM);

    // GEMM2: Tmp[m][l] = sum_l' W2[m][l'] * S[l][l'], Kw=1152
    build_W2_k<<<(NB*MM2*LW + T-1)/T, T>>>(bim, W2H, W2M);
    mmabf_k<<<dim3(LL/128, MM2/128, NB), T, MMASMEMB>>>(
        W2H, W2M, SH, SM, Tmp,
        MM2, LL, LW, (ll)MM2*LW, (ll)LL*LW, (ll)MM2*LL, nullptr, 0);

    // gather into y (/4)
    deconv_k<<<(NB*NC*NPIX + T-1)/T, T>>>(Tmp, yb);

    // conv1 / conv2 (scalar FFMA2 path)
    transpose_w_k<<<(NC*KK1 + T-1)/T, T>>>(w1, w1T);
    im2col_k<<<(NB*KK1*NPIX + T-1)/T, T>>>(yb, im);
    sgemm_nt_k<64><<<dim3(NPIX/128, 1, NB), T>>>(w1T, im, c1,
        NC, NPIX, KK1, 0, (ll)KK1*NPIX, (ll)NC*NPIX, b1);

    transpose_w_k<<<(NC*KK1 + T-1)/T, T>>>(w2, w2T);
    im2col_k<<<(NB*KK1*NPIX + T-1)/T, T>>>(c1, im);
    sgemm_nt_k<64><<<dim3(NPIX/128, 1, NB), T>>>(w2T, im, out,
        NC, NPIX, KK1, 0, (ll)KK1*NPIX, (ll)NC*NPIX, b2);
}